// round 5
// baseline (speedup 1.0000x reference)
#include <cuda_runtime.h>

#define BB    16
#define CC    112
#define HH    64
#define HWN   4096
#define NHEAD 4
#define HD    28
#define NWIN  256
#define TOPK  128
#define SCALE 0.18898223650461363f   // 28^-0.5

#define KV_STRIDE 116   // K/V/Q row stride (floats): 29 float4s (odd) -> conflict-free
#define S_STRIDE  131   // S row stride: odd -> conflict-free scalar row-per-lane
#define ST_STRIDE 113   // qkv stage stride
#define BUF_STRIDE 29   // O-phase partial buffer stride (odd)

// ---------------- scratch (device globals; no allocation allowed) ------------
__device__ __align__(16) float g_q[BB * HWN * CC];
__device__ __align__(16) float g_k[BB * HWN * CC];
__device__ __align__(16) float g_v[BB * HWN * CC];

__device__ __forceinline__ float dot4(float4 a, float4 b) {
    return a.x * b.x + a.y * b.y + a.z * b.z + a.w * b.w;
}

// =============================================================================
// Kernel A: QKV projection. qkv[b,hw,d] = sum_c x[b,c,hw] * Wqkv[d,c]
// 512 threads, 86KB smem -> 2 blocks/SM. W via warp-uniform __ldg (L1/L2).
// =============================================================================
__global__ __launch_bounds__(512, 2) void qkv_kernel(const float* __restrict__ x,
                                                     const float* __restrict__ Wqkv) {
    extern __shared__ float sm[];
    float* xs = sm;                          // [112][128]    14336
    float* st = sm + 14336;                  // [64][113]      7232

    const int tid = threadIdx.x;
    const int b   = blockIdx.y;
    const int hw0 = blockIdx.x * 128;

    for (int i = tid; i < 3584; i += 512) {
        int c = i >> 5, p4 = i & 31;
        ((float4*)xs)[c * 32 + p4] =
            ((const float4*)(x + (b * CC + c) * HWN + hw0))[p4];
    }
    __syncthreads();

    const int pg = tid & 31;        // pixel group (4 px), lanes consecutive
    const int dg = tid >> 5;        // d group (7 d), uniform within warp
    const int px = pg * 4;

    for (int seg = 0; seg < 3; seg++) {
        const float scl = (seg == 0) ? SCALE : 1.0f;
        float acc[4][7];
        #pragma unroll
        for (int i = 0; i < 4; i++)
            #pragma unroll
            for (int j = 0; j < 7; j++) acc[i][j] = 0.0f;

        const float* wsp = Wqkv + (seg * CC + dg * 7) * CC;
        #pragma unroll 2
        for (int c4 = 0; c4 < 28; c4++) {
            float4 xv[4];
            #pragma unroll
            for (int u = 0; u < 4; u++)
                xv[u] = *(const float4*)(xs + (c4 * 4 + u) * 128 + px);
            #pragma unroll
            for (int j = 0; j < 7; j++) {
                float4 w4 = __ldg((const float4*)(wsp + j * CC + c4 * 4));  // uniform
                #pragma unroll
                for (int i = 0; i < 4; i++) {
                    acc[i][j] += ((const float*)&xv[0])[i] * w4.x
                               + ((const float*)&xv[1])[i] * w4.y
                               + ((const float*)&xv[2])[i] * w4.z
                               + ((const float*)&xv[3])[i] * w4.w;
                }
            }
        }

        float* dst = (seg == 0 ? g_q : (seg == 1 ? g_k : g_v)) + (size_t)(b * HWN + hw0) * CC;
        #pragma unroll
        for (int wv = 0; wv < 2; wv++) {
            if ((pg >> 4) == wv) {
                #pragma unroll
                for (int i = 0; i < 4; i++)
                    #pragma unroll
                    for (int j = 0; j < 7; j++)
                        st[(px - wv * 64 + i) * ST_STRIDE + dg * 7 + j] = acc[i][j] * scl;
            }
            __syncthreads();
            for (int i = tid; i < 1792; i += 512) {
                int p = i / 28, c4 = i - p * 28;
                const float* s = st + p * ST_STRIDE + c4 * 4;
                ((float4*)dst)[wv * 1792 + i] = make_float4(s[0], s[1], s[2], s[3]);
            }
            __syncthreads();
        }
    }
}

// =============================================================================
// Kernel B: windowed top-k attention + fused output projection.
// One block per (batch, window), 1024 threads.
// =============================================================================
__global__ __launch_bounds__(1024, 1) void attn_kernel(const int* __restrict__ topk,
                                                       const float* __restrict__ Wp,
                                                       const float* __restrict__ bias,
                                                       float* __restrict__ out) {
    extern __shared__ float sm[];
    float* Ks   = sm;                        // 128 x 116 = 14848 (reused as Obuf 16x116)
    float* Vs   = sm + 14848;                // 128 x 116 = 14848
    float* Qs   = sm + 29696;                // 16 x 116  = 1856 (reused as partial buf 64x29)
    float* S    = sm + 31552;                // 64 x 131  = 8384
    float* sums = sm + 39936;                // 64
    int*   poss = (int*)(sm + 40000);        // 128  -> total 40128 floats

    const int tid = threadIdx.x;
    const int w   = blockIdx.x & (NWIN - 1);
    const int b   = blockIdx.x >> 8;
    const int wy  = w >> 4, wx = w & 15;

    if (tid < TOPK) poss[tid] = topk[w * TOPK + tid];
    __syncthreads();

    // gather K, V into padded rows
    for (int i = tid; i < 3584; i += 1024) {
        int row = i / 28, c4 = i - row * 28;
        size_t base4 = (size_t)(b * HWN + poss[row]) * 28 + c4;
        ((float4*)Ks)[row * 29 + c4] = ((const float4*)g_k)[base4];
        ((float4*)Vs)[row * 29 + c4] = ((const float4*)g_v)[base4];
    }
    if (tid < 448) {
        int qi = tid / 28, c4 = tid - qi * 28;
        int hw = (wy * 4 + (qi >> 2)) * HH + wx * 4 + (qi & 3);
        ((float4*)Qs)[qi * 29 + c4] = ((const float4*)g_q)[(size_t)(b * HWN + hw) * 28 + c4];
    }
    __syncthreads();

    // ---- S = Q K^T : thread = (h, qg of 4 qi, khalf) x lane kj, 4qi x 2kj ----
    {
        const int lane  = tid & 31;
        const int khalf = (tid >> 5) & 1;
        const int qg    = (tid >> 6) & 3;
        const int h     = tid >> 8;

        float acc[4][2];
        #pragma unroll
        for (int i = 0; i < 4; i++) { acc[i][0] = 0.f; acc[i][1] = 0.f; }

        const float* kp = Ks + (khalf * 64 + lane) * KV_STRIDE + h * HD;
        const float* qp = Qs + (qg * 4) * KV_STRIDE + h * HD;           // warp-uniform
        #pragma unroll
        for (int s = 0; s < 7; s++) {
            float4 k0 = *(const float4*)(kp + s * 4);
            float4 k1 = *(const float4*)(kp + 32 * KV_STRIDE + s * 4);
            #pragma unroll
            for (int i = 0; i < 4; i++) {
                float4 qv = *(const float4*)(qp + i * KV_STRIDE + s * 4);  // broadcast
                acc[i][0] += dot4(qv, k0);
                acc[i][1] += dot4(qv, k1);
            }
        }
        float* srow = S + (h * 16 + qg * 4) * S_STRIDE + khalf * 64 + lane;
        #pragma unroll
        for (int i = 0; i < 4; i++) {
            srow[i * S_STRIDE]      = acc[i][0];
            srow[i * S_STRIDE + 32] = acc[i][1];
        }
    }
    __syncthreads();

    // ---- softmax (un-normalized exp; per-row sum stored) ----
    {
        int r   = tid >> 4;
        int sub = tid & 15;
        float* row = S + r * S_STRIDE + sub * 8;
        float mx = -1e30f;
        #pragma unroll
        for (int i = 0; i < 8; i++) mx = fmaxf(mx, row[i]);
        mx = fmaxf(mx, __shfl_xor_sync(0xffffffffu, mx, 1));
        mx = fmaxf(mx, __shfl_xor_sync(0xffffffffu, mx, 2));
        mx = fmaxf(mx, __shfl_xor_sync(0xffffffffu, mx, 4));
        mx = fmaxf(mx, __shfl_xor_sync(0xffffffffu, mx, 8));
        float sum = 0.0f;
        #pragma unroll
        for (int i = 0; i < 8; i++) {
            float e = __expf(row[i] - mx);
            row[i] = e;
            sum += e;
        }
        sum += __shfl_xor_sync(0xffffffffu, sum, 1);
        sum += __shfl_xor_sync(0xffffffffu, sum, 2);
        sum += __shfl_xor_sync(0xffffffffu, sum, 4);
        sum += __shfl_xor_sync(0xffffffffu, sum, 8);
        if (sub == 0) sums[r] = sum;
    }
    __syncthreads();

    // ---- O = P V : split-K over kj halves; half 1 -> partial buf (Qs) ----
    {
        const int slot = tid & 7;            // 0..6 active, 4 d's each
        const int hq   = (tid >> 3) & 63;
        const int half = tid >> 9;
        const int h    = hq >> 4, qi = hq & 15;
        float4 acc = make_float4(0.f, 0.f, 0.f, 0.f);
        if (slot < 7) {
            const float* prow = S + hq * S_STRIDE + half * 64;
            const float* vp   = Vs + (half * 64) * KV_STRIDE + h * HD + slot * 4;
            #pragma unroll 4
            for (int kj = 0; kj < 64; kj++) {
                float p = prow[kj];
                float4 v = *(const float4*)(vp + kj * KV_STRIDE);
                acc.x += p * v.x; acc.y += p * v.y;
                acc.z += p * v.z; acc.w += p * v.w;
            }
            if (half == 1) {
                float* bp = Qs + hq * BUF_STRIDE + slot * 4;
                bp[0] = acc.x; bp[1] = acc.y; bp[2] = acc.z; bp[3] = acc.w;
            }
        }
        __syncthreads();
        if (slot < 7 && half == 0) {
            const float* bp = Qs + hq * BUF_STRIDE + slot * 4;
            float inv = 1.0f / sums[hq];
            acc.x = (acc.x + bp[0]) * inv;
            acc.y = (acc.y + bp[1]) * inv;
            acc.z = (acc.z + bp[2]) * inv;
            acc.w = (acc.w + bp[3]) * inv;
            // Obuf reuses Ks region: O[qi][112] at stride KV_STRIDE
            *(float4*)(Ks + qi * KV_STRIDE + h * HD + slot * 4) = acc;
        }
    }
    __syncthreads();

    // ---- fused output projection: out[b,d,hw] = O[qi]·Wp[d] + bias[d] ----
    {
        const int px   = tid & 15;
        const int dgrp = tid >> 4;           // 0..63, 56 active, 2 d's each
        if (dgrp < 56) {
            const int d = dgrp * 2;
            float a0 = __ldg(bias + d);
            float a1 = __ldg(bias + d + 1);
            const float* obp = Ks + px * KV_STRIDE;
            const float* wr  = Wp + d * CC;
            #pragma unroll 4
            for (int c4 = 0; c4 < 28; c4++) {
                float4 ov = *(const float4*)(obp + c4 * 4);
                float4 w0 = __ldg((const float4*)(wr + c4 * 4));          // 2 addrs/warp
                float4 w1 = __ldg((const float4*)(wr + CC + c4 * 4));
                a0 += dot4(ov, w0);
                a1 += dot4(ov, w1);
            }
            int hw = (wy * 4 + (px >> 2)) * HH + wx * 4 + (px & 3);
            size_t o0 = ((size_t)b * CC + d) * HWN + hw;
            out[o0]       = a0;
            out[o0 + HWN] = a1;
        }
    }
}

// =============================================================================
extern "C" void kernel_launch(void* const* d_in, const int* in_sizes, int n_in,
                              void* d_out, int out_size) {
    const float* x     = (const float*)d_in[0];
    const float* Wqkv  = (const float*)d_in[1];
    const float* Wproj = (const float*)d_in[2];
    const float* bproj = (const float*)d_in[3];
    const int*   topk  = (const int*)d_in[4];
    float* out = (float*)d_out;

    const int smemA = (14336 + 64 * ST_STRIDE) * 4;            // 86272
    const int smemB = 40128 * 4;                               // 160512 (fixes OOB poss[])

    cudaFuncSetAttribute(qkv_kernel,  cudaFuncAttributeMaxDynamicSharedMemorySize, smemA);
    cudaFuncSetAttribute(attn_kernel, cudaFuncAttributeMaxDynamicSharedMemorySize, smemB);

    qkv_kernel<<<dim3(32, 16), 512, smemA>>>(x, Wqkv);
    attn_kernel<<<BB * NWIN, 1024, smemB>>>(topk, Wproj, bproj, out);
}

// round 6
// speedup vs baseline: 1.2657x; 1.2657x over previous
#include <cuda_runtime.h>

#define BB    16
#define CC    112
#define HH    64
#define HWN   4096
#define NHEAD 4
#define HD    28
#define NWIN  256
#define TOPK  128
#define SCALE 0.18898223650461363f   // 28^-0.5

#define KV_STRIDE 36    // per-head K/V/Q row stride (floats): 9 f4 (9%8=1) conflict-free
#define S_STRIDE  132   // S row stride: 33 f4 (33%8=1) conflict-free f4 access
#define ST_STRIDE 113   // qkv stage stride
#define PJ_STRIDE 116   // proj o-tile row stride

// ---------------- scratch (device globals; no allocation allowed) ------------
__device__ __align__(16) float g_q[BB * HWN * CC];
__device__ __align__(16) float g_k[BB * HWN * CC];
__device__ __align__(16) float g_v[BB * HWN * CC];
__device__ __align__(16) float g_o[BB * HWN * CC];

__device__ __forceinline__ float dot4(float4 a, float4 b) {
    return a.x * b.x + a.y * b.y + a.z * b.z + a.w * b.w;
}

// =============================================================================
// Kernel A: QKV projection (unchanged; 197us, 2 blocks/SM).
// =============================================================================
__global__ __launch_bounds__(512, 2) void qkv_kernel(const float* __restrict__ x,
                                                     const float* __restrict__ Wqkv) {
    extern __shared__ float sm[];
    float* xs = sm;                          // [112][128]    14336
    float* st = sm + 14336;                  // [64][113]      7232

    const int tid = threadIdx.x;
    const int b   = blockIdx.y;
    const int hw0 = blockIdx.x * 128;

    for (int i = tid; i < 3584; i += 512) {
        int c = i >> 5, p4 = i & 31;
        ((float4*)xs)[c * 32 + p4] =
            ((const float4*)(x + (b * CC + c) * HWN + hw0))[p4];
    }
    __syncthreads();

    const int pg = tid & 31;
    const int dg = tid >> 5;
    const int px = pg * 4;

    for (int seg = 0; seg < 3; seg++) {
        const float scl = (seg == 0) ? SCALE : 1.0f;
        float acc[4][7];
        #pragma unroll
        for (int i = 0; i < 4; i++)
            #pragma unroll
            for (int j = 0; j < 7; j++) acc[i][j] = 0.0f;

        const float* wsp = Wqkv + (seg * CC + dg * 7) * CC;
        #pragma unroll 2
        for (int c4 = 0; c4 < 28; c4++) {
            float4 xv[4];
            #pragma unroll
            for (int u = 0; u < 4; u++)
                xv[u] = *(const float4*)(xs + (c4 * 4 + u) * 128 + px);
            #pragma unroll
            for (int j = 0; j < 7; j++) {
                float4 w4 = __ldg((const float4*)(wsp + j * CC + c4 * 4));
                #pragma unroll
                for (int i = 0; i < 4; i++) {
                    acc[i][j] += ((const float*)&xv[0])[i] * w4.x
                               + ((const float*)&xv[1])[i] * w4.y
                               + ((const float*)&xv[2])[i] * w4.z
                               + ((const float*)&xv[3])[i] * w4.w;
                }
            }
        }

        float* dst = (seg == 0 ? g_q : (seg == 1 ? g_k : g_v)) + (size_t)(b * HWN + hw0) * CC;
        #pragma unroll
        for (int wv = 0; wv < 2; wv++) {
            if ((pg >> 4) == wv) {
                #pragma unroll
                for (int i = 0; i < 4; i++)
                    #pragma unroll
                    for (int j = 0; j < 7; j++)
                        st[(px - wv * 64 + i) * ST_STRIDE + dg * 7 + j] = acc[i][j] * scl;
            }
            __syncthreads();
            for (int i = tid; i < 1792; i += 512) {
                int p = i / 28, c4 = i - p * 28;
                const float* s = st + p * ST_STRIDE + c4 * 4;
                ((float4*)dst)[wv * 1792 + i] = make_float4(s[0], s[1], s[2], s[3]);
            }
            __syncthreads();
        }
    }
}

// =============================================================================
// Kernel B: windowed top-k attention, one block per (batch, window, HEAD).
// 256 threads, 48KB smem -> 4 blocks/SM.
// =============================================================================
__global__ __launch_bounds__(256, 4) void attn_kernel(const int* __restrict__ topk) {
    extern __shared__ float sm[];
    float* Ks   = sm;                        // 128 x 36 = 4608
    float* Vs   = sm + 4608;                 // 128 x 36 = 4608
    float* Qs   = sm + 9216;                 // 16 x 36  = 576 (reused as PV partial buf)
    float* S    = sm + 9792;                 // 16 x 132 = 2112
    float* sums = sm + 11904;                // 16
    int*   poss = (int*)(sm + 11920);        // 128 -> total 12048 floats

    const int tid = threadIdx.x;
    const int bx  = blockIdx.x;
    const int h   = bx & 3;
    const int w   = (bx >> 2) & 255;
    const int b   = bx >> 10;
    const int wy  = w >> 4, wx = w & 15;

    if (tid < TOPK) poss[tid] = topk[w * TOPK + tid];
    __syncthreads();

    // gather this head's 28-float slice of K and V for 128 rows
    for (int i = tid; i < 896; i += 256) {
        int row = i / 7, c4 = i - row * 7;
        size_t base = (size_t)(b * HWN + poss[row]) * CC + h * HD + c4 * 4;
        *(float4*)(Ks + row * KV_STRIDE + c4 * 4) = *(const float4*)(g_k + base);
        *(float4*)(Vs + row * KV_STRIDE + c4 * 4) = *(const float4*)(g_v + base);
    }
    if (tid < 112) {
        int qi = tid / 7, c4 = tid - qi * 7;
        int hw = (wy * 4 + (qi >> 2)) * HH + wx * 4 + (qi & 3);
        *(float4*)(Qs + qi * KV_STRIDE + c4 * 4) =
            *(const float4*)(g_q + (size_t)(b * HWN + hw) * CC + h * HD + c4 * 4);
    }
    __syncthreads();

    // ---- S = Q K^T : thread = (qg of 4 qi, khalf) x lane; tile 4qi x 2kj ----
    {
        const int lane = tid & 31;
        const int kh   = (tid >> 5) & 1;
        const int qg   = tid >> 6;

        float acc[4][2];
        #pragma unroll
        for (int i = 0; i < 4; i++) { acc[i][0] = 0.f; acc[i][1] = 0.f; }

        const float* kp = Ks + (kh * 64 + lane) * KV_STRIDE;
        const float* qp = Qs + (qg * 4) * KV_STRIDE;     // warp-uniform
        #pragma unroll
        for (int s = 0; s < 7; s++) {
            float4 k0 = *(const float4*)(kp + s * 4);
            float4 k1 = *(const float4*)(kp + 32 * KV_STRIDE + s * 4);
            #pragma unroll
            for (int i = 0; i < 4; i++) {
                float4 qv = *(const float4*)(qp + i * KV_STRIDE + s * 4);  // broadcast
                acc[i][0] += dot4(qv, k0);
                acc[i][1] += dot4(qv, k1);
            }
        }
        float* srow = S + (qg * 4) * S_STRIDE + kh * 64 + lane;
        #pragma unroll
        for (int i = 0; i < 4; i++) {
            srow[i * S_STRIDE]      = acc[i][0];
            srow[i * S_STRIDE + 32] = acc[i][1];
        }
    }
    __syncthreads();

    // ---- softmax (un-normalized exp; per-row sums), float4 I/O ----
    {
        const int r   = tid >> 4;
        const int sub = tid & 15;
        float* row = S + r * S_STRIDE + sub * 8;
        float4 a = *(float4*)row;
        float4 c = *(float4*)(row + 4);
        float mx = fmaxf(fmaxf(fmaxf(a.x, a.y), fmaxf(a.z, a.w)),
                         fmaxf(fmaxf(c.x, c.y), fmaxf(c.z, c.w)));
        mx = fmaxf(mx, __shfl_xor_sync(0xffffffffu, mx, 1));
        mx = fmaxf(mx, __shfl_xor_sync(0xffffffffu, mx, 2));
        mx = fmaxf(mx, __shfl_xor_sync(0xffffffffu, mx, 4));
        mx = fmaxf(mx, __shfl_xor_sync(0xffffffffu, mx, 8));
        a.x = __expf(a.x - mx); a.y = __expf(a.y - mx);
        a.z = __expf(a.z - mx); a.w = __expf(a.w - mx);
        c.x = __expf(c.x - mx); c.y = __expf(c.y - mx);
        c.z = __expf(c.z - mx); c.w = __expf(c.w - mx);
        float sum = a.x + a.y + a.z + a.w + c.x + c.y + c.z + c.w;
        sum += __shfl_xor_sync(0xffffffffu, sum, 1);
        sum += __shfl_xor_sync(0xffffffffu, sum, 2);
        sum += __shfl_xor_sync(0xffffffffu, sum, 4);
        sum += __shfl_xor_sync(0xffffffffu, sum, 8);
        *(float4*)row       = a;
        *(float4*)(row + 4) = c;
        if (sub == 0) sums[r] = sum;
    }
    __syncthreads();

    // ---- O = P V : thread = (slot of 4 d, qi, kj-half); float4 P loads ----
    {
        const int slot = tid & 7;            // 0..6 active
        const int qi   = (tid >> 3) & 15;
        const int half = tid >> 7;
        float4 acc = make_float4(0.f, 0.f, 0.f, 0.f);
        if (slot < 7) {
            const float* prow = S + qi * S_STRIDE + half * 64;
            const float* vp   = Vs + (half * 64) * KV_STRIDE + slot * 4;
            #pragma unroll 4
            for (int k4 = 0; k4 < 16; k4++) {
                float4 p  = *(const float4*)(prow + k4 * 4);
                float4 v0 = *(const float4*)(vp + (k4 * 4 + 0) * KV_STRIDE);
                float4 v1 = *(const float4*)(vp + (k4 * 4 + 1) * KV_STRIDE);
                float4 v2 = *(const float4*)(vp + (k4 * 4 + 2) * KV_STRIDE);
                float4 v3 = *(const float4*)(vp + (k4 * 4 + 3) * KV_STRIDE);
                acc.x += p.x * v0.x + p.y * v1.x + p.z * v2.x + p.w * v3.x;
                acc.y += p.x * v0.y + p.y * v1.y + p.z * v2.y + p.w * v3.y;
                acc.z += p.x * v0.z + p.y * v1.z + p.z * v2.z + p.w * v3.z;
                acc.w += p.x * v0.w + p.y * v1.w + p.z * v2.w + p.w * v3.w;
            }
            if (half == 1) {
                float* bp = Qs + qi * KV_STRIDE + slot * 4;   // Qs is dead; reuse
                *(float4*)bp = acc;
            }
        }
        __syncthreads();
        if (slot < 7 && half == 0) {
            float4 pb = *(const float4*)(Qs + qi * KV_STRIDE + slot * 4);
            float inv = 1.0f / sums[qi];
            acc.x = (acc.x + pb.x) * inv;
            acc.y = (acc.y + pb.y) * inv;
            acc.z = (acc.z + pb.z) * inv;
            acc.w = (acc.w + pb.w) * inv;
            int hw = (wy * 4 + (qi >> 2)) * HH + wx * 4 + (qi & 3);
            *(float4*)(g_o + (size_t)(b * HWN + hw) * CC + h * HD + slot * 4) = acc;
        }
    }
}

// =============================================================================
// Kernel C: output projection (standalone; 128 px/block amortizes W).
// =============================================================================
__global__ __launch_bounds__(512, 2) void proj_kernel(const float* __restrict__ Wp,
                                                      const float* __restrict__ bias,
                                                      float* __restrict__ out) {
    extern __shared__ float sm[];
    float* os = sm;                  // [128][116]  14848
    float* wp = sm + 14848;          // [112][112]  12544
    float* bs = sm + 27392;          // 112

    const int tid = threadIdx.x;
    const int b   = blockIdx.y;
    const int hw0 = blockIdx.x * 128;

    const float4* osrc = ((const float4*)g_o) + (size_t)(b * HWN + hw0) * 28;
    for (int i = tid; i < 3584; i += 512) {
        int row = i / 28, c4 = i - row * 28;
        ((float4*)os)[row * 29 + c4] = osrc[i];
    }
    for (int i = tid; i < 3136; i += 512) ((float4*)wp)[i] = ((const float4*)Wp)[i];
    if (tid < CC) bs[tid] = bias[tid];
    __syncthreads();

    const int px = tid & 127;        // lanes = consecutive pixels
    const int dg = tid >> 7;         // 0..3, uniform within warp
    float acc[28];
    #pragma unroll
    for (int j = 0; j < 28; j++) acc[j] = bs[dg * 28 + j];

    const float* orow = os + px * PJ_STRIDE;
    const float* wrow = wp + dg * 28 * CC;
    #pragma unroll 2
    for (int c4 = 0; c4 < 28; c4++) {
        float4 xv = *(const float4*)(orow + c4 * 4);
        #pragma unroll
        for (int j = 0; j < 28; j++) {
            float4 w4 = *(const float4*)(wrow + j * CC + c4 * 4);  // broadcast
            acc[j] += dot4(xv, w4);
        }
    }
    float* op = out + ((size_t)b * CC + dg * 28) * HWN + hw0 + px;
    #pragma unroll
    for (int j = 0; j < 28; j++) op[j * HWN] = acc[j];
}

// =============================================================================
extern "C" void kernel_launch(void* const* d_in, const int* in_sizes, int n_in,
                              void* d_out, int out_size) {
    const float* x     = (const float*)d_in[0];
    const float* Wqkv  = (const float*)d_in[1];
    const float* Wproj = (const float*)d_in[2];
    const float* bproj = (const float*)d_in[3];
    const int*   topk  = (const int*)d_in[4];
    float* out = (float*)d_out;

    const int smemA = (14336 + 64 * ST_STRIDE) * 4;            // 86272
    const int smemB = 12048 * 4;                               // 48192
    const int smemC = (14848 + 12544 + 112) * 4;               // 110016

    cudaFuncSetAttribute(qkv_kernel,  cudaFuncAttributeMaxDynamicSharedMemorySize, smemA);
    cudaFuncSetAttribute(attn_kernel, cudaFuncAttributeMaxDynamicSharedMemorySize, smemB);
    cudaFuncSetAttribute(proj_kernel, cudaFuncAttributeMaxDynamicSharedMemorySize, smemC);

    qkv_kernel<<<dim3(32, 16), 512, smemA>>>(x, Wqkv);
    attn_kernel<<<BB * NWIN * NHEAD, 256, smemB>>>(topk);
    proj_kernel<<<dim3(32, 16), 512, smemC>>>(Wproj, bproj, out);
}

// round 8
// speedup vs baseline: 1.3694x; 1.0820x over previous
#include <cuda_runtime.h>
#include <cstdint>

#define BB    16
#define CC    112
#define HH    64
#define HWN   4096
#define NHEAD 4
#define HD    28
#define NWIN  256
#define TOPK  128
#define SCALE 0.18898223650461363f   // 28^-0.5

#define S_STRIDE  132   // S row stride: 33 f4 (odd) -> conflict-free
#define ST_STRIDE 113   // qkv stage stride
#define PJ_STRIDE 116   // proj o-tile row stride

// attn smem float offsets
#define KS_F   0        // 128 x 32 (swizzled)
#define VS_F   4096     // 128 x 32 (swizzled)
#define QS_F   8192     // 16 x 36 (also PV partial buffer)
#define S_F    8768     // 16 x 132
#define RMAX_F 10880    // 16 x 2
#define RSUM_F 10912    // 16 x 2
#define ATTN_SMEM_F 10944

// ---------------- scratch (device globals; no allocation allowed) ------------
__device__ __align__(16) float g_q[BB * HWN * CC];
__device__ __align__(16) float g_k[BB * HWN * CC];
__device__ __align__(16) float g_v[BB * HWN * CC];
__device__ __align__(16) float g_o[BB * HWN * CC];

__device__ __forceinline__ float dot4(float4 a, float4 b) {
    return a.x * b.x + a.y * b.y + a.z * b.z + a.w * b.w;
}
__device__ __forceinline__ uint32_t smem_u32(const void* p) {
    uint32_t a;
    asm("{ .reg .u64 t; cvta.to.shared.u64 t, %1; cvt.u32.u64 %0, t; }" : "=r"(a) : "l"(p));
    return a;
}
__device__ __forceinline__ void cp16(uint32_t dst, const void* src) {
    asm volatile("cp.async.cg.shared.global [%0], [%1], 16;" :: "r"(dst), "l"(src) : "memory");
}

// =============================================================================
// Kernel A: QKV projection (unchanged from round 6: 196us, 2 blocks/SM).
// =============================================================================
__global__ __launch_bounds__(512, 2) void qkv_kernel(const float* __restrict__ x,
                                                     const float* __restrict__ Wqkv) {
    extern __shared__ float sm[];
    float* xs = sm;                          // [112][128]    14336
    float* st = sm + 14336;                  // [64][113]      7232

    const int tid = threadIdx.x;
    const int b   = blockIdx.y;
    const int hw0 = blockIdx.x * 128;

    for (int i = tid; i < 3584; i += 512) {
        int c = i >> 5, p4 = i & 31;
        ((float4*)xs)[c * 32 + p4] =
            ((const float4*)(x + (b * CC + c) * HWN + hw0))[p4];
    }
    __syncthreads();

    const int pg = tid & 31;
    const int dg = tid >> 5;
    const int px = pg * 4;

    for (int seg = 0; seg < 3; seg++) {
        const float scl = (seg == 0) ? SCALE : 1.0f;
        float acc[4][7];
        #pragma unroll
        for (int i = 0; i < 4; i++)
            #pragma unroll
            for (int j = 0; j < 7; j++) acc[i][j] = 0.0f;

        const float* wsp = Wqkv + (seg * CC + dg * 7) * CC;
        #pragma unroll 2
        for (int c4 = 0; c4 < 28; c4++) {
            float4 xv[4];
            #pragma unroll
            for (int u = 0; u < 4; u++)
                xv[u] = *(const float4*)(xs + (c4 * 4 + u) * 128 + px);
            #pragma unroll
            for (int j = 0; j < 7; j++) {
                float4 w4 = __ldg((const float4*)(wsp + j * CC + c4 * 4));
                #pragma unroll
                for (int i = 0; i < 4; i++) {
                    acc[i][j] += ((const float*)&xv[0])[i] * w4.x
                               + ((const float*)&xv[1])[i] * w4.y
                               + ((const float*)&xv[2])[i] * w4.z
                               + ((const float*)&xv[3])[i] * w4.w;
                }
            }
        }

        float* dst = (seg == 0 ? g_q : (seg == 1 ? g_k : g_v)) + (size_t)(b * HWN + hw0) * CC;
        #pragma unroll
        for (int wv = 0; wv < 2; wv++) {
            if ((pg >> 4) == wv) {
                #pragma unroll
                for (int i = 0; i < 4; i++)
                    #pragma unroll
                    for (int j = 0; j < 7; j++)
                        st[(px - wv * 64 + i) * ST_STRIDE + dg * 7 + j] = acc[i][j] * scl;
            }
            __syncthreads();
            for (int i = tid; i < 1792; i += 512) {
                int p = i / 28, c4 = i - p * 28;
                const float* s = st + p * ST_STRIDE + c4 * 4;
                ((float4*)dst)[wv * 1792 + i] = make_float4(s[0], s[1], s[2], s[3]);
            }
            __syncthreads();
        }
    }
}

// =============================================================================
// Kernel B: windowed top-k attention. One block per (batch, window, head).
// 256 threads, 43.8KB smem -> 5 blocks/SM. cp.async gather, fused softmax.
// K/V rows: 8 f4 slots, swizzled col = c4 ^ (row & 7).
// =============================================================================
__global__ __launch_bounds__(256, 5) void attn_kernel(const int* __restrict__ topk) {
    extern __shared__ float sm[];
    float* Ks   = sm + KS_F;
    float* Vs   = sm + VS_F;
    float* Qs   = sm + QS_F;
    float* S    = sm + S_F;
    float* rmax = sm + RMAX_F;
    float* rsum = sm + RSUM_F;

    const uint32_t sbase = smem_u32(sm);
    const int tid = threadIdx.x;
    const int bx  = blockIdx.x;
    const int h   = bx & 3;
    const int w   = (bx >> 2) & 255;
    const int b   = bx >> 10;
    const int wy  = w >> 4, wx = w & 15;

    // ---- gather K/V (cp.async, swizzled) + Q ----
    {
        const int* tkw = topk + w * TOPK;
        for (int i = tid; i < 896; i += 256) {
            int row = i / 7, c4 = i - row * 7;
            int pos = __ldg(tkw + row);
            size_t gb = (size_t)(b * HWN + pos) * CC + h * HD + c4 * 4;
            uint32_t off = (uint32_t)(row * 32 + ((c4 ^ (row & 7)) << 2)) * 4;
            cp16(sbase + KS_F * 4 + off, g_k + gb);
            cp16(sbase + VS_F * 4 + off, g_v + gb);
        }
        if (tid < 112) {
            int qi = tid / 7, c4 = tid - qi * 7;
            int hw = (wy * 4 + (qi >> 2)) * HH + wx * 4 + (qi & 3);
            cp16(sbase + (QS_F + qi * 36 + c4 * 4) * 4,
                 g_q + (size_t)(b * HWN + hw) * CC + h * HD + c4 * 4);
        }
        asm volatile("cp.async.commit_group;");
        asm volatile("cp.async.wait_group 0;" ::: "memory");
    }
    __syncthreads();

    // ---- S = Q K^T with fused softmax reductions ----
    {
        const int lane = tid & 31;
        const int kh   = (tid >> 5) & 1;
        const int qg   = tid >> 6;

        float acc[4][2];
        #pragma unroll
        for (int i = 0; i < 4; i++) { acc[i][0] = 0.f; acc[i][1] = 0.f; }

        const float* kp = Ks + (kh * 64 + lane) * 32;
        const float* qp = Qs + (qg * 4) * 36;          // warp-uniform
        #pragma unroll
        for (int s = 0; s < 7; s++) {
            const int sc = (s ^ (lane & 7)) << 2;
            float4 k0 = *(const float4*)(kp + sc);
            float4 k1 = *(const float4*)(kp + 1024 + sc);    // +32 rows * 32
            #pragma unroll
            for (int i = 0; i < 4; i++) {
                float4 qv = *(const float4*)(qp + i * 36 + s * 4);  // broadcast
                acc[i][0] += dot4(qv, k0);
                acc[i][1] += dot4(qv, k1);
            }
        }

        // per-warp max over its 64 kj, per qi
        #pragma unroll
        for (int i = 0; i < 4; i++) {
            float m = fmaxf(acc[i][0], acc[i][1]);
            m = fmaxf(m, __shfl_xor_sync(0xffffffffu, m, 1));
            m = fmaxf(m, __shfl_xor_sync(0xffffffffu, m, 2));
            m = fmaxf(m, __shfl_xor_sync(0xffffffffu, m, 4));
            m = fmaxf(m, __shfl_xor_sync(0xffffffffu, m, 8));
            m = fmaxf(m, __shfl_xor_sync(0xffffffffu, m, 16));
            if (lane == 0) rmax[(qg * 4 + i) * 2 + kh] = m;
        }
        __syncthreads();

        float* srow = S + (qg * 4) * S_STRIDE + kh * 64 + lane;
        #pragma unroll
        for (int i = 0; i < 4; i++) {
            const int qi = qg * 4 + i;
            float mx = fmaxf(rmax[qi * 2], rmax[qi * 2 + 1]);
            float e0 = __expf(acc[i][0] - mx);
            float e1 = __expf(acc[i][1] - mx);
            srow[i * S_STRIDE]      = e0;
            srow[i * S_STRIDE + 32] = e1;
            float s2 = e0 + e1;
            s2 += __shfl_xor_sync(0xffffffffu, s2, 1);
            s2 += __shfl_xor_sync(0xffffffffu, s2, 2);
            s2 += __shfl_xor_sync(0xffffffffu, s2, 4);
            s2 += __shfl_xor_sync(0xffffffffu, s2, 8);
            s2 += __shfl_xor_sync(0xffffffffu, s2, 16);
            if (lane == 0) rsum[qi * 2 + kh] = s2;
        }
    }
    __syncthreads();

    // ---- O = P V : split-K over kj halves; half 1 -> partial buf (Qs) ----
    {
        const int slot = tid & 7;            // 0..6 active, 4 d's each
        const int qi   = (tid >> 3) & 15;
        const int half = tid >> 7;
        float4 acc = make_float4(0.f, 0.f, 0.f, 0.f);
        if (slot < 7) {
            const float* prow  = S + qi * S_STRIDE + half * 64;
            const float* vbase = Vs + (half * 64) * 32;
            #pragma unroll 4
            for (int k4 = 0; k4 < 16; k4++) {
                float4 p = *(const float4*)(prow + k4 * 4);
                #pragma unroll
                for (int u = 0; u < 4; u++) {
                    const int k = k4 * 4 + u;
                    float4 v = *(const float4*)(vbase + k * 32 + ((slot ^ (k & 7)) << 2));
                    float pu = ((const float*)&p)[u];
                    acc.x += pu * v.x; acc.y += pu * v.y;
                    acc.z += pu * v.z; acc.w += pu * v.w;
                }
            }
            if (half == 1) {
                *(float4*)(Qs + qi * 36 + slot * 4) = acc;   // Qs is dead; reuse
            }
        }
        __syncthreads();
        if (slot < 7 && half == 0) {
            float4 pb = *(const float4*)(Qs + qi * 36 + slot * 4);
            float inv = 1.0f / (rsum[qi * 2] + rsum[qi * 2 + 1]);
            acc.x = (acc.x + pb.x) * inv;
            acc.y = (acc.y + pb.y) * inv;
            acc.z = (acc.z + pb.z) * inv;
            acc.w = (acc.w + pb.w) * inv;
            int hw = (wy * 4 + (qi >> 2)) * HH + wx * 4 + (qi & 3);
            *(float4*)(g_o + (size_t)(b * HWN + hw) * CC + h * HD + slot * 4) = acc;
        }
    }
}

// =============================================================================
// Kernel C: output projection (unchanged from round 6)
// =============================================================================
__global__ __launch_bounds__(512, 2) void proj_kernel(const float* __restrict__ Wp,
                                                      const float* __restrict__ bias,
                                                      float* __restrict__ out) {
    extern __shared__ float sm[];
    float* os = sm;                  // [128][116]  14848
    float* wp = sm + 14848;          // [112][112]  12544
    float* bs = sm + 27392;          // 112

    const int tid = threadIdx.x;
    const int b   = blockIdx.y;
    const int hw0 = blockIdx.x * 128;

    const float4* osrc = ((const float4*)g_o) + (size_t)(b * HWN + hw0) * 28;
    for (int i = tid; i < 3584; i += 512) {
        int row = i / 28, c4 = i - row * 28;
        ((float4*)os)[row * 29 + c4] = osrc[i];
    }
    for (int i = tid; i < 3136; i += 512) ((float4*)wp)[i] = ((const float4*)Wp)[i];
    if (tid < CC) bs[tid] = bias[tid];
    __syncthreads();

    const int px = tid & 127;
    const int dg = tid >> 7;
    float acc[28];
    #pragma unroll
    for (int j = 0; j < 28; j++) acc[j] = bs[dg * 28 + j];

    const float* orow = os + px * PJ_STRIDE;
    const float* wrow = wp + dg * 28 * CC;
    #pragma unroll 2
    for (int c4 = 0; c4 < 28; c4++) {
        float4 xv = *(const float4*)(orow + c4 * 4);
        #pragma unroll
        for (int j = 0; j < 28; j++) {
            float4 w4 = *(const float4*)(wrow + j * CC + c4 * 4);
            acc[j] += dot4(xv, w4);
        }
    }
    float* op = out + ((size_t)b * CC + dg * 28) * HWN + hw0 + px;
    #pragma unroll
    for (int j = 0; j < 28; j++) op[j * HWN] = acc[j];
}

// =============================================================================
extern "C" void kernel_launch(void* const* d_in, const int* in_sizes, int n_in,
                              void* d_out, int out_size) {
    const float* x     = (const float*)d_in[0];
    const float* Wqkv  = (const float*)d_in[1];
    const float* Wproj = (const float*)d_in[2];
    const float* bproj = (const float*)d_in[3];
    const int*   topk  = (const int*)d_in[4];
    float* out = (float*)d_out;

    const int smemA = (14336 + 64 * ST_STRIDE) * 4;            // 86272
    const int smemB = ATTN_SMEM_F * 4;                         // 43776
    const int smemC = (14848 + 12544 + 112) * 4;               // 110016

    cudaFuncSetAttribute(qkv_kernel,  cudaFuncAttributeMaxDynamicSharedMemorySize, smemA);
    cudaFuncSetAttribute(attn_kernel, cudaFuncAttributeMaxDynamicSharedMemorySize, smemB);
    cudaFuncSetAttribute(proj_kernel, cudaFuncAttributeMaxDynamicSharedMemorySize, smemC);

    qkv_kernel<<<dim3(32, 16), 512, smemA>>>(x, Wqkv);
    attn_kernel<<<BB * NWIN * NHEAD, 256, smemB>>>(topk);
    proj_kernel<<<dim3(32, 16), 512, smemC>>>(Wproj, bproj, out);
}

// round 9
// speedup vs baseline: 1.8449x; 1.3472x over previous
#include <cuda_runtime.h>
#include <cuda_bf16.h>
#include <cstdint>

#define BB    16
#define CC    112
#define HH    64
#define HWN   4096
#define NHEAD 4
#define HD    28
#define NWIN  256
#define TOPK  128
#define SCALE 0.18898223650461363f   // 28^-0.5

#define S_STRIDE  132
#define PJ_STRIDE 116

// qkv mma smem byte offsets (dynamic smem base is 16B aligned; strides 240B)
#define AH_B   0        // Ah [128 rows][240B]  = 30720
#define AL_B   30720    // Al                   = 30720
#define WH_B   61440    // Wh [112][240B]       = 26880  (xs chunk overlaps here)
#define WL_B   88320    // Wl                   = 26880
#define QKV_SMEM_B 115200
#define XS_F   (WH_B / 4)   // fp32 x chunk [56][128] = 28672 B, reused before W conv

// attn smem float offsets
#define KS_F   0
#define VS_F   4096
#define QS_F   8192
#define S_F    8768
#define RMAX_F 10880
#define RSUM_F 10912
#define ATTN_SMEM_F 10944

// ---------------- scratch (device globals; no allocation allowed) ------------
__device__ __align__(16) float g_q[BB * HWN * CC];
__device__ __align__(16) float g_k[BB * HWN * CC];
__device__ __align__(16) float g_v[BB * HWN * CC];
__device__ __align__(16) float g_o[BB * HWN * CC];

__device__ __forceinline__ float dot4(float4 a, float4 b) {
    return a.x * b.x + a.y * b.y + a.z * b.z + a.w * b.w;
}
__device__ __forceinline__ uint32_t smem_u32(const void* p) {
    uint32_t a;
    asm("{ .reg .u64 t; cvta.to.shared.u64 t, %1; cvt.u32.u64 %0, t; }" : "=r"(a) : "l"(p));
    return a;
}
__device__ __forceinline__ void cp16(uint32_t dst, const void* src) {
    asm volatile("cp.async.cg.shared.global [%0], [%1], 16;" :: "r"(dst), "l"(src) : "memory");
}
__device__ __forceinline__ void ldsm4(uint32_t* r, uint32_t a) {
    asm volatile("ldmatrix.sync.aligned.m8n8.x4.shared.b16 {%0,%1,%2,%3}, [%4];"
                 : "=r"(r[0]), "=r"(r[1]), "=r"(r[2]), "=r"(r[3]) : "r"(a));
}
__device__ __forceinline__ void ldsm2(uint32_t* r, uint32_t a) {
    asm volatile("ldmatrix.sync.aligned.m8n8.x2.shared.b16 {%0,%1}, [%2];"
                 : "=r"(r[0]), "=r"(r[1]) : "r"(a));
}
__device__ __forceinline__ void mma_bf16(float* d, const uint32_t* a, const uint32_t* b) {
    asm volatile("mma.sync.aligned.m16n8k16.row.col.f32.bf16.bf16.f32 "
                 "{%0,%1,%2,%3}, {%4,%5,%6,%7}, {%8,%9}, {%0,%1,%2,%3};"
                 : "+f"(d[0]), "+f"(d[1]), "+f"(d[2]), "+f"(d[3])
                 : "r"(a[0]), "r"(a[1]), "r"(a[2]), "r"(a[3]), "r"(b[0]), "r"(b[1]));
}
__device__ __forceinline__ void split_pack(float a0, float a1, uint32_t& hi, uint32_t& lo) {
    __nv_bfloat16 h0 = __float2bfloat16(a0);
    __nv_bfloat16 h1 = __float2bfloat16(a1);
    __nv_bfloat16 l0 = __float2bfloat16(a0 - __bfloat162float(h0));
    __nv_bfloat16 l1 = __float2bfloat16(a1 - __bfloat162float(h1));
    hi = ((uint32_t)__bfloat16_as_ushort(h1) << 16) | __bfloat16_as_ushort(h0);
    lo = ((uint32_t)__bfloat16_as_ushort(l1) << 16) | __bfloat16_as_ushort(l0);
}

// =============================================================================
// Kernel A: QKV projection via mma.sync bf16-split (3-term fp32 emulation).
// Block = (batch, 128-px tile), 512 threads. 16 warps = 8 m-tiles x 2 n-halves.
// =============================================================================
__global__ __launch_bounds__(512, 2) void qkv_kernel(const float* __restrict__ x,
                                                     const float* __restrict__ Wqkv) {
    extern __shared__ char smb[];
    float* xs = (float*)(smb + WH_B);     // fp32 chunk buffer (dead before W conv)
    const uint32_t sbase = smem_u32(smb);

    const int tid = threadIdx.x;
    const int b   = blockIdx.y;
    const int hw0 = blockIdx.x * 128;

    // ---- convert A = x tile -> Ah/Al bf16 [px][c], two 56-channel chunks ----
    #pragma unroll
    for (int chunk = 0; chunk < 2; chunk++) {
        for (int i = tid; i < 1792; i += 512) {        // 56 rows x 32 f4
            int c = i >> 5, p4 = i & 31;
            ((float4*)xs)[i] =
                ((const float4*)(x + (b * CC + chunk * 56 + c) * HWN + hw0))[p4];
        }
        __syncthreads();
        for (int i = tid; i < 3584; i += 512) {        // 128 px x 28 c-pairs
            int px = i & 127, cp = i >> 7;
            float v0 = xs[(cp * 2) * 128 + px];
            float v1 = xs[(cp * 2 + 1) * 128 + px];
            uint32_t hi, lo;
            split_pack(v0, v1, hi, lo);
            int idx = px * 60 + chunk * 28 + cp;       // u32 units (240B rows)
            ((uint32_t*)(smb + AH_B))[idx] = hi;
            ((uint32_t*)(smb + AL_B))[idx] = lo;
        }
        __syncthreads();
    }

    const int lane = tid & 31;
    const int wid  = tid >> 5;
    const int wm   = wid & 7;           // m-tile (16 px)
    const int wn   = wid >> 3;          // n-half (56 d)
    const int mrow = wm * 16;

    // A ldmatrix.x4 lane addressing
    const int amat = lane >> 3, ar = lane & 7;
    const uint32_t a_off = (uint32_t)((mrow + ar + (amat & 1) * 8) * 240
                                      + (amat >> 1) * 16);
    // B ldmatrix.x2 lane addressing (lanes >=16 give harmless dup addresses)
    const uint32_t b_lane_off = (uint32_t)((lane & 7) * 240 + ((lane >> 3) & 1) * 16);

    const int orow  = mrow + (lane >> 2);      // output row (px)
    const int ocol0 = wn * 56 + 2 * (lane & 3);

    for (int seg = 0; seg < 3; seg++) {
        // ---- convert W segment -> Wh/Wl bf16 [d][c] (fold SCALE into seg 0) --
        const float s = (seg == 0) ? SCALE : 1.0f;
        for (int i = tid; i < 6272; i += 512) {        // 112 d x 56 c-pairs
            int d = i / 56, cp = i - d * 56;
            float2 wv = *(const float2*)(Wqkv + (size_t)(seg * CC + d) * CC + cp * 2);
            uint32_t hi, lo;
            split_pack(wv.x * s, wv.y * s, hi, lo);
            ((uint32_t*)(smb + WH_B))[d * 60 + cp] = hi;
            ((uint32_t*)(smb + WL_B))[d * 60 + cp] = lo;
        }
        __syncthreads();

        // ---- MMA mainloop: acc = Ah*Wh + Ah*Wl + Al*Wh ----
        float acc[7][4];
        #pragma unroll
        for (int nt = 0; nt < 7; nt++)
            #pragma unroll
            for (int j = 0; j < 4; j++) acc[nt][j] = 0.0f;

        #pragma unroll
        for (int ks = 0; ks < 7; ks++) {
            uint32_t ah[4], al[4];
            ldsm4(ah, sbase + AH_B + a_off + ks * 32);
            ldsm4(al, sbase + AL_B + a_off + ks * 32);
            #pragma unroll
            for (int nt = 0; nt < 7; nt++) {
                uint32_t bh[2], bl[2];
                uint32_t boff = (uint32_t)((wn * 56 + nt * 8) * 240) + b_lane_off + ks * 32;
                ldsm2(bh, sbase + WH_B + boff);
                ldsm2(bl, sbase + WL_B + boff);
                mma_bf16(acc[nt], ah, bh);
                mma_bf16(acc[nt], ah, bl);
                mma_bf16(acc[nt], al, bh);
            }
        }

        // ---- store fragments straight to g_q/g_k/g_v ----
        float* dst = (seg == 0 ? g_q : (seg == 1 ? g_k : g_v));
        float* base = dst + (size_t)(b * HWN + hw0 + orow) * CC;
        #pragma unroll
        for (int nt = 0; nt < 7; nt++) {
            int d = ocol0 + nt * 8;
            *(float2*)(base + d)            = make_float2(acc[nt][0], acc[nt][1]);
            *(float2*)(base + 8 * CC + d)   = make_float2(acc[nt][2], acc[nt][3]);
        }
        __syncthreads();   // W buffers reused next seg
    }
}

// =============================================================================
// Kernel B: windowed top-k attention (unchanged from round 8).
// =============================================================================
__global__ __launch_bounds__(256, 5) void attn_kernel(const int* __restrict__ topk) {
    extern __shared__ float sm[];
    float* Ks   = sm + KS_F;
    float* Vs   = sm + VS_F;
    float* Qs   = sm + QS_F;
    float* S    = sm + S_F;
    float* rmax = sm + RMAX_F;
    float* rsum = sm + RSUM_F;

    const uint32_t sbase = smem_u32(sm);
    const int tid = threadIdx.x;
    const int bx  = blockIdx.x;
    const int h   = bx & 3;
    const int w   = (bx >> 2) & 255;
    const int b   = bx >> 10;
    const int wy  = w >> 4, wx = w & 15;

    {
        const int* tkw = topk + w * TOPK;
        for (int i = tid; i < 896; i += 256) {
            int row = i / 7, c4 = i - row * 7;
            int pos = __ldg(tkw + row);
            size_t gb = (size_t)(b * HWN + pos) * CC + h * HD + c4 * 4;
            uint32_t off = (uint32_t)(row * 32 + ((c4 ^ (row & 7)) << 2)) * 4;
            cp16(sbase + KS_F * 4 + off, g_k + gb);
            cp16(sbase + VS_F * 4 + off, g_v + gb);
        }
        if (tid < 112) {
            int qi = tid / 7, c4 = tid - qi * 7;
            int hw = (wy * 4 + (qi >> 2)) * HH + wx * 4 + (qi & 3);
            cp16(sbase + (QS_F + qi * 36 + c4 * 4) * 4,
                 g_q + (size_t)(b * HWN + hw) * CC + h * HD + c4 * 4);
        }
        asm volatile("cp.async.commit_group;");
        asm volatile("cp.async.wait_group 0;" ::: "memory");
    }
    __syncthreads();

    {
        const int lane = tid & 31;
        const int kh   = (tid >> 5) & 1;
        const int qg   = tid >> 6;

        float acc[4][2];
        #pragma unroll
        for (int i = 0; i < 4; i++) { acc[i][0] = 0.f; acc[i][1] = 0.f; }

        const float* kp = Ks + (kh * 64 + lane) * 32;
        const float* qp = Qs + (qg * 4) * 36;
        #pragma unroll
        for (int s = 0; s < 7; s++) {
            const int sc = (s ^ (lane & 7)) << 2;
            float4 k0 = *(const float4*)(kp + sc);
            float4 k1 = *(const float4*)(kp + 1024 + sc);
            #pragma unroll
            for (int i = 0; i < 4; i++) {
                float4 qv = *(const float4*)(qp + i * 36 + s * 4);
                acc[i][0] += dot4(qv, k0);
                acc[i][1] += dot4(qv, k1);
            }
        }

        #pragma unroll
        for (int i = 0; i < 4; i++) {
            float m = fmaxf(acc[i][0], acc[i][1]);
            m = fmaxf(m, __shfl_xor_sync(0xffffffffu, m, 1));
            m = fmaxf(m, __shfl_xor_sync(0xffffffffu, m, 2));
            m = fmaxf(m, __shfl_xor_sync(0xffffffffu, m, 4));
            m = fmaxf(m, __shfl_xor_sync(0xffffffffu, m, 8));
            m = fmaxf(m, __shfl_xor_sync(0xffffffffu, m, 16));
            if (lane == 0) rmax[(qg * 4 + i) * 2 + kh] = m;
        }
        __syncthreads();

        float* srow = S + (qg * 4) * S_STRIDE + kh * 64 + lane;
        #pragma unroll
        for (int i = 0; i < 4; i++) {
            const int qi = qg * 4 + i;
            float mx = fmaxf(rmax[qi * 2], rmax[qi * 2 + 1]);
            float e0 = __expf(acc[i][0] - mx);
            float e1 = __expf(acc[i][1] - mx);
            srow[i * S_STRIDE]      = e0;
            srow[i * S_STRIDE + 32] = e1;
            float s2 = e0 + e1;
            s2 += __shfl_xor_sync(0xffffffffu, s2, 1);
            s2 += __shfl_xor_sync(0xffffffffu, s2, 2);
            s2 += __shfl_xor_sync(0xffffffffu, s2, 4);
            s2 += __shfl_xor_sync(0xffffffffu, s2, 8);
            s2 += __shfl_xor_sync(0xffffffffu, s2, 16);
            if (lane == 0) rsum[qi * 2 + kh] = s2;
        }
    }
    __syncthreads();

    {
        const int slot = tid & 7;
        const int qi   = (tid >> 3) & 15;
        const int half = tid >> 7;
        float4 acc = make_float4(0.f, 0.f, 0.f, 0.f);
        if (slot < 7) {
            const float* prow  = S + qi * S_STRIDE + half * 64;
            const float* vbase = Vs + (half * 64) * 32;
            #pragma unroll 4
            for (int k4 = 0; k4 < 16; k4++) {
                float4 p = *(const float4*)(prow + k4 * 4);
                #pragma unroll
                for (int u = 0; u < 4; u++) {
                    const int k = k4 * 4 + u;
                    float4 v = *(const float4*)(vbase + k * 32 + ((slot ^ (k & 7)) << 2));
                    float pu = ((const float*)&p)[u];
                    acc.x += pu * v.x; acc.y += pu * v.y;
                    acc.z += pu * v.z; acc.w += pu * v.w;
                }
            }
            if (half == 1) {
                *(float4*)(Qs + qi * 36 + slot * 4) = acc;
            }
        }
        __syncthreads();
        if (slot < 7 && half == 0) {
            float4 pb = *(const float4*)(Qs + qi * 36 + slot * 4);
            float inv = 1.0f / (rsum[qi * 2] + rsum[qi * 2 + 1]);
            acc.x = (acc.x + pb.x) * inv;
            acc.y = (acc.y + pb.y) * inv;
            acc.z = (acc.z + pb.z) * inv;
            acc.w = (acc.w + pb.w) * inv;
            int hw = (wy * 4 + (qi >> 2)) * HH + wx * 4 + (qi & 3);
            *(float4*)(g_o + (size_t)(b * HWN + hw) * CC + h * HD + slot * 4) = acc;
        }
    }
}

// =============================================================================
// Kernel C: output projection (unchanged from round 8).
// =============================================================================
__global__ __launch_bounds__(512, 2) void proj_kernel(const float* __restrict__ Wp,
                                                      const float* __restrict__ bias,
                                                      float* __restrict__ out) {
    extern __shared__ float sm[];
    float* os = sm;
    float* wp = sm + 14848;
    float* bs = sm + 27392;

    const int tid = threadIdx.x;
    const int b   = blockIdx.y;
    const int hw0 = blockIdx.x * 128;

    const float4* osrc = ((const float4*)g_o) + (size_t)(b * HWN + hw0) * 28;
    for (int i = tid; i < 3584; i += 512) {
        int row = i / 28, c4 = i - row * 28;
        ((float4*)os)[row * 29 + c4] = osrc[i];
    }
    for (int i = tid; i < 3136; i += 512) ((float4*)wp)[i] = ((const float4*)Wp)[i];
    if (tid < CC) bs[tid] = bias[tid];
    __syncthreads();

    const int px = tid & 127;
    const int dg = tid >> 7;
    float acc[28];
    #pragma unroll
    for (int j = 0; j < 28; j++) acc[j] = bs[dg * 28 + j];

    const float* orow = os + px * PJ_STRIDE;
    const float* wrow = wp + dg * 28 * CC;
    #pragma unroll 2
    for (int c4 = 0; c4 < 28; c4++) {
        float4 xv = *(const float4*)(orow + c4 * 4);
        #pragma unroll
        for (int j = 0; j < 28; j++) {
            float4 w4 = *(const float4*)(wrow + j * CC + c4 * 4);
            acc[j] += dot4(xv, w4);
        }
    }
    float* op = out + ((size_t)b * CC + dg * 28) * HWN + hw0 + px;
    #pragma unroll
    for (int j = 0; j < 28; j++) op[j * HWN] = acc[j];
}

// =============================================================================
extern "C" void kernel_launch(void* const* d_in, const int* in_sizes, int n_in,
                              void* d_out, int out_size) {
    const float* x     = (const float*)d_in[0];
    const float* Wqkv  = (const float*)d_in[1];
    const float* Wproj = (const float*)d_in[2];
    const float* bproj = (const float*)d_in[3];
    const int*   topk  = (const int*)d_in[4];
    float* out = (float*)d_out;

    const int smemA = QKV_SMEM_B;                              // 115200
    const int smemB = ATTN_SMEM_F * 4;                         // 43776
    const int smemC = (14848 + 12544 + 112) * 4;               // 110016

    cudaFuncSetAttribute(qkv_kernel,  cudaFuncAttributeMaxDynamicSharedMemorySize, smemA);
    cudaFuncSetAttribute(attn_kernel, cudaFuncAttributeMaxDynamicSharedMemorySize, smemB);
    cudaFuncSetAttribute(proj_kernel, cudaFuncAttributeMaxDynamicSharedMemorySize, smemC);

    qkv_kernel<<<dim3(32, 16), 512, smemA>>>(x, Wqkv);
    attn_kernel<<<BB * NWIN * NHEAD, 256, smemB>>>(topk);
    proj_kernel<<<dim3(32, 16), 512, smemC>>>(Wproj, bproj, out);
}

// round 11
// speedup vs baseline: 2.2963x; 1.2447x over previous
#include <cuda_runtime.h>
#include <cuda_bf16.h>
#include <cstdint>

#define BB    16
#define CC    112
#define HH    64
#define HWN   4096
#define NHEAD 4
#define HD    28
#define NWIN  256
#define TOPK  128
#define SCALE 0.18898223650461363f   // 28^-0.5

#define S_STRIDE  132

// mma smem byte offsets (240B rows = 60 u32; 15x16B odd -> ldmatrix conflict-free)
#define AH_B   0        // Ah [128 rows][240B]  = 30720
#define AL_B   30720    // Al                   = 30720
#define WH_B   61440    // Wh [112][240B]       = 26880
#define WL_B   88320    // Wl                   = 26880
#define MMA_SMEM_B 115200

// attn smem float offsets
#define KS_F   0
#define VS_F   4096
#define QS_F   8192
#define S_F    8768
#define RMAX_F 10880
#define RSUM_F 10912
#define ATTN_SMEM_F 10944

// ---------------- scratch (device globals; no allocation allowed) ------------
__device__ __align__(16) float g_q[BB * HWN * CC];
__device__ __align__(16) float g_k[BB * HWN * CC];
__device__ __align__(16) float g_v[BB * HWN * CC];
__device__ __align__(16) float g_o[BB * HWN * CC];

__device__ __forceinline__ float dot4(float4 a, float4 b) {
    return a.x * b.x + a.y * b.y + a.z * b.z + a.w * b.w;
}
__device__ __forceinline__ uint32_t smem_u32(const void* p) {
    uint32_t a;
    asm("{ .reg .u64 t; cvta.to.shared.u64 t, %1; cvt.u32.u64 %0, t; }" : "=r"(a) : "l"(p));
    return a;
}
__device__ __forceinline__ void cp16(uint32_t dst, const void* src) {
    asm volatile("cp.async.cg.shared.global [%0], [%1], 16;" :: "r"(dst), "l"(src) : "memory");
}
__device__ __forceinline__ void ldsm4(uint32_t* r, uint32_t a) {
    asm volatile("ldmatrix.sync.aligned.m8n8.x4.shared.b16 {%0,%1,%2,%3}, [%4];"
                 : "=r"(r[0]), "=r"(r[1]), "=r"(r[2]), "=r"(r[3]) : "r"(a));
}
__device__ __forceinline__ void ldsm2(uint32_t* r, uint32_t a) {
    asm volatile("ldmatrix.sync.aligned.m8n8.x2.shared.b16 {%0,%1}, [%2];"
                 : "=r"(r[0]), "=r"(r[1]) : "r"(a));
}
__device__ __forceinline__ void mma_bf16(float* d, const uint32_t* a, const uint32_t* b) {
    asm volatile("mma.sync.aligned.m16n8k16.row.col.f32.bf16.bf16.f32 "
                 "{%0,%1,%2,%3}, {%4,%5,%6,%7}, {%8,%9}, {%0,%1,%2,%3};"
                 : "+f"(d[0]), "+f"(d[1]), "+f"(d[2]), "+f"(d[3])
                 : "r"(a[0]), "r"(a[1]), "r"(a[2]), "r"(a[3]), "r"(b[0]), "r"(b[1]));
}
__device__ __forceinline__ void split_pack(float a0, float a1, uint32_t& hi, uint32_t& lo) {
    __nv_bfloat16 h0 = __float2bfloat16(a0);
    __nv_bfloat16 h1 = __float2bfloat16(a1);
    __nv_bfloat16 l0 = __float2bfloat16(a0 - __bfloat162float(h0));
    __nv_bfloat16 l1 = __float2bfloat16(a1 - __bfloat162float(h1));
    hi = ((uint32_t)__bfloat16_as_ushort(h1) << 16) | __bfloat16_as_ushort(h0);
    lo = ((uint32_t)__bfloat16_as_ushort(l1) << 16) | __bfloat16_as_ushort(l0);
}

// =============================================================================
// Kernel A: QKV projection via mma.sync bf16-split (unchanged from round 9).
// =============================================================================
__global__ __launch_bounds__(512, 2) void qkv_kernel(const float* __restrict__ x,
                                                     const float* __restrict__ Wqkv) {
    extern __shared__ char smb[];
    float* xs = (float*)(smb + WH_B);
    const uint32_t sbase = smem_u32(smb);

    const int tid = threadIdx.x;
    const int b   = blockIdx.y;
    const int hw0 = blockIdx.x * 128;

    #pragma unroll
    for (int chunk = 0; chunk < 2; chunk++) {
        for (int i = tid; i < 1792; i += 512) {
            int c = i >> 5, p4 = i & 31;
            ((float4*)xs)[i] =
                ((const float4*)(x + (b * CC + chunk * 56 + c) * HWN + hw0))[p4];
        }
        __syncthreads();
        for (int i = tid; i < 3584; i += 512) {
            int px = i & 127, cp = i >> 7;
            float v0 = xs[(cp * 2) * 128 + px];
            float v1 = xs[(cp * 2 + 1) * 128 + px];
            uint32_t hi, lo;
            split_pack(v0, v1, hi, lo);
            int idx = px * 60 + chunk * 28 + cp;
            ((uint32_t*)(smb + AH_B))[idx] = hi;
            ((uint32_t*)(smb + AL_B))[idx] = lo;
        }
        __syncthreads();
    }

    const int lane = tid & 31;
    const int wid  = tid >> 5;
    const int wm   = wid & 7;
    const int wn   = wid >> 3;
    const int mrow = wm * 16;

    const int amat = lane >> 3, ar = lane & 7;
    const uint32_t a_off = (uint32_t)((mrow + ar + (amat & 1) * 8) * 240
                                      + (amat >> 1) * 16);
    const uint32_t b_lane_off = (uint32_t)((lane & 7) * 240 + ((lane >> 3) & 1) * 16);

    const int orow  = mrow + (lane >> 2);
    const int ocol0 = wn * 56 + 2 * (lane & 3);

    for (int seg = 0; seg < 3; seg++) {
        const float s = (seg == 0) ? SCALE : 1.0f;
        for (int i = tid; i < 6272; i += 512) {
            int d = i / 56, cp = i - d * 56;
            float2 wv = *(const float2*)(Wqkv + (size_t)(seg * CC + d) * CC + cp * 2);
            uint32_t hi, lo;
            split_pack(wv.x * s, wv.y * s, hi, lo);
            ((uint32_t*)(smb + WH_B))[d * 60 + cp] = hi;
            ((uint32_t*)(smb + WL_B))[d * 60 + cp] = lo;
        }
        __syncthreads();

        float acc[7][4];
        #pragma unroll
        for (int nt = 0; nt < 7; nt++)
            #pragma unroll
            for (int j = 0; j < 4; j++) acc[nt][j] = 0.0f;

        #pragma unroll
        for (int ks = 0; ks < 7; ks++) {
            uint32_t ah[4], al[4];
            ldsm4(ah, sbase + AH_B + a_off + ks * 32);
            ldsm4(al, sbase + AL_B + a_off + ks * 32);
            #pragma unroll
            for (int nt = 0; nt < 7; nt++) {
                uint32_t bh[2], bl[2];
                uint32_t boff = (uint32_t)((wn * 56 + nt * 8) * 240) + b_lane_off + ks * 32;
                ldsm2(bh, sbase + WH_B + boff);
                ldsm2(bl, sbase + WL_B + boff);
                mma_bf16(acc[nt], ah, bh);
                mma_bf16(acc[nt], ah, bl);
                mma_bf16(acc[nt], al, bh);
            }
        }

        float* dst = (seg == 0 ? g_q : (seg == 1 ? g_k : g_v));
        float* base = dst + (size_t)(b * HWN + hw0 + orow) * CC;
        #pragma unroll
        for (int nt = 0; nt < 7; nt++) {
            int d = ocol0 + nt * 8;
            *(float2*)(base + d)            = make_float2(acc[nt][0], acc[nt][1]);
            *(float2*)(base + 8 * CC + d)   = make_float2(acc[nt][2], acc[nt][3]);
        }
        __syncthreads();
    }
}

// =============================================================================
// Kernel B: windowed top-k attention (round-10 PV retile, audited clean).
// =============================================================================
__global__ __launch_bounds__(256, 5) void attn_kernel(const int* __restrict__ topk) {
    extern __shared__ float sm[];
    float* Ks   = sm + KS_F;
    float* Vs   = sm + VS_F;
    float* Qs   = sm + QS_F;
    float* S    = sm + S_F;
    float* rmax = sm + RMAX_F;
    float* rsum = sm + RSUM_F;

    const uint32_t sbase = smem_u32(sm);
    const int tid = threadIdx.x;
    const int bx  = blockIdx.x;
    const int h   = bx & 3;
    const int w   = (bx >> 2) & 255;
    const int b   = bx >> 10;
    const int wy  = w >> 4, wx = w & 15;

    // ---- gather K/V (cp.async, swizzled) + Q ----
    {
        const int* tkw = topk + w * TOPK;
        for (int i = tid; i < 896; i += 256) {
            int row = i / 7, c4 = i - row * 7;
            int pos = __ldg(tkw + row);
            size_t gb = (size_t)(b * HWN + pos) * CC + h * HD + c4 * 4;
            uint32_t off = (uint32_t)(row * 32 + ((c4 ^ (row & 7)) << 2)) * 4;
            cp16(sbase + KS_F * 4 + off, g_k + gb);
            cp16(sbase + VS_F * 4 + off, g_v + gb);
        }
        if (tid < 112) {
            int qi = tid / 7, c4 = tid - qi * 7;
            int hw = (wy * 4 + (qi >> 2)) * HH + wx * 4 + (qi & 3);
            cp16(sbase + (QS_F + qi * 36 + c4 * 4) * 4,
                 g_q + (size_t)(b * HWN + hw) * CC + h * HD + c4 * 4);
        }
        asm volatile("cp.async.commit_group;");
        asm volatile("cp.async.wait_group 0;" ::: "memory");
    }
    __syncthreads();

    // ---- S = Q K^T with fused softmax reductions ----
    {
        const int lane = tid & 31;
        const int kh   = (tid >> 5) & 1;
        const int qg   = tid >> 6;

        float acc[4][2];
        #pragma unroll
        for (int i = 0; i < 4; i++) { acc[i][0] = 0.f; acc[i][1] = 0.f; }

        const float* kp = Ks + (kh * 64 + lane) * 32;
        const float* qp = Qs + (qg * 4) * 36;
        #pragma unroll
        for (int s = 0; s < 7; s++) {
            const int sc = (s ^ (lane & 7)) << 2;
            float4 k0 = *(const float4*)(kp + sc);
            float4 k1 = *(const float4*)(kp + 1024 + sc);
            #pragma unroll
            for (int i = 0; i < 4; i++) {
                float4 qv = *(const float4*)(qp + i * 36 + s * 4);
                acc[i][0] += dot4(qv, k0);
                acc[i][1] += dot4(qv, k1);
            }
        }

        #pragma unroll
        for (int i = 0; i < 4; i++) {
            float m = fmaxf(acc[i][0], acc[i][1]);
            m = fmaxf(m, __shfl_xor_sync(0xffffffffu, m, 1));
            m = fmaxf(m, __shfl_xor_sync(0xffffffffu, m, 2));
            m = fmaxf(m, __shfl_xor_sync(0xffffffffu, m, 4));
            m = fmaxf(m, __shfl_xor_sync(0xffffffffu, m, 8));
            m = fmaxf(m, __shfl_xor_sync(0xffffffffu, m, 16));
            if (lane == 0) rmax[(qg * 4 + i) * 2 + kh] = m;
        }
        __syncthreads();

        float* srow = S + (qg * 4) * S_STRIDE + kh * 64 + lane;
        #pragma unroll
        for (int i = 0; i < 4; i++) {
            const int qi = qg * 4 + i;
            float mx = fmaxf(rmax[qi * 2], rmax[qi * 2 + 1]);
            float e0 = __expf(acc[i][0] - mx);
            float e1 = __expf(acc[i][1] - mx);
            srow[i * S_STRIDE]      = e0;
            srow[i * S_STRIDE + 32] = e1;
            float s2 = e0 + e1;
            s2 += __shfl_xor_sync(0xffffffffu, s2, 1);
            s2 += __shfl_xor_sync(0xffffffffu, s2, 2);
            s2 += __shfl_xor_sync(0xffffffffu, s2, 4);
            s2 += __shfl_xor_sync(0xffffffffu, s2, 8);
            s2 += __shfl_xor_sync(0xffffffffu, s2, 16);
            if (lane == 0) rsum[qi * 2 + kh] = s2;
        }
    }
    __syncthreads();

    // ---- O = P V : thread = (qg: 4 qi, slot: 4 d, khalf: k%8); V read once --
    {
        const int khalf = tid & 7;
        const int slot  = (tid >> 3) & 7;    // slot 7 computes garbage, no write
        const int qg    = tid >> 6;
        float4 acc[4];
        #pragma unroll
        for (int j = 0; j < 4; j++) acc[j] = make_float4(0.f, 0.f, 0.f, 0.f);

        const float* vcol = Vs + ((slot ^ khalf) << 2);   // k&7 == khalf always
        const float* prow = S + (qg * 4) * S_STRIDE + khalf;
        #pragma unroll 4
        for (int i = 0; i < 16; i++) {
            const int k = khalf + 8 * i;
            float4 v = *(const float4*)(vcol + k * 32);
            #pragma unroll
            for (int j = 0; j < 4; j++) {
                float p = prow[j * S_STRIDE + 8 * i];
                acc[j].x += p * v.x; acc[j].y += p * v.y;
                acc[j].z += p * v.z; acc[j].w += p * v.w;
            }
        }
        #pragma unroll
        for (int j = 0; j < 4; j++) {
            #pragma unroll
            for (int off = 1; off < 8; off <<= 1) {
                acc[j].x += __shfl_xor_sync(0xffffffffu, acc[j].x, off);
                acc[j].y += __shfl_xor_sync(0xffffffffu, acc[j].y, off);
                acc[j].z += __shfl_xor_sync(0xffffffffu, acc[j].z, off);
                acc[j].w += __shfl_xor_sync(0xffffffffu, acc[j].w, off);
            }
        }
        if (khalf == 0 && slot < 7) {
            #pragma unroll
            for (int j = 0; j < 4; j++) {
                int qi = qg * 4 + j;
                float inv = 1.0f / (rsum[qi * 2] + rsum[qi * 2 + 1]);
                float4 o = make_float4(acc[j].x * inv, acc[j].y * inv,
                                       acc[j].z * inv, acc[j].w * inv);
                int hw = (wy * 4 + (qi >> 2)) * HH + wx * 4 + (qi & 3);
                *(float4*)(g_o + (size_t)(b * HWN + hw) * CC + h * HD + slot * 4) = o;
            }
        }
    }
}

// =============================================================================
// Kernel C: output projection via mma.sync bf16-split + bias.
// FIX vs round 10: A conversion covers all 56 c-pairs (i < 7168), not 28.
// =============================================================================
__global__ __launch_bounds__(512, 2) void proj_kernel(const float* __restrict__ Wp,
                                                      const float* __restrict__ bias,
                                                      float* __restrict__ out) {
    extern __shared__ char smb[];
    const uint32_t sbase = smem_u32(smb);
    const int tid = threadIdx.x;
    const int b   = blockIdx.y;
    const int hw0 = blockIdx.x * 128;

    // ---- A conversion: o tile [128 px][112 c] -> Ah/Al (ALL 56 pairs) ----
    const float* obase = g_o + (size_t)(b * HWN + hw0) * CC;
    for (int i = tid; i < 7168; i += 512) {
        int px = i / 56, cp = i - px * 56;
        float2 ov = *(const float2*)(obase + (size_t)px * CC + cp * 2);
        uint32_t hi, lo;
        split_pack(ov.x, ov.y, hi, lo);
        ((uint32_t*)(smb + AH_B))[px * 60 + cp] = hi;
        ((uint32_t*)(smb + AL_B))[px * 60 + cp] = lo;
    }
    // ---- W conversion ----
    for (int i = tid; i < 6272; i += 512) {
        int d = i / 56, cp = i - d * 56;
        float2 wv = *(const float2*)(Wp + (size_t)d * CC + cp * 2);
        uint32_t hi, lo;
        split_pack(wv.x, wv.y, hi, lo);
        ((uint32_t*)(smb + WH_B))[d * 60 + cp] = hi;
        ((uint32_t*)(smb + WL_B))[d * 60 + cp] = lo;
    }
    __syncthreads();

    const int lane = tid & 31;
    const int wid  = tid >> 5;
    const int wm   = wid & 7;
    const int wn   = wid >> 3;
    const int mrow = wm * 16;
    const int amat = lane >> 3, ar = lane & 7;
    const uint32_t a_off = (uint32_t)((mrow + ar + (amat & 1) * 8) * 240
                                      + (amat >> 1) * 16);
    const uint32_t b_lane_off = (uint32_t)((lane & 7) * 240 + ((lane >> 3) & 1) * 16);
    const int orow  = mrow + (lane >> 2);
    const int ocol0 = wn * 56 + 2 * (lane & 3);

    float acc[7][4];
    #pragma unroll
    for (int nt = 0; nt < 7; nt++)
        #pragma unroll
        for (int j = 0; j < 4; j++) acc[nt][j] = 0.0f;

    #pragma unroll
    for (int ks = 0; ks < 7; ks++) {
        uint32_t ah[4], al[4];
        ldsm4(ah, sbase + AH_B + a_off + ks * 32);
        ldsm4(al, sbase + AL_B + a_off + ks * 32);
        #pragma unroll
        for (int nt = 0; nt < 7; nt++) {
            uint32_t bh[2], bl[2];
            uint32_t boff = (uint32_t)((wn * 56 + nt * 8) * 240) + b_lane_off + ks * 32;
            ldsm2(bh, sbase + WH_B + boff);
            ldsm2(bl, sbase + WL_B + boff);
            mma_bf16(acc[nt], ah, bh);
            mma_bf16(acc[nt], ah, bl);
            mma_bf16(acc[nt], al, bh);
        }
    }
    __syncthreads();   // A region dead; reuse as transpose stage

    // ---- stage fragments [d][px] stride 132 ----
    float* stage = (float*)smb;
    #pragma unroll
    for (int nt = 0; nt < 7; nt++) {
        int d = ocol0 + nt * 8;
        stage[d * 132 + orow]             = acc[nt][0];
        stage[(d + 1) * 132 + orow]       = acc[nt][1];
        stage[d * 132 + orow + 8]         = acc[nt][2];
        stage[(d + 1) * 132 + orow + 8]   = acc[nt][3];
    }
    __syncthreads();

    // ---- coalesced channel-major output + bias ----
    for (int i = tid; i < 3584; i += 512) {
        int d = i >> 5, j = i & 31;
        float4 v = *(const float4*)(stage + d * 132 + j * 4);
        float bv = __ldg(bias + d);                 // warp-uniform
        v.x += bv; v.y += bv; v.z += bv; v.w += bv;
        *(float4*)(out + ((size_t)b * CC + d) * HWN + hw0 + j * 4) = v;
    }
}

// =============================================================================
extern "C" void kernel_launch(void* const* d_in, const int* in_sizes, int n_in,
                              void* d_out, int out_size) {
    const float* x     = (const float*)d_in[0];
    const float* Wqkv  = (const float*)d_in[1];
    const float* Wproj = (const float*)d_in[2];
    const float* bproj = (const float*)d_in[3];
    const int*   topk  = (const int*)d_in[4];
    float* out = (float*)d_out;

    const int smemA = MMA_SMEM_B;                              // 115200
    const int smemB = ATTN_SMEM_F * 4;                         // 43776
    const int smemC = MMA_SMEM_B;                              // 115200

    cudaFuncSetAttribute(qkv_kernel,  cudaFuncAttributeMaxDynamicSharedMemorySize, smemA);
    cudaFuncSetAttribute(attn_kernel, cudaFuncAttributeMaxDynamicSharedMemorySize, smemB);
    cudaFuncSetAttribute(proj_kernel, cudaFuncAttributeMaxDynamicSharedMemorySize, smemC);

    qkv_kernel<<<dim3(32, 16), 512, smemA>>>(x, Wqkv);
    attn_kernel<<<BB * NWIN * NHEAD, 256, smemB>>>(topk);
    proj_kernel<<<dim3(32, 16), 512, smemC>>>(Wproj, bproj, out);
}

// round 12
// speedup vs baseline: 2.4407x; 1.0629x over previous
#include <cuda_runtime.h>
#include <cuda_bf16.h>
#include <cstdint>

#define BB    16
#define CC    112
#define HH    64
#define HWN   4096
#define NHEAD 4
#define HD    28
#define NWIN  256
#define TOPK  128
#define SCALE 0.18898223650461363f   // 28^-0.5

// ---- mma (qkv/proj) smem byte offsets: 240B rows (15x16B odd, conflict-free)
#define AH_B   0
#define AL_B   30720
#define WH_B   61440
#define WL_B   88320
#define MMA_SMEM_B 115200

// ---- attn smem byte offsets: 80B rows (5x16B odd, ldsm conflict-free) ----
#define KH_B    0        // 128 x 80B = 10240
#define KL_B    10240
#define VH_B    20480
#define VL_B    30720
#define QH_B    40960    // 16 x 80B = 1280
#define QL_B    42240
#define RMAX_B  43520    // 8 warps x 16 f32
#define RSUM_B  44032
#define ATTN_SMEM_B 44544
// O stage overlays KH/KL: 8 slabs x (16 rows x 40 f32) = 20480B exactly

// ---------------- scratch (device globals; no allocation allowed) ------------
// bf16-split planes, per-head rows of 16 u32 (ch pairs 0..13 + zero pads 14,15)
__device__ __align__(16) uint32_t g_qh[BB * NHEAD * HWN * 16];
__device__ __align__(16) uint32_t g_ql[BB * NHEAD * HWN * 16];
__device__ __align__(16) uint32_t g_kh[BB * NHEAD * HWN * 16];
__device__ __align__(16) uint32_t g_kl[BB * NHEAD * HWN * 16];
__device__ __align__(16) uint32_t g_vh[BB * NHEAD * HWN * 16];
__device__ __align__(16) uint32_t g_vl[BB * NHEAD * HWN * 16];
// attention output, split, rows of 60 u32 (56 ch pairs + 4 pad, 240B rows)
__device__ __align__(16) uint32_t g_oh[BB * HWN * 60];
__device__ __align__(16) uint32_t g_ol[BB * HWN * 60];

__device__ __forceinline__ uint32_t smem_u32(const void* p) {
    uint32_t a;
    asm("{ .reg .u64 t; cvta.to.shared.u64 t, %1; cvt.u32.u64 %0, t; }" : "=r"(a) : "l"(p));
    return a;
}
__device__ __forceinline__ void cp16(uint32_t dst, const void* src) {
    asm volatile("cp.async.cg.shared.global [%0], [%1], 16;" :: "r"(dst), "l"(src) : "memory");
}
__device__ __forceinline__ void ldsm4(uint32_t* r, uint32_t a) {
    asm volatile("ldmatrix.sync.aligned.m8n8.x4.shared.b16 {%0,%1,%2,%3}, [%4];"
                 : "=r"(r[0]), "=r"(r[1]), "=r"(r[2]), "=r"(r[3]) : "r"(a));
}
__device__ __forceinline__ void ldsm2(uint32_t* r, uint32_t a) {
    asm volatile("ldmatrix.sync.aligned.m8n8.x2.shared.b16 {%0,%1}, [%2];"
                 : "=r"(r[0]), "=r"(r[1]) : "r"(a));
}
__device__ __forceinline__ void ldsm2t(uint32_t* r, uint32_t a) {
    asm volatile("ldmatrix.sync.aligned.m8n8.x2.trans.shared.b16 {%0,%1}, [%2];"
                 : "=r"(r[0]), "=r"(r[1]) : "r"(a));
}
__device__ __forceinline__ void mma_bf16(float* d, const uint32_t* a, const uint32_t* b) {
    asm volatile("mma.sync.aligned.m16n8k16.row.col.f32.bf16.bf16.f32 "
                 "{%0,%1,%2,%3}, {%4,%5,%6,%7}, {%8,%9}, {%0,%1,%2,%3};"
                 : "+f"(d[0]), "+f"(d[1]), "+f"(d[2]), "+f"(d[3])
                 : "r"(a[0]), "r"(a[1]), "r"(a[2]), "r"(a[3]), "r"(b[0]), "r"(b[1]));
}
__device__ __forceinline__ void split_pack(float a0, float a1, uint32_t& hi, uint32_t& lo) {
    __nv_bfloat16 h0 = __float2bfloat16(a0);
    __nv_bfloat16 h1 = __float2bfloat16(a1);
    __nv_bfloat16 l0 = __float2bfloat16(a0 - __bfloat162float(h0));
    __nv_bfloat16 l1 = __float2bfloat16(a1 - __bfloat162float(h1));
    hi = ((uint32_t)__bfloat16_as_ushort(h1) << 16) | __bfloat16_as_ushort(h0);
    lo = ((uint32_t)__bfloat16_as_ushort(l1) << 16) | __bfloat16_as_ushort(l0);
}

// =============================================================================
// Kernel A: QKV projection via mma.sync bf16-split; outputs pre-split planes.
// =============================================================================
__global__ __launch_bounds__(512, 2) void qkv_kernel(const float* __restrict__ x,
                                                     const float* __restrict__ Wqkv) {
    extern __shared__ char smb[];
    float* xs = (float*)(smb + WH_B);
    const uint32_t sbase = smem_u32(smb);

    const int tid = threadIdx.x;
    const int b   = blockIdx.y;
    const int hw0 = blockIdx.x * 128;

    // A conversion (x tile, transposed to [px][ch]) in two 56-channel chunks
    #pragma unroll
    for (int chunk = 0; chunk < 2; chunk++) {
        for (int i = tid; i < 1792; i += 512) {
            int c = i >> 5, p4 = i & 31;
            ((float4*)xs)[i] =
                ((const float4*)(x + (b * CC + chunk * 56 + c) * HWN + hw0))[p4];
        }
        __syncthreads();
        for (int i = tid; i < 3584; i += 512) {
            int px = i & 127, cp = i >> 7;
            uint32_t hi, lo;
            split_pack(xs[(cp * 2) * 128 + px], xs[(cp * 2 + 1) * 128 + px], hi, lo);
            int idx = px * 60 + chunk * 28 + cp;
            ((uint32_t*)(smb + AH_B))[idx] = hi;
            ((uint32_t*)(smb + AL_B))[idx] = lo;
        }
        __syncthreads();
    }

    const int lane = tid & 31;
    const int wid  = tid >> 5;
    const int wm   = wid & 7;
    const int wn   = wid >> 3;
    const int mrow = wm * 16;

    const int amat = lane >> 3, ar = lane & 7;
    const uint32_t a_off = (uint32_t)((mrow + ar + (amat & 1) * 8) * 240
                                      + (amat >> 1) * 16);
    const uint32_t b_lane_off = (uint32_t)((lane & 7) * 240 + ((lane >> 3) & 1) * 16);

    const int orow  = mrow + (lane >> 2);
    const int ocol0 = wn * 56 + 2 * (lane & 3);

    for (int seg = 0; seg < 3; seg++) {
        const float s = (seg == 0) ? SCALE : 1.0f;
        for (int i = tid; i < 6272; i += 512) {
            int d = i / 56, cp = i - d * 56;
            float2 wv = *(const float2*)(Wqkv + (size_t)(seg * CC + d) * CC + cp * 2);
            uint32_t hi, lo;
            split_pack(wv.x * s, wv.y * s, hi, lo);
            ((uint32_t*)(smb + WH_B))[d * 60 + cp] = hi;
            ((uint32_t*)(smb + WL_B))[d * 60 + cp] = lo;
        }
        __syncthreads();

        float acc[7][4];
        #pragma unroll
        for (int nt = 0; nt < 7; nt++)
            #pragma unroll
            for (int j = 0; j < 4; j++) acc[nt][j] = 0.0f;

        #pragma unroll
        for (int ks = 0; ks < 7; ks++) {
            uint32_t ah[4], al[4];
            ldsm4(ah, sbase + AH_B + a_off + ks * 32);
            ldsm4(al, sbase + AL_B + a_off + ks * 32);
            #pragma unroll
            for (int nt = 0; nt < 7; nt++) {
                uint32_t bh[2], bl[2];
                uint32_t boff = (uint32_t)((wn * 56 + nt * 8) * 240) + b_lane_off + ks * 32;
                ldsm2(bh, sbase + WH_B + boff);
                ldsm2(bl, sbase + WL_B + boff);
                mma_bf16(acc[nt], ah, bh);
                mma_bf16(acc[nt], ah, bl);
                mma_bf16(acc[nt], al, bh);
            }
        }

        // ---- epilogue: split fragments into per-head hi/lo planes ----
        uint32_t* ph = (seg == 0) ? g_qh : (seg == 1) ? g_kh : g_vh;
        uint32_t* pl = (seg == 0) ? g_ql : (seg == 1) ? g_kl : g_vl;
        #pragma unroll
        for (int nt = 0; nt < 7; nt++) {
            int d = ocol0 + nt * 8;
            int h = d / 28;
            int cidx = (d - h * 28) >> 1;
            size_t base = ((size_t)(b * 4 + h) * HWN + hw0) * 16 + cidx;
            uint32_t hi, lo;
            split_pack(acc[nt][0], acc[nt][1], hi, lo);
            ph[base + (size_t)orow * 16] = hi;
            pl[base + (size_t)orow * 16] = lo;
            split_pack(acc[nt][2], acc[nt][3], hi, lo);
            ph[base + (size_t)(orow + 8) * 16] = hi;
            pl[base + (size_t)(orow + 8) * 16] = lo;
        }
        __syncthreads();
    }

    // ---- zero channel pads (u32 cols 14,15) for all planes, this tile ----
    for (int i = tid; i < 1024; i += 512) {
        int row = i >> 3, h = (i >> 1) & 3, pc = 14 + (i & 1);
        size_t a = ((size_t)(b * 4 + h) * HWN + hw0 + row) * 16 + pc;
        g_qh[a] = 0; g_ql[a] = 0;
        g_kh[a] = 0; g_kl[a] = 0;
        g_vh[a] = 0; g_vl[a] = 0;
    }
}

// =============================================================================
// Kernel B: FA2-style windowed top-k attention on mma.sync.
// Block = (b, w, h), 256 threads = 8 warps. Warp w: S n-tiles {2w,2w+1},
// then PV kstep w; O reduced 8-way through smem stage (stride-40, STS.64).
// =============================================================================
__global__ __launch_bounds__(256, 4) void attn_kernel(const int* __restrict__ topk) {
    extern __shared__ char smb[];
    const uint32_t sbase = smem_u32(smb);
    const int tid  = threadIdx.x;
    const int lane = tid & 31;
    const int wrp  = tid >> 5;
    const int bx   = blockIdx.x;
    const int h    = bx & 3;
    const int w    = (bx >> 2) & 255;
    const int b    = bx >> 10;
    const int wy   = w >> 4, wx = w & 15;

    // ---- gather K/V hi+lo slices + Q (cp.async) ----
    {
        const int* tkw = topk + w * TOPK;
        const size_t hb = (size_t)(b * 4 + h) * HWN;
        for (int i = tid; i < 512; i += 256) {
            int row = i & 127, c = i >> 7;
            int pos = __ldg(tkw + row);
            size_t s = (hb + pos) * 16 + c * 4;
            uint32_t doff = (uint32_t)(row * 80 + c * 16);
            cp16(sbase + KH_B + doff, g_kh + s);
            cp16(sbase + KL_B + doff, g_kl + s);
            cp16(sbase + VH_B + doff, g_vh + s);
            cp16(sbase + VL_B + doff, g_vl + s);
        }
        if (tid < 64) {
            int qi = tid & 15, c = tid >> 4;
            int hw = (wy * 4 + (qi >> 2)) * HH + wx * 4 + (qi & 3);
            size_t s = (hb + hw) * 16 + c * 4;
            cp16(sbase + QH_B + qi * 80 + c * 16, g_qh + s);
            cp16(sbase + QL_B + qi * 80 + c * 16, g_ql + s);
        }
        asm volatile("cp.async.commit_group;");
        asm volatile("cp.async.wait_group 0;" ::: "memory");
    }
    __syncthreads();

    // ---- S = Q K^T (3-term bf16 split). Warp owns n-tiles 2w, 2w+1 ----
    float c0[4] = {0.f, 0.f, 0.f, 0.f};
    float c1[4] = {0.f, 0.f, 0.f, 0.f};
    {
        const uint32_t q_l = (uint32_t)((lane & 15) * 80 + (lane >> 4) * 16);
        const uint32_t k_l = (uint32_t)((lane & 7) * 80 + ((lane >> 3) & 1) * 16);
        #pragma unroll
        for (int ks = 0; ks < 2; ks++) {
            uint32_t aqh[4], aql[4];
            ldsm4(aqh, sbase + QH_B + q_l + ks * 32);
            ldsm4(aql, sbase + QL_B + q_l + ks * 32);
            uint32_t bh[2], bl[2];
            uint32_t kb = (uint32_t)(wrp * 16 * 80) + k_l + ks * 32;
            ldsm2(bh, sbase + KH_B + kb);
            ldsm2(bl, sbase + KL_B + kb);
            mma_bf16(c0, aqh, bh); mma_bf16(c0, aqh, bl); mma_bf16(c0, aql, bh);
            kb += 8 * 80;
            ldsm2(bh, sbase + KH_B + kb);
            ldsm2(bl, sbase + KL_B + kb);
            mma_bf16(c1, aqh, bh); mma_bf16(c1, aqh, bl); mma_bf16(c1, aql, bh);
        }
    }

    float* rmaxs = (float*)(smb + RMAX_B);
    float* rsums = (float*)(smb + RSUM_B);
    const int r0 = lane >> 2;
    {
        float m0 = fmaxf(fmaxf(c0[0], c0[1]), fmaxf(c1[0], c1[1]));
        float m1 = fmaxf(fmaxf(c0[2], c0[3]), fmaxf(c1[2], c1[3]));
        m0 = fmaxf(m0, __shfl_xor_sync(0xffffffffu, m0, 1));
        m0 = fmaxf(m0, __shfl_xor_sync(0xffffffffu, m0, 2));
        m1 = fmaxf(m1, __shfl_xor_sync(0xffffffffu, m1, 1));
        m1 = fmaxf(m1, __shfl_xor_sync(0xffffffffu, m1, 2));
        if ((lane & 3) == 0) {
            rmaxs[wrp * 16 + r0]     = m0;
            rmaxs[wrp * 16 + r0 + 8] = m1;
        }
    }
    __syncthreads();

    uint32_t aph[4], apl[4];
    {
        float g0 = rmaxs[r0], g1 = rmaxs[r0 + 8];
        #pragma unroll
        for (int ww = 1; ww < 8; ww++) {
            g0 = fmaxf(g0, rmaxs[ww * 16 + r0]);
            g1 = fmaxf(g1, rmaxs[ww * 16 + r0 + 8]);
        }
        c0[0] = __expf(c0[0] - g0); c0[1] = __expf(c0[1] - g0);
        c1[0] = __expf(c1[0] - g0); c1[1] = __expf(c1[1] - g0);
        c0[2] = __expf(c0[2] - g1); c0[3] = __expf(c0[3] - g1);
        c1[2] = __expf(c1[2] - g1); c1[3] = __expf(c1[3] - g1);
        float s0 = c0[0] + c0[1] + c1[0] + c1[1];
        float s1 = c0[2] + c0[3] + c1[2] + c1[3];
        s0 += __shfl_xor_sync(0xffffffffu, s0, 1);
        s0 += __shfl_xor_sync(0xffffffffu, s0, 2);
        s1 += __shfl_xor_sync(0xffffffffu, s1, 1);
        s1 += __shfl_xor_sync(0xffffffffu, s1, 2);
        if ((lane & 3) == 0) {
            rsums[wrp * 16 + r0]     = s0;
            rsums[wrp * 16 + r0 + 8] = s1;
        }
        // pack P c-frags into PV A-frags (layout identity)
        split_pack(c0[0], c0[1], aph[0], apl[0]);
        split_pack(c0[2], c0[3], aph[1], apl[1]);
        split_pack(c1[0], c1[1], aph[2], apl[2]);
        split_pack(c1[2], c1[3], aph[3], apl[3]);
    }
    __syncthreads();   // rsums visible; K region now dead -> O stage overlay

    // ---- PV: warp's kstep = kj 16w..16w+15; V via ldmatrix.trans ----
    {
        const uint32_t v_l = (uint32_t)((wrp * 16 + (lane & 15)) * 80);
        float* slab = (float*)smb + wrp * 640;   // 16 rows x 40 f32
        #pragma unroll
        for (int nt = 0; nt < 4; nt++) {
            float o[4] = {0.f, 0.f, 0.f, 0.f};
            uint32_t bh[2], bl[2];
            ldsm2t(bh, sbase + VH_B + v_l + nt * 16);
            ldsm2t(bl, sbase + VL_B + v_l + nt * 16);
            mma_bf16(o, aph, bh); mma_bf16(o, aph, bl); mma_bf16(o, apl, bh);
            float* sp = slab + r0 * 40 + nt * 8 + 2 * (lane & 3);
            *(float2*)sp            = make_float2(o[0], o[1]);
            *(float2*)(sp + 8 * 40) = make_float2(o[2], o[3]);
        }
    }
    __syncthreads();

    // ---- reduce 8 slabs, normalize, split, store ----
    if (tid < 224) {
        int qi = tid / 14, p = tid - qi * 14;
        float o0 = 0.f, o1 = 0.f, gs = 0.f;
        #pragma unroll
        for (int ww = 0; ww < 8; ww++) {
            float2 v = *(const float2*)((const float*)smb + ww * 640 + qi * 40 + 2 * p);
            o0 += v.x; o1 += v.y;
            gs += rsums[ww * 16 + qi];
        }
        float inv = 1.0f / gs;
        uint32_t hi, lo;
        split_pack(o0 * inv, o1 * inv, hi, lo);
        int hw = (wy * 4 + (qi >> 2)) * HH + wx * 4 + (qi & 3);
        size_t a = ((size_t)b * HWN + hw) * 60 + h * 14 + p;
        g_oh[a] = hi;
        g_ol[a] = lo;
    }
}

// =============================================================================
// Kernel C: output projection via mma.sync; A loaded pre-split via cp.async.
// =============================================================================
__global__ __launch_bounds__(512, 2) void proj_kernel(const float* __restrict__ Wp,
                                                      const float* __restrict__ bias,
                                                      float* __restrict__ out) {
    extern __shared__ char smb[];
    const uint32_t sbase = smem_u32(smb);
    const int tid = threadIdx.x;
    const int b   = blockIdx.y;
    const int hw0 = blockIdx.x * 128;

    // A tiles direct from pre-split attention output (15 x 16B per 240B row)
    for (int i = tid; i < 1920; i += 512) {
        int row = i / 15, j = i - row * 15;
        size_t s = ((size_t)b * HWN + hw0 + row) * 60 + j * 4;
        uint32_t doff = (uint32_t)(row * 240 + j * 16);
        cp16(sbase + AH_B + doff, g_oh + s);
        cp16(sbase + AL_B + doff, g_ol + s);
    }
    asm volatile("cp.async.commit_group;");

    // W conversion (overlaps with cp.async)
    for (int i = tid; i < 6272; i += 512) {
        int d = i / 56, cp = i - d * 56;
        float2 wv = *(const float2*)(Wp + (size_t)d * CC + cp * 2);
        uint32_t hi, lo;
        split_pack(wv.x, wv.y, hi, lo);
        ((uint32_t*)(smb + WH_B))[d * 60 + cp] = hi;
        ((uint32_t*)(smb + WL_B))[d * 60 + cp] = lo;
    }
    asm volatile("cp.async.wait_group 0;" ::: "memory");
    __syncthreads();

    const int lane = tid & 31;
    const int wid  = tid >> 5;
    const int wm   = wid & 7;
    const int wn   = wid >> 3;
    const int mrow = wm * 16;
    const int amat = lane >> 3, ar = lane & 7;
    const uint32_t a_off = (uint32_t)((mrow + ar + (amat & 1) * 8) * 240
                                      + (amat >> 1) * 16);
    const uint32_t b_lane_off = (uint32_t)((lane & 7) * 240 + ((lane >> 3) & 1) * 16);
    const int orow  = mrow + (lane >> 2);
    const int ocol0 = wn * 56 + 2 * (lane & 3);

    float acc[7][4];
    #pragma unroll
    for (int nt = 0; nt < 7; nt++)
        #pragma unroll
        for (int j = 0; j < 4; j++) acc[nt][j] = 0.0f;

    #pragma unroll
    for (int ks = 0; ks < 7; ks++) {
        uint32_t ah[4], al[4];
        ldsm4(ah, sbase + AH_B + a_off + ks * 32);
        ldsm4(al, sbase + AL_B + a_off + ks * 32);
        #pragma unroll
        for (int nt = 0; nt < 7; nt++) {
            uint32_t bh[2], bl[2];
            uint32_t boff = (uint32_t)((wn * 56 + nt * 8) * 240) + b_lane_off + ks * 32;
            ldsm2(bh, sbase + WH_B + boff);
            ldsm2(bl, sbase + WL_B + boff);
            mma_bf16(acc[nt], ah, bh);
            mma_bf16(acc[nt], ah, bl);
            mma_bf16(acc[nt], al, bh);
        }
    }
    __syncthreads();   // A region dead; reuse as transpose stage

    float* stage = (float*)smb;
    #pragma unroll
    for (int nt = 0; nt < 7; nt++) {
        int d = ocol0 + nt * 8;
        stage[d * 132 + orow]           = acc[nt][0];
        stage[(d + 1) * 132 + orow]     = acc[nt][1];
        stage[d * 132 + orow + 8]       = acc[nt][2];
        stage[(d + 1) * 132 + orow + 8] = acc[nt][3];
    }
    __syncthreads();

    for (int i = tid; i < 3584; i += 512) {
        int d = i >> 5, j = i & 31;
        float4 v = *(const float4*)(stage + d * 132 + j * 4);
        float bv = __ldg(bias + d);
        v.x += bv; v.y += bv; v.z += bv; v.w += bv;
        *(float4*)(out + ((size_t)b * CC + d) * HWN + hw0 + j * 4) = v;
    }
}

// =============================================================================
extern "C" void kernel_launch(void* const* d_in, const int* in_sizes, int n_in,
                              void* d_out, int out_size) {
    const float* x     = (const float*)d_in[0];
    const float* Wqkv  = (const float*)d_in[1];
    const float* Wproj = (const float*)d_in[2];
    const float* bproj = (const float*)d_in[3];
    const int*   topk  = (const int*)d_in[4];
    float* out = (float*)d_out;

    cudaFuncSetAttribute(qkv_kernel,  cudaFuncAttributeMaxDynamicSharedMemorySize, MMA_SMEM_B);
    cudaFuncSetAttribute(attn_kernel, cudaFuncAttributeMaxDynamicSharedMemorySize, ATTN_SMEM_B);
    cudaFuncSetAttribute(proj_kernel, cudaFuncAttributeMaxDynamicSharedMemorySize, MMA_SMEM_B);

    qkv_kernel<<<dim3(32, 16), 512, MMA_SMEM_B>>>(x, Wqkv);
    attn_kernel<<<BB * NWIN * NHEAD, 256, ATTN_SMEM_B>>>(topk);
    proj_kernel<<<dim3(32, 16), 512, MMA_SMEM_B>>>(Wproj, bproj, out);
}

// round 13
// speedup vs baseline: 2.5398x; 1.0406x over previous
#include <cuda_runtime.h>
#include <cuda_bf16.h>
#include <cstdint>

#define BB    16
#define CC    112
#define HH    64
#define HWN   4096
#define NHEAD 4
#define HD    28
#define NWIN  256
#define TOPK  128
#define SCALE 0.18898223650461363f   // 28^-0.5

// ---- mma (qkv/proj) smem byte offsets: 240B rows (15x16B odd, conflict-free)
#define AH_B   0
#define AL_B   30720
#define WH_B   61440
#define WL_B   88320
#define MMA_SMEM_B 115200
// qkv epilogue stage overlays WH/WL: 128 rows x 68 u32 = 34816B

// ---- attn smem byte offsets: 80B rows (5x16B odd, ldsm conflict-free) ----
#define KH_B    0        // 128 x 80B = 10240
#define KL_B    10240
#define VH_B    20480
#define VL_B    30720
#define QH_B    40960    // 16 x 80B = 1280
#define QL_B    42240
#define RMAX_B  43520    // 8 warps x 16 f32
#define RSUM_B  44032
#define ATTN_SMEM_B 44544
// O stage overlays KH/KL: 8 slabs x (16 rows x 40 f32) = 20480B exactly

// ---------------- scratch (device globals; no allocation allowed) ------------
// bf16-split planes, per-head rows of 16 u32 (ch pairs 0..13 + zero pads 14,15)
__device__ __align__(16) uint32_t g_qh[BB * NHEAD * HWN * 16];
__device__ __align__(16) uint32_t g_ql[BB * NHEAD * HWN * 16];
__device__ __align__(16) uint32_t g_kh[BB * NHEAD * HWN * 16];
__device__ __align__(16) uint32_t g_kl[BB * NHEAD * HWN * 16];
__device__ __align__(16) uint32_t g_vh[BB * NHEAD * HWN * 16];
__device__ __align__(16) uint32_t g_vl[BB * NHEAD * HWN * 16];
// attention output, split, rows of 60 u32 (56 ch pairs + 4 pad, 240B rows)
__device__ __align__(16) uint32_t g_oh[BB * HWN * 60];
__device__ __align__(16) uint32_t g_ol[BB * HWN * 60];

__device__ __forceinline__ uint32_t smem_u32(const void* p) {
    uint32_t a;
    asm("{ .reg .u64 t; cvta.to.shared.u64 t, %1; cvt.u32.u64 %0, t; }" : "=r"(a) : "l"(p));
    return a;
}
__device__ __forceinline__ void cp16(uint32_t dst, const void* src) {
    asm volatile("cp.async.cg.shared.global [%0], [%1], 16;" :: "r"(dst), "l"(src) : "memory");
}
__device__ __forceinline__ void ldsm4(uint32_t* r, uint32_t a) {
    asm volatile("ldmatrix.sync.aligned.m8n8.x4.shared.b16 {%0,%1,%2,%3}, [%4];"
                 : "=r"(r[0]), "=r"(r[1]), "=r"(r[2]), "=r"(r[3]) : "r"(a));
}
__device__ __forceinline__ void ldsm2(uint32_t* r, uint32_t a) {
    asm volatile("ldmatrix.sync.aligned.m8n8.x2.shared.b16 {%0,%1}, [%2];"
                 : "=r"(r[0]), "=r"(r[1]) : "r"(a));
}
__device__ __forceinline__ void ldsm2t(uint32_t* r, uint32_t a) {
    asm volatile("ldmatrix.sync.aligned.m8n8.x2.trans.shared.b16 {%0,%1}, [%2];"
                 : "=r"(r[0]), "=r"(r[1]) : "r"(a));
}
__device__ __forceinline__ void mma_bf16(float* d, const uint32_t* a, const uint32_t* b) {
    asm volatile("mma.sync.aligned.m16n8k16.row.col.f32.bf16.bf16.f32 "
                 "{%0,%1,%2,%3}, {%4,%5,%6,%7}, {%8,%9}, {%0,%1,%2,%3};"
                 : "+f"(d[0]), "+f"(d[1]), "+f"(d[2]), "+f"(d[3])
                 : "r"(a[0]), "r"(a[1]), "r"(a[2]), "r"(a[3]), "r"(b[0]), "r"(b[1]));
}
__device__ __forceinline__ void split_pack(float a0, float a1, uint32_t& hi, uint32_t& lo) {
    __nv_bfloat16 h0 = __float2bfloat16(a0);
    __nv_bfloat16 h1 = __float2bfloat16(a1);
    __nv_bfloat16 l0 = __float2bfloat16(a0 - __bfloat162float(h0));
    __nv_bfloat16 l1 = __float2bfloat16(a1 - __bfloat162float(h1));
    hi = ((uint32_t)__bfloat16_as_ushort(h1) << 16) | __bfloat16_as_ushort(h0);
    lo = ((uint32_t)__bfloat16_as_ushort(l1) << 16) | __bfloat16_as_ushort(l0);
}

// =============================================================================
// Kernel A: QKV projection via mma.sync bf16-split; staged coalesced epilogue.
// =============================================================================
__global__ __launch_bounds__(512, 2) void qkv_kernel(const float* __restrict__ x,
                                                     const float* __restrict__ Wqkv) {
    extern __shared__ char smb[];
    float* xs = (float*)(smb + WH_B);
    const uint32_t sbase = smem_u32(smb);

    const int tid = threadIdx.x;
    const int b   = blockIdx.y;
    const int hw0 = blockIdx.x * 128;

    // A conversion (x tile, transposed to [px][ch]) in two 56-channel chunks
    #pragma unroll
    for (int chunk = 0; chunk < 2; chunk++) {
        for (int i = tid; i < 1792; i += 512) {
            int c = i >> 5, p4 = i & 31;
            ((float4*)xs)[i] =
                ((const float4*)(x + (b * CC + chunk * 56 + c) * HWN + hw0))[p4];
        }
        __syncthreads();
        for (int i = tid; i < 3584; i += 512) {
            int px = i & 127, cp = i >> 7;
            uint32_t hi, lo;
            split_pack(xs[(cp * 2) * 128 + px], xs[(cp * 2 + 1) * 128 + px], hi, lo);
            int idx = px * 60 + chunk * 28 + cp;
            ((uint32_t*)(smb + AH_B))[idx] = hi;
            ((uint32_t*)(smb + AL_B))[idx] = lo;
        }
        __syncthreads();
    }

    const int lane = tid & 31;
    const int wid  = tid >> 5;
    const int wm   = wid & 7;
    const int wn   = wid >> 3;
    const int mrow = wm * 16;

    const int amat = lane >> 3, ar = lane & 7;
    const uint32_t a_off = (uint32_t)((mrow + ar + (amat & 1) * 8) * 240
                                      + (amat >> 1) * 16);
    const uint32_t b_lane_off = (uint32_t)((lane & 7) * 240 + ((lane >> 3) & 1) * 16);

    const int orow  = mrow + (lane >> 2);
    const int ocol0 = wn * 56 + 2 * (lane & 3);

    for (int seg = 0; seg < 3; seg++) {
        const float s = (seg == 0) ? SCALE : 1.0f;
        for (int i = tid; i < 6272; i += 512) {
            int d = i / 56, cp = i - d * 56;
            float2 wv = *(const float2*)(Wqkv + (size_t)(seg * CC + d) * CC + cp * 2);
            uint32_t hi, lo;
            split_pack(wv.x * s, wv.y * s, hi, lo);
            ((uint32_t*)(smb + WH_B))[d * 60 + cp] = hi;
            ((uint32_t*)(smb + WL_B))[d * 60 + cp] = lo;
        }
        __syncthreads();

        float acc[7][4];
        #pragma unroll
        for (int nt = 0; nt < 7; nt++)
            #pragma unroll
            for (int j = 0; j < 4; j++) acc[nt][j] = 0.0f;

        #pragma unroll
        for (int ks = 0; ks < 7; ks++) {
            uint32_t ah[4], al[4];
            ldsm4(ah, sbase + AH_B + a_off + ks * 32);
            ldsm4(al, sbase + AL_B + a_off + ks * 32);
            #pragma unroll
            for (int nt = 0; nt < 7; nt++) {
                uint32_t bh[2], bl[2];
                uint32_t boff = (uint32_t)((wn * 56 + nt * 8) * 240) + b_lane_off + ks * 32;
                ldsm2(bh, sbase + WH_B + boff);
                ldsm2(bl, sbase + WL_B + boff);
                mma_bf16(acc[nt], ah, bh);
                mma_bf16(acc[nt], ah, bl);
                mma_bf16(acc[nt], al, bh);
            }
        }

        // ---- epilogue: two passes (hi, lo) through stride-68 smem stage ----
        uint32_t* stg = (uint32_t*)(smb + WH_B);   // W dead after MMA loop
        #pragma unroll
        for (int pass = 0; pass < 2; pass++) {
            __syncthreads();   // pass0: all warps done reading W; pass1: stores done
            // zero pad columns (u32 cols 14,15 of each head's 16)
            for (int i = tid; i < 1024; i += 512) {
                int px = i >> 3, hh = (i >> 1) & 3, pc = 14 + (i & 1);
                stg[px * 68 + hh * 16 + pc] = 0;
            }
            #pragma unroll
            for (int nt = 0; nt < 7; nt++) {
                int d = ocol0 + nt * 8;
                int hh = d / 28;
                int cidx = (d - hh * 28) >> 1;
                uint32_t hi, lo;
                split_pack(acc[nt][0], acc[nt][1], hi, lo);
                stg[orow * 68 + hh * 16 + cidx] = pass ? lo : hi;
                split_pack(acc[nt][2], acc[nt][3], hi, lo);
                stg[(orow + 8) * 68 + hh * 16 + cidx] = pass ? lo : hi;
            }
            __syncthreads();
            uint32_t* gp;
            if (seg == 0)      gp = pass ? g_ql : g_qh;
            else if (seg == 1) gp = pass ? g_kl : g_kh;
            else               gp = pass ? g_vl : g_vh;
            for (int i = tid; i < 2048; i += 512) {
                int px = i >> 4, j = i & 15;     // j: head(2b) | chunk(2b)
                uint4 v = *(const uint4*)(stg + px * 68 + j * 4);
                *(uint4*)(gp + ((size_t)(b * 4 + (j >> 2)) * HWN + hw0 + px) * 16
                          + (j & 3) * 4) = v;
            }
        }
        __syncthreads();   // stage dead before next seg's W conversion
    }
}

// =============================================================================
// Kernel B: FA2-style windowed top-k attention on mma.sync (occupancy 5).
// =============================================================================
__global__ __launch_bounds__(256, 5) void attn_kernel(const int* __restrict__ topk) {
    extern __shared__ char smb[];
    const uint32_t sbase = smem_u32(smb);
    const int tid  = threadIdx.x;
    const int lane = tid & 31;
    const int wrp  = tid >> 5;
    const int bx   = blockIdx.x;
    const int h    = bx & 3;
    const int w    = (bx >> 2) & 255;
    const int b    = bx >> 10;
    const int wy   = w >> 4, wx = w & 15;

    // ---- gather K/V hi+lo slices + Q (cp.async) ----
    {
        const int* tkw = topk + w * TOPK;
        const size_t hb = (size_t)(b * 4 + h) * HWN;
        for (int i = tid; i < 512; i += 256) {
            int row = i & 127, c = i >> 7;
            int pos = __ldg(tkw + row);
            size_t s = (hb + pos) * 16 + c * 4;
            uint32_t doff = (uint32_t)(row * 80 + c * 16);
            cp16(sbase + KH_B + doff, g_kh + s);
            cp16(sbase + KL_B + doff, g_kl + s);
            cp16(sbase + VH_B + doff, g_vh + s);
            cp16(sbase + VL_B + doff, g_vl + s);
        }
        if (tid < 64) {
            int qi = tid & 15, c = tid >> 4;
            int hw = (wy * 4 + (qi >> 2)) * HH + wx * 4 + (qi & 3);
            size_t s = (hb + hw) * 16 + c * 4;
            cp16(sbase + QH_B + qi * 80 + c * 16, g_qh + s);
            cp16(sbase + QL_B + qi * 80 + c * 16, g_ql + s);
        }
        asm volatile("cp.async.commit_group;");
        asm volatile("cp.async.wait_group 0;" ::: "memory");
    }
    __syncthreads();

    // ---- S = Q K^T (3-term bf16 split). Warp owns n-tiles 2w, 2w+1 ----
    float c0[4] = {0.f, 0.f, 0.f, 0.f};
    float c1[4] = {0.f, 0.f, 0.f, 0.f};
    {
        const uint32_t q_l = (uint32_t)((lane & 15) * 80 + (lane >> 4) * 16);
        const uint32_t k_l = (uint32_t)((lane & 7) * 80 + ((lane >> 3) & 1) * 16);
        #pragma unroll
        for (int ks = 0; ks < 2; ks++) {
            uint32_t aqh[4], aql[4];
            ldsm4(aqh, sbase + QH_B + q_l + ks * 32);
            ldsm4(aql, sbase + QL_B + q_l + ks * 32);
            uint32_t bh[2], bl[2];
            uint32_t kb = (uint32_t)(wrp * 16 * 80) + k_l + ks * 32;
            ldsm2(bh, sbase + KH_B + kb);
            ldsm2(bl, sbase + KL_B + kb);
            mma_bf16(c0, aqh, bh); mma_bf16(c0, aqh, bl); mma_bf16(c0, aql, bh);
            kb += 8 * 80;
            ldsm2(bh, sbase + KH_B + kb);
            ldsm2(bl, sbase + KL_B + kb);
            mma_bf16(c1, aqh, bh); mma_bf16(c1, aqh, bl); mma_bf16(c1, aql, bh);
        }
    }

    float* rmaxs = (float*)(smb + RMAX_B);
    float* rsums = (float*)(smb + RSUM_B);
    const int r0 = lane >> 2;
    {
        float m0 = fmaxf(fmaxf(c0[0], c0[1]), fmaxf(c1[0], c1[1]));
        float m1 = fmaxf(fmaxf(c0[2], c0[3]), fmaxf(c1[2], c1[3]));
        m0 = fmaxf(m0, __shfl_xor_sync(0xffffffffu, m0, 1));
        m0 = fmaxf(m0, __shfl_xor_sync(0xffffffffu, m0, 2));
        m1 = fmaxf(m1, __shfl_xor_sync(0xffffffffu, m1, 1));
        m1 = fmaxf(m1, __shfl_xor_sync(0xffffffffu, m1, 2));
        if ((lane & 3) == 0) {
            rmaxs[wrp * 16 + r0]     = m0;
            rmaxs[wrp * 16 + r0 + 8] = m1;
        }
    }
    __syncthreads();

    uint32_t aph[4], apl[4];
    {
        float g0 = rmaxs[r0], g1 = rmaxs[r0 + 8];
        #pragma unroll
        for (int ww = 1; ww < 8; ww++) {
            g0 = fmaxf(g0, rmaxs[ww * 16 + r0]);
            g1 = fmaxf(g1, rmaxs[ww * 16 + r0 + 8]);
        }
        c0[0] = __expf(c0[0] - g0); c0[1] = __expf(c0[1] - g0);
        c1[0] = __expf(c1[0] - g0); c1[1] = __expf(c1[1] - g0);
        c0[2] = __expf(c0[2] - g1); c0[3] = __expf(c0[3] - g1);
        c1[2] = __expf(c1[2] - g1); c1[3] = __expf(c1[3] - g1);
        float s0 = c0[0] + c0[1] + c1[0] + c1[1];
        float s1 = c0[2] + c0[3] + c1[2] + c1[3];
        s0 += __shfl_xor_sync(0xffffffffu, s0, 1);
        s0 += __shfl_xor_sync(0xffffffffu, s0, 2);
        s1 += __shfl_xor_sync(0xffffffffu, s1, 1);
        s1 += __shfl_xor_sync(0xffffffffu, s1, 2);
        if ((lane & 3) == 0) {
            rsums[wrp * 16 + r0]     = s0;
            rsums[wrp * 16 + r0 + 8] = s1;
        }
        split_pack(c0[0], c0[1], aph[0], apl[0]);
        split_pack(c0[2], c0[3], aph[1], apl[1]);
        split_pack(c1[0], c1[1], aph[2], apl[2]);
        split_pack(c1[2], c1[3], aph[3], apl[3]);
    }
    __syncthreads();   // rsums visible; K region now dead -> O stage overlay

    // ---- PV: warp's kstep = kj 16w..16w+15; V via ldmatrix.trans ----
    {
        const uint32_t v_l = (uint32_t)((wrp * 16 + (lane & 15)) * 80);
        float* slab = (float*)smb + wrp * 640;   // 16 rows x 40 f32
        #pragma unroll
        for (int nt = 0; nt < 4; nt++) {
            float o[4] = {0.f, 0.f, 0.f, 0.f};
            uint32_t bh[2], bl[2];
            ldsm2t(bh, sbase + VH_B + v_l + nt * 16);
            ldsm2t(bl, sbase + VL_B + v_l + nt * 16);
            mma_bf16(o, aph, bh); mma_bf16(o, aph, bl); mma_bf16(o, apl, bh);
            float* sp = slab + r0 * 40 + nt * 8 + 2 * (lane & 3);
            *(float2*)sp            = make_float2(o[0], o[1]);
            *(float2*)(sp + 8 * 40) = make_float2(o[2], o[3]);
        }
    }
    __syncthreads();

    // ---- reduce 8 slabs, normalize, split, store ----
    if (tid < 224) {
        int qi = tid / 14, p = tid - qi * 14;
        float o0 = 0.f, o1 = 0.f, gs = 0.f;
        #pragma unroll
        for (int ww = 0; ww < 8; ww++) {
            float2 v = *(const float2*)((const float*)smb + ww * 640 + qi * 40 + 2 * p);
            o0 += v.x; o1 += v.y;
            gs += rsums[ww * 16 + qi];
        }
        float inv = 1.0f / gs;
        uint32_t hi, lo;
        split_pack(o0 * inv, o1 * inv, hi, lo);
        int hw = (wy * 4 + (qi >> 2)) * HH + wx * 4 + (qi & 3);
        size_t a = ((size_t)b * HWN + hw) * 60 + h * 14 + p;
        g_oh[a] = hi;
        g_ol[a] = lo;
    }
}

// =============================================================================
// Kernel C: output projection via mma.sync; A loaded pre-split via cp.async.
// =============================================================================
__global__ __launch_bounds__(512, 2) void proj_kernel(const float* __restrict__ Wp,
                                                      const float* __restrict__ bias,
                                                      float* __restrict__ out) {
    extern __shared__ char smb[];
    const uint32_t sbase = smem_u32(smb);
    const int tid = threadIdx.x;
    const int b   = blockIdx.y;
    const int hw0 = blockIdx.x * 128;

    for (int i = tid; i < 1920; i += 512) {
        int row = i / 15, j = i - row * 15;
        size_t s = ((size_t)b * HWN + hw0 + row) * 60 + j * 4;
        uint32_t doff = (uint32_t)(row * 240 + j * 16);
        cp16(sbase + AH_B + doff, g_oh + s);
        cp16(sbase + AL_B + doff, g_ol + s);
    }
    asm volatile("cp.async.commit_group;");

    for (int i = tid; i < 6272; i += 512) {
        int d = i / 56, cp = i - d * 56;
        float2 wv = *(const float2*)(Wp + (size_t)d * CC + cp * 2);
        uint32_t hi, lo;
        split_pack(wv.x, wv.y, hi, lo);
        ((uint32_t*)(smb + WH_B))[d * 60 + cp] = hi;
        ((uint32_t*)(smb + WL_B))[d * 60 + cp] = lo;
    }
    asm volatile("cp.async.wait_group 0;" ::: "memory");
    __syncthreads();

    const int lane = tid & 31;
    const int wid  = tid >> 5;
    const int wm   = wid & 7;
    const int wn   = wid >> 3;
    const int mrow = wm * 16;
    const int amat = lane >> 3, ar = lane & 7;
    const uint32_t a_off = (uint32_t)((mrow + ar + (amat & 1) * 8) * 240
                                      + (amat >> 1) * 16);
    const uint32_t b_lane_off = (uint32_t)((lane & 7) * 240 + ((lane >> 3) & 1) * 16);
    const int orow  = mrow + (lane >> 2);
    const int ocol0 = wn * 56 + 2 * (lane & 3);

    float acc[7][4];
    #pragma unroll
    for (int nt = 0; nt < 7; nt++)
        #pragma unroll
        for (int j = 0; j < 4; j++) acc[nt][j] = 0.0f;

    #pragma unroll
    for (int ks = 0; ks < 7; ks++) {
        uint32_t ah[4], al[4];
        ldsm4(ah, sbase + AH_B + a_off + ks * 32);
        ldsm4(al, sbase + AL_B + a_off + ks * 32);
        #pragma unroll
        for (int nt = 0; nt < 7; nt++) {
            uint32_t bh[2], bl[2];
            uint32_t boff = (uint32_t)((wn * 56 + nt * 8) * 240) + b_lane_off + ks * 32;
            ldsm2(bh, sbase + WH_B + boff);
            ldsm2(bl, sbase + WL_B + boff);
            mma_bf16(acc[nt], ah, bh);
            mma_bf16(acc[nt], ah, bl);
            mma_bf16(acc[nt], al, bh);
        }
    }
    __syncthreads();   // A region dead; reuse as transpose stage

    float* stage = (float*)smb;
    #pragma unroll
    for (int nt = 0; nt < 7; nt++) {
        int d = ocol0 + nt * 8;
        stage[d * 132 + orow]           = acc[nt][0];
        stage[(d + 1) * 132 + orow]     = acc[nt][1];
        stage[d * 132 + orow + 8]       = acc[nt][2];
        stage[(d + 1) * 132 + orow + 8] = acc[nt][3];
    }
    __syncthreads();

    for (int i = tid; i < 3584; i += 512) {
        int d = i >> 5, j = i & 31;
        float4 v = *(const float4*)(stage + d * 132 + j * 4);
        float bv = __ldg(bias + d);
        v.x += bv; v.y += bv; v.z += bv; v.w += bv;
        *(float4*)(out + ((size_t)b * CC + d) * HWN + hw0 + j * 4) = v;
    }
}

// =============================================================================
extern "C" void kernel_launch(void* const* d_in, const int* in_sizes, int n_in,
                              void* d_out, int out_size) {
    const float* x     = (const float*)d_in[0];
    const float* Wqkv  = (const float*)d_in[1];
    const float* Wproj = (const float*)d_in[2];
    const float* bproj = (const float*)d_in[3];
    const int*   topk  = (const int*)d_in[4];
    float* out = (float*)d_out;

    cudaFuncSetAttribute(qkv_kernel,  cudaFuncAttributeMaxDynamicSharedMemorySize, MMA_SMEM_B);
    cudaFuncSetAttribute(attn_kernel, cudaFuncAttributeMaxDynamicSharedMemorySize, ATTN_SMEM_B);
    cudaFuncSetAttribute(proj_kernel, cudaFuncAttributeMaxDynamicSharedMemorySize, MMA_SMEM_B);

    qkv_kernel<<<dim3(32, 16), 512, MMA_SMEM_B>>>(x, Wqkv);
    attn_kernel<<<BB * NWIN * NHEAD, 256, ATTN_SMEM_B>>>(topk);
    proj_kernel<<<dim3(32, 16), 512, MMA_SMEM_B>>>(Wproj, bproj, out);
}

// round 14
// speedup vs baseline: 2.6782x; 1.0545x over previous
#include <cuda_runtime.h>
#include <cuda_bf16.h>
#include <cstdint>

#define BB    16
#define CC    112
#define HH    64
#define HWN   4096
#define NHEAD 4
#define HD    28
#define NWIN  256
#define TOPK  128
#define SCALE 0.18898223650461363f   // 28^-0.5

// ---- mma (qkv/proj) smem byte offsets: 240B rows (15x16B odd, conflict-free)
#define AH_B   0
#define AL_B   30720
#define WH_B   61440
#define WL_B   88320
#define MMA_SMEM_B 115200
// qkv epilogue stage overlays WH/WL: 128 rows x 68 u32 = 34816B

// ---- attn smem byte offsets: 80B rows (5x16B odd, ldsm conflict-free) ----
#define KH_B    0        // 128 x 80B = 10240
#define KL_B    10240
#define VH_B    20480
#define VL_B    30720
#define QH_B    40960    // 16 x 80B = 1280
#define QL_B    42240
#define RMAX_B  43520    // 8 warps x 16 f32
#define RSUM_B  44032
#define ATTN_SMEM_B 44544
// O stage overlays KH/KL: 8 slabs x (16 rows x 40 f32) = 20480B exactly

// ---------------- scratch (device globals; no allocation allowed) ------------
__device__ __align__(16) uint32_t g_qh[BB * NHEAD * HWN * 16];
__device__ __align__(16) uint32_t g_ql[BB * NHEAD * HWN * 16];
__device__ __align__(16) uint32_t g_kh[BB * NHEAD * HWN * 16];
__device__ __align__(16) uint32_t g_kl[BB * NHEAD * HWN * 16];
__device__ __align__(16) uint32_t g_vh[BB * NHEAD * HWN * 16];
__device__ __align__(16) uint32_t g_vl[BB * NHEAD * HWN * 16];
__device__ __align__(16) uint32_t g_oh[BB * HWN * 60];
__device__ __align__(16) uint32_t g_ol[BB * HWN * 60];
// pre-split weights: segs 0..2 = Wqkv (SCALE folded into seg 0), seg 3 = Wproj
__device__ __align__(16) uint32_t g_wh[4 * CC * 60];
__device__ __align__(16) uint32_t g_wl[4 * CC * 60];

__device__ __forceinline__ uint32_t smem_u32(const void* p) {
    uint32_t a;
    asm("{ .reg .u64 t; cvta.to.shared.u64 t, %1; cvt.u32.u64 %0, t; }" : "=r"(a) : "l"(p));
    return a;
}
__device__ __forceinline__ void cp16(uint32_t dst, const void* src) {
    asm volatile("cp.async.cg.shared.global [%0], [%1], 16;" :: "r"(dst), "l"(src) : "memory");
}
__device__ __forceinline__ void ldsm4(uint32_t* r, uint32_t a) {
    asm volatile("ldmatrix.sync.aligned.m8n8.x4.shared.b16 {%0,%1,%2,%3}, [%4];"
                 : "=r"(r[0]), "=r"(r[1]), "=r"(r[2]), "=r"(r[3]) : "r"(a));
}
__device__ __forceinline__ void ldsm2(uint32_t* r, uint32_t a) {
    asm volatile("ldmatrix.sync.aligned.m8n8.x2.shared.b16 {%0,%1}, [%2];"
                 : "=r"(r[0]), "=r"(r[1]) : "r"(a));
}
__device__ __forceinline__ void ldsm4t(uint32_t* r, uint32_t a) {
    asm volatile("ldmatrix.sync.aligned.m8n8.x4.trans.shared.b16 {%0,%1,%2,%3}, [%4];"
                 : "=r"(r[0]), "=r"(r[1]), "=r"(r[2]), "=r"(r[3]) : "r"(a));
}
__device__ __forceinline__ void mma_bf16(float* d, const uint32_t* a, const uint32_t* b) {
    asm volatile("mma.sync.aligned.m16n8k16.row.col.f32.bf16.bf16.f32 "
                 "{%0,%1,%2,%3}, {%4,%5,%6,%7}, {%8,%9}, {%0,%1,%2,%3};"
                 : "+f"(d[0]), "+f"(d[1]), "+f"(d[2]), "+f"(d[3])
                 : "r"(a[0]), "r"(a[1]), "r"(a[2]), "r"(a[3]), "r"(b[0]), "r"(b[1]));
}
__device__ __forceinline__ void split_pack(float a0, float a1, uint32_t& hi, uint32_t& lo) {
    __nv_bfloat16 h0 = __float2bfloat16(a0);
    __nv_bfloat16 h1 = __float2bfloat16(a1);
    __nv_bfloat16 l0 = __float2bfloat16(a0 - __bfloat162float(h0));
    __nv_bfloat16 l1 = __float2bfloat16(a1 - __bfloat162float(h1));
    hi = ((uint32_t)__bfloat16_as_ushort(h1) << 16) | __bfloat16_as_ushort(h0);
    lo = ((uint32_t)__bfloat16_as_ushort(l1) << 16) | __bfloat16_as_ushort(l0);
}

// =============================================================================
// Kernel 0: one-shot weight pre-split. Block = seg (0..2 Wqkv, 3 Wproj).
// =============================================================================
__global__ __launch_bounds__(256) void prep_kernel(const float* __restrict__ Wqkv,
                                                   const float* __restrict__ Wproj) {
    const int seg = blockIdx.x;
    const float* src = (seg < 3) ? (Wqkv + (size_t)seg * CC * CC) : Wproj;
    const float s = (seg == 0) ? SCALE : 1.0f;
    const int base = seg * 6720;
    for (int i = threadIdx.x; i < 6272; i += 256) {
        int d = i / 56, cp = i - d * 56;
        float2 wv = *(const float2*)(src + (size_t)d * CC + cp * 2);
        uint32_t hi, lo;
        split_pack(wv.x * s, wv.y * s, hi, lo);
        g_wh[base + d * 60 + cp] = hi;
        g_wl[base + d * 60 + cp] = lo;
    }
    for (int i = threadIdx.x; i < 448; i += 256) {   // zero tail cols 56..59
        int d = i >> 2;
        g_wh[base + d * 60 + 56 + (i & 3)] = 0;
        g_wl[base + d * 60 + 56 + (i & 3)] = 0;
    }
}

// =============================================================================
// Kernel A: QKV projection via mma.sync bf16-split; W tiles via cp.async.
// =============================================================================
__global__ __launch_bounds__(512, 2) void qkv_kernel(const float* __restrict__ x) {
    extern __shared__ char smb[];
    float* xs = (float*)(smb + WH_B);
    const uint32_t sbase = smem_u32(smb);

    const int tid = threadIdx.x;
    const int b   = blockIdx.y;
    const int hw0 = blockIdx.x * 128;

    // A conversion (x tile, transposed to [px][ch]) in two 56-channel chunks
    #pragma unroll
    for (int chunk = 0; chunk < 2; chunk++) {
        for (int i = tid; i < 1792; i += 512) {
            int c = i >> 5, p4 = i & 31;
            ((float4*)xs)[i] =
                ((const float4*)(x + (b * CC + chunk * 56 + c) * HWN + hw0))[p4];
        }
        __syncthreads();
        for (int i = tid; i < 3584; i += 512) {
            int px = i & 127, cp = i >> 7;
            uint32_t hi, lo;
            split_pack(xs[(cp * 2) * 128 + px], xs[(cp * 2 + 1) * 128 + px], hi, lo);
            int idx = px * 60 + chunk * 28 + cp;
            ((uint32_t*)(smb + AH_B))[idx] = hi;
            ((uint32_t*)(smb + AL_B))[idx] = lo;
        }
        __syncthreads();
    }

    const int lane = tid & 31;
    const int wid  = tid >> 5;
    const int wm   = wid & 7;
    const int wn   = wid >> 3;
    const int mrow = wm * 16;

    const int amat = lane >> 3, ar = lane & 7;
    const uint32_t a_off = (uint32_t)((mrow + ar + (amat & 1) * 8) * 240
                                      + (amat >> 1) * 16);
    const uint32_t b_lane_off = (uint32_t)((lane & 7) * 240 + ((lane >> 3) & 1) * 16);

    const int orow  = mrow + (lane >> 2);
    const int ocol0 = wn * 56 + 2 * (lane & 3);

    for (int seg = 0; seg < 3; seg++) {
        // ---- load pre-split W tiles (linear cp.async) ----
        for (int i = tid; i < 1680; i += 512) {
            cp16(sbase + WH_B + i * 16, g_wh + seg * 6720 + i * 4);
            cp16(sbase + WL_B + i * 16, g_wl + seg * 6720 + i * 4);
        }
        asm volatile("cp.async.commit_group;");
        asm volatile("cp.async.wait_group 0;" ::: "memory");
        __syncthreads();

        float acc[7][4];
        #pragma unroll
        for (int nt = 0; nt < 7; nt++)
            #pragma unroll
            for (int j = 0; j < 4; j++) acc[nt][j] = 0.0f;

        #pragma unroll
        for (int ks = 0; ks < 7; ks++) {
            uint32_t ah[4], al[4];
            ldsm4(ah, sbase + AH_B + a_off + ks * 32);
            ldsm4(al, sbase + AL_B + a_off + ks * 32);
            #pragma unroll
            for (int nt = 0; nt < 7; nt++) {
                uint32_t bh[2], bl[2];
                uint32_t boff = (uint32_t)((wn * 56 + nt * 8) * 240) + b_lane_off + ks * 32;
                ldsm2(bh, sbase + WH_B + boff);
                ldsm2(bl, sbase + WL_B + boff);
                mma_bf16(acc[nt], ah, bh);
                mma_bf16(acc[nt], ah, bl);
                mma_bf16(acc[nt], al, bh);
            }
        }

        // ---- epilogue: two passes (hi, lo) through stride-68 smem stage ----
        uint32_t* stg = (uint32_t*)(smb + WH_B);   // W dead after MMA loop
        #pragma unroll
        for (int pass = 0; pass < 2; pass++) {
            __syncthreads();
            for (int i = tid; i < 1024; i += 512) {
                int px = i >> 3, hh = (i >> 1) & 3, pc = 14 + (i & 1);
                stg[px * 68 + hh * 16 + pc] = 0;
            }
            #pragma unroll
            for (int nt = 0; nt < 7; nt++) {
                int d = ocol0 + nt * 8;
                int hh = d / 28;
                int cidx = (d - hh * 28) >> 1;
                uint32_t hi, lo;
                split_pack(acc[nt][0], acc[nt][1], hi, lo);
                stg[orow * 68 + hh * 16 + cidx] = pass ? lo : hi;
                split_pack(acc[nt][2], acc[nt][3], hi, lo);
                stg[(orow + 8) * 68 + hh * 16 + cidx] = pass ? lo : hi;
            }
            __syncthreads();
            uint32_t* gp;
            if (seg == 0)      gp = pass ? g_ql : g_qh;
            else if (seg == 1) gp = pass ? g_kl : g_kh;
            else               gp = pass ? g_vl : g_vh;
            for (int i = tid; i < 2048; i += 512) {
                int px = i >> 4, j = i & 15;
                uint4 v = *(const uint4*)(stg + px * 68 + j * 4);
                *(uint4*)(gp + ((size_t)(b * 4 + (j >> 2)) * HWN + hw0 + px) * 16
                          + (j & 3) * 4) = v;
            }
        }
        __syncthreads();
    }
}

// =============================================================================
// Kernel B: FA2-style windowed top-k attention on mma.sync (occ 5, x4 ldsm).
// =============================================================================
__global__ __launch_bounds__(256, 5) void attn_kernel(const int* __restrict__ topk) {
    extern __shared__ char smb[];
    const uint32_t sbase = smem_u32(smb);
    const int tid  = threadIdx.x;
    const int lane = tid & 31;
    const int wrp  = tid >> 5;
    const int bx   = blockIdx.x;
    const int h    = bx & 3;
    const int w    = (bx >> 2) & 255;
    const int b    = bx >> 10;
    const int wy   = w >> 4, wx = w & 15;

    // ---- gather K/V hi+lo slices + Q (cp.async) ----
    {
        const int* tkw = topk + w * TOPK;
        const size_t hb = (size_t)(b * 4 + h) * HWN;
        for (int i = tid; i < 512; i += 256) {
            int row = i & 127, c = i >> 7;
            int pos = __ldg(tkw + row);
            size_t s = (hb + pos) * 16 + c * 4;
            uint32_t doff = (uint32_t)(row * 80 + c * 16);
            cp16(sbase + KH_B + doff, g_kh + s);
            cp16(sbase + KL_B + doff, g_kl + s);
            cp16(sbase + VH_B + doff, g_vh + s);
            cp16(sbase + VL_B + doff, g_vl + s);
        }
        if (tid < 64) {
            int qi = tid & 15, c = tid >> 4;
            int hw = (wy * 4 + (qi >> 2)) * HH + wx * 4 + (qi & 3);
            size_t s = (hb + hw) * 16 + c * 4;
            cp16(sbase + QH_B + qi * 80 + c * 16, g_qh + s);
            cp16(sbase + QL_B + qi * 80 + c * 16, g_ql + s);
        }
        asm volatile("cp.async.commit_group;");
        asm volatile("cp.async.wait_group 0;" ::: "memory");
    }
    __syncthreads();

    // ---- S = Q K^T (3-term bf16 split). Warp owns n-tiles 2w, 2w+1 ----
    float c0[4] = {0.f, 0.f, 0.f, 0.f};
    float c1[4] = {0.f, 0.f, 0.f, 0.f};
    {
        const uint32_t q_l = (uint32_t)((lane & 15) * 80 + (lane >> 4) * 16);
        const uint32_t k4 = (uint32_t)((wrp * 16 + (lane & 7) + (lane >> 4) * 8) * 80
                                       + ((lane >> 3) & 1) * 16);
        #pragma unroll
        for (int ks = 0; ks < 2; ks++) {
            uint32_t aqh[4], aql[4];
            ldsm4(aqh, sbase + QH_B + q_l + ks * 32);
            ldsm4(aql, sbase + QL_B + q_l + ks * 32);
            uint32_t kh4[4], kl4[4];
            ldsm4(kh4, sbase + KH_B + k4 + ks * 32);
            ldsm4(kl4, sbase + KL_B + k4 + ks * 32);
            mma_bf16(c0, aqh, kh4);     mma_bf16(c0, aqh, kl4);     mma_bf16(c0, aql, kh4);
            mma_bf16(c1, aqh, kh4 + 2); mma_bf16(c1, aqh, kl4 + 2); mma_bf16(c1, aql, kh4 + 2);
        }
    }

    float* rmaxs = (float*)(smb + RMAX_B);
    float* rsums = (float*)(smb + RSUM_B);
    const int r0 = lane >> 2;
    {
        float m0 = fmaxf(fmaxf(c0[0], c0[1]), fmaxf(c1[0], c1[1]));
        float m1 = fmaxf(fmaxf(c0[2], c0[3]), fmaxf(c1[2], c1[3]));
        m0 = fmaxf(m0, __shfl_xor_sync(0xffffffffu, m0, 1));
        m0 = fmaxf(m0, __shfl_xor_sync(0xffffffffu, m0, 2));
        m1 = fmaxf(m1, __shfl_xor_sync(0xffffffffu, m1, 1));
        m1 = fmaxf(m1, __shfl_xor_sync(0xffffffffu, m1, 2));
        if ((lane & 3) == 0) {
            rmaxs[wrp * 16 + r0]     = m0;
            rmaxs[wrp * 16 + r0 + 8] = m1;
        }
    }
    __syncthreads();

    uint32_t aph[4], apl[4];
    {
        float g0 = rmaxs[r0], g1 = rmaxs[r0 + 8];
        #pragma unroll
        for (int ww = 1; ww < 8; ww++) {
            g0 = fmaxf(g0, rmaxs[ww * 16 + r0]);
            g1 = fmaxf(g1, rmaxs[ww * 16 + r0 + 8]);
        }
        c0[0] = __expf(c0[0] - g0); c0[1] = __expf(c0[1] - g0);
        c1[0] = __expf(c1[0] - g0); c1[1] = __expf(c1[1] - g0);
        c0[2] = __expf(c0[2] - g1); c0[3] = __expf(c0[3] - g1);
        c1[2] = __expf(c1[2] - g1); c1[3] = __expf(c1[3] - g1);
        float s0 = c0[0] + c0[1] + c1[0] + c1[1];
        float s1 = c0[2] + c0[3] + c1[2] + c1[3];
        s0 += __shfl_xor_sync(0xffffffffu, s0, 1);
        s0 += __shfl_xor_sync(0xffffffffu, s0, 2);
        s1 += __shfl_xor_sync(0xffffffffu, s1, 1);
        s1 += __shfl_xor_sync(0xffffffffu, s1, 2);
        if ((lane & 3) == 0) {
            rsums[wrp * 16 + r0]     = s0;
            rsums[wrp * 16 + r0 + 8] = s1;
        }
        split_pack(c0[0], c0[1], aph[0], apl[0]);
        split_pack(c0[2], c0[3], aph[1], apl[1]);
        split_pack(c1[0], c1[1], aph[2], apl[2]);
        split_pack(c1[2], c1[3], aph[3], apl[3]);
    }
    __syncthreads();   // rsums visible; K region now dead -> O stage overlay

    // ---- PV: warp's kstep = kj 16w..16w+15; V via ldmatrix.x4.trans ----
    {
        const uint32_t v4 = (uint32_t)((wrp * 16 + (lane & 15)) * 80 + (lane >> 4) * 16);
        float* slab = (float*)smb + wrp * 640;   // 16 rows x 40 f32
        #pragma unroll
        for (int ntp = 0; ntp < 2; ntp++) {
            uint32_t vh4[4], vl4[4];
            ldsm4t(vh4, sbase + VH_B + v4 + ntp * 32);
            ldsm4t(vl4, sbase + VL_B + v4 + ntp * 32);
            float o0[4] = {0.f, 0.f, 0.f, 0.f};
            float o1[4] = {0.f, 0.f, 0.f, 0.f};
            mma_bf16(o0, aph, vh4);     mma_bf16(o0, aph, vl4);     mma_bf16(o0, apl, vh4);
            mma_bf16(o1, aph, vh4 + 2); mma_bf16(o1, aph, vl4 + 2); mma_bf16(o1, apl, vh4 + 2);
            float* sp0 = slab + r0 * 40 + (2 * ntp) * 8 + 2 * (lane & 3);
            *(float2*)sp0            = make_float2(o0[0], o0[1]);
            *(float2*)(sp0 + 8 * 40) = make_float2(o0[2], o0[3]);
            float* sp1 = sp0 + 8;
            *(float2*)sp1            = make_float2(o1[0], o1[1]);
            *(float2*)(sp1 + 8 * 40) = make_float2(o1[2], o1[3]);
        }
    }
    __syncthreads();

    // ---- reduce 8 slabs, normalize, split, store ----
    if (tid < 224) {
        int qi = tid / 14, p = tid - qi * 14;
        float o0 = 0.f, o1 = 0.f, gs = 0.f;
        #pragma unroll
        for (int ww = 0; ww < 8; ww++) {
            float2 v = *(const float2*)((const float*)smb + ww * 640 + qi * 40 + 2 * p);
            o0 += v.x; o1 += v.y;
            gs += rsums[ww * 16 + qi];
        }
        float inv = 1.0f / gs;
        uint32_t hi, lo;
        split_pack(o0 * inv, o1 * inv, hi, lo);
        int hw = (wy * 4 + (qi >> 2)) * HH + wx * 4 + (qi & 3);
        size_t a = ((size_t)b * HWN + hw) * 60 + h * 14 + p;
        g_oh[a] = hi;
        g_ol[a] = lo;
    }
}

// =============================================================================
// Kernel C: output projection via mma.sync; A and W pre-split via cp.async.
// =============================================================================
__global__ __launch_bounds__(512, 2) void proj_kernel(const float* __restrict__ bias,
                                                      float* __restrict__ out) {
    extern __shared__ char smb[];
    const uint32_t sbase = smem_u32(smb);
    const int tid = threadIdx.x;
    const int b   = blockIdx.y;
    const int hw0 = blockIdx.x * 128;

    for (int i = tid; i < 1920; i += 512) {
        int row = i / 15, j = i - row * 15;
        size_t s = ((size_t)b * HWN + hw0 + row) * 60 + j * 4;
        uint32_t doff = (uint32_t)(row * 240 + j * 16);
        cp16(sbase + AH_B + doff, g_oh + s);
        cp16(sbase + AL_B + doff, g_ol + s);
    }
    for (int i = tid; i < 1680; i += 512) {
        cp16(sbase + WH_B + i * 16, g_wh + 3 * 6720 + i * 4);
        cp16(sbase + WL_B + i * 16, g_wl + 3 * 6720 + i * 4);
    }
    asm volatile("cp.async.commit_group;");
    asm volatile("cp.async.wait_group 0;" ::: "memory");
    __syncthreads();

    const int lane = tid & 31;
    const int wid  = tid >> 5;
    const int wm   = wid & 7;
    const int wn   = wid >> 3;
    const int mrow = wm * 16;
    const int amat = lane >> 3, ar = lane & 7;
    const uint32_t a_off = (uint32_t)((mrow + ar + (amat & 1) * 8) * 240
                                      + (amat >> 1) * 16);
    const uint32_t b_lane_off = (uint32_t)((lane & 7) * 240 + ((lane >> 3) & 1) * 16);
    const int orow  = mrow + (lane >> 2);
    const int ocol0 = wn * 56 + 2 * (lane & 3);

    float acc[7][4];
    #pragma unroll
    for (int nt = 0; nt < 7; nt++)
        #pragma unroll
        for (int j = 0; j < 4; j++) acc[nt][j] = 0.0f;

    #pragma unroll
    for (int ks = 0; ks < 7; ks++) {
        uint32_t ah[4], al[4];
        ldsm4(ah, sbase + AH_B + a_off + ks * 32);
        ldsm4(al, sbase + AL_B + a_off + ks * 32);
        #pragma unroll
        for (int nt = 0; nt < 7; nt++) {
            uint32_t bh[2], bl[2];
            uint32_t boff = (uint32_t)((wn * 56 + nt * 8) * 240) + b_lane_off + ks * 32;
            ldsm2(bh, sbase + WH_B + boff);
            ldsm2(bl, sbase + WL_B + boff);
            mma_bf16(acc[nt], ah, bh);
            mma_bf16(acc[nt], ah, bl);
            mma_bf16(acc[nt], al, bh);
        }
    }
    __syncthreads();   // A region dead; reuse as transpose stage

    float* stage = (float*)smb;
    #pragma unroll
    for (int nt = 0; nt < 7; nt++) {
        int d = ocol0 + nt * 8;
        stage[d * 132 + orow]           = acc[nt][0];
        stage[(d + 1) * 132 + orow]     = acc[nt][1];
        stage[d * 132 + orow + 8]       = acc[nt][2];
        stage[(d + 1) * 132 + orow + 8] = acc[nt][3];
    }
    __syncthreads();

    for (int i = tid; i < 3584; i += 512) {
        int d = i >> 5, j = i & 31;
        float4 v = *(const float4*)(stage + d * 132 + j * 4);
        float bv = __ldg(bias + d);
        v.x += bv; v.y += bv; v.z += bv; v.w += bv;
        *(float4*)(out + ((size_t)b * CC + d) * HWN + hw0 + j * 4) = v;
    }
}

// =============================================================================
extern "C" void kernel_launch(void* const* d_in, const int* in_sizes, int n_in,
                              void* d_out, int out_size) {
    const float* x     = (const float*)d_in[0];
    const float* Wqkv  = (const float*)d_in[1];
    const float* Wproj = (const float*)d_in[2];
    const float* bproj = (const float*)d_in[3];
    const int*   topk  = (const int*)d_in[4];
    float* out = (float*)d_out;

    cudaFuncSetAttribute(qkv_kernel,  cudaFuncAttributeMaxDynamicSharedMemorySize, MMA_SMEM_B);
    cudaFuncSetAttribute(attn_kernel, cudaFuncAttributeMaxDynamicSharedMemorySize, ATTN_SMEM_B);
    cudaFuncSetAttribute(proj_kernel, cudaFuncAttributeMaxDynamicSharedMemorySize, MMA_SMEM_B);

    prep_kernel<<<4, 256>>>(Wqkv, Wproj);
    qkv_kernel<<<dim3(32, 16), 512, MMA_SMEM_B>>>(x);
    attn_kernel<<<BB * NWIN * NHEAD, 256, ATTN_SMEM_B>>>(topk);
    proj_kernel<<<dim3(32, 16), 512, MMA_SMEM_B>>>(bproj, out);
}

// round 15
// speedup vs baseline: 3.3256x; 1.2417x over previous
#include <cuda_runtime.h>
#include <cuda_bf16.h>
#include <cstdint>

#define BB    16
#define CC    112
#define HH    64
#define HWN   4096
#define NHEAD 4
#define HD    28
#define NWIN  256
#define TOPK  128
#define SCALE 0.18898223650461363f   // 28^-0.5

// ---- mma (qkv/proj) smem byte offsets: 240B rows (15x16B odd, conflict-free)
#define AH_B   0
#define AL_B   30720
#define WH_B   61440
#define WL_B   88320
#define MMA_SMEM_B 115200
// qkv epilogue stage overlays WH/WL: 128 rows x 68 u32 = 34816B

// ---- attn smem byte offsets: 80B rows (5x16B odd, ldsm conflict-free) ----
#define KH_B    0        // 128 x 80B = 10240
#define KL_B    10240
#define VH_B    20480
#define VL_B    30720
#define QH_B    40960    // 16 x 80B = 1280
#define QL_B    42240
#define RMAX_B  43520    // 8 warps x 16 f32
#define RSUM_B  44032
#define ATTN_SMEM_B 44544
// O stage overlays KH/KL: 8 slabs x (16 rows x 40 f32) = 20480B exactly

// ---------------- scratch (device globals; no allocation allowed) ------------
__device__ __align__(16) uint32_t g_qh[BB * NHEAD * HWN * 16];
__device__ __align__(16) uint32_t g_ql[BB * NHEAD * HWN * 16];
__device__ __align__(16) uint32_t g_kh[BB * NHEAD * HWN * 16];
__device__ __align__(16) uint32_t g_kl[BB * NHEAD * HWN * 16];
__device__ __align__(16) uint32_t g_vh[BB * NHEAD * HWN * 16];
__device__ __align__(16) uint32_t g_vl[BB * NHEAD * HWN * 16];
__device__ __align__(16) uint32_t g_oh[BB * HWN * 60];
__device__ __align__(16) uint32_t g_ol[BB * HWN * 60];
// pre-split weights: segs 0..2 = Wqkv (SCALE folded into seg 0), seg 3 = Wproj
__device__ __align__(16) uint32_t g_wh[4 * CC * 60];
__device__ __align__(16) uint32_t g_wl[4 * CC * 60];

__device__ __forceinline__ uint32_t smem_u32(const void* p) {
    uint32_t a;
    asm("{ .reg .u64 t; cvta.to.shared.u64 t, %1; cvt.u32.u64 %0, t; }" : "=r"(a) : "l"(p));
    return a;
}
__device__ __forceinline__ void cp16(uint32_t dst, const void* src) {
    asm volatile("cp.async.cg.shared.global [%0], [%1], 16;" :: "r"(dst), "l"(src) : "memory");
}
__device__ __forceinline__ void ldsm4(uint32_t* r, uint32_t a) {
    asm volatile("ldmatrix.sync.aligned.m8n8.x4.shared.b16 {%0,%1,%2,%3}, [%4];"
                 : "=r"(r[0]), "=r"(r[1]), "=r"(r[2]), "=r"(r[3]) : "r"(a));
}
__device__ __forceinline__ void ldsm2(uint32_t* r, uint32_t a) {
    asm volatile("ldmatrix.sync.aligned.m8n8.x2.shared.b16 {%0,%1}, [%2];"
                 : "=r"(r[0]), "=r"(r[1]) : "r"(a));
}
__device__ __forceinline__ void ldsm4t(uint32_t* r, uint32_t a) {
    asm volatile("ldmatrix.sync.aligned.m8n8.x4.trans.shared.b16 {%0,%1,%2,%3}, [%4];"
                 : "=r"(r[0]), "=r"(r[1]), "=r"(r[2]), "=r"(r[3]) : "r"(a));
}
__device__ __forceinline__ void mma_bf16(float* d, const uint32_t* a, const uint32_t* b) {
    asm volatile("mma.sync.aligned.m16n8k16.row.col.f32.bf16.bf16.f32 "
                 "{%0,%1,%2,%3}, {%4,%5,%6,%7}, {%8,%9}, {%0,%1,%2,%3};"
                 : "+f"(d[0]), "+f"(d[1]), "+f"(d[2]), "+f"(d[3])
                 : "r"(a[0]), "r"(a[1]), "r"(a[2]), "r"(a[3]), "r"(b[0]), "r"(b[1]));
}
__device__ __forceinline__ void split_pack(float a0, float a1, uint32_t& hi, uint32_t& lo) {
    __nv_bfloat16 h0 = __float2bfloat16(a0);
    __nv_bfloat16 h1 = __float2bfloat16(a1);
    __nv_bfloat16 l0 = __float2bfloat16(a0 - __bfloat162float(h0));
    __nv_bfloat16 l1 = __float2bfloat16(a1 - __bfloat162float(h1));
    hi = ((uint32_t)__bfloat16_as_ushort(h1) << 16) | __bfloat16_as_ushort(h0);
    lo = ((uint32_t)__bfloat16_as_ushort(l1) << 16) | __bfloat16_as_ushort(l0);
}

// =============================================================================
// Kernel 0: one-shot weight pre-split. Block = seg (0..2 Wqkv, 3 Wproj).
// =============================================================================
__global__ __launch_bounds__(256) void prep_kernel(const float* __restrict__ Wqkv,
                                                   const float* __restrict__ Wproj) {
    const int seg = blockIdx.x;
    const float* src = (seg < 3) ? (Wqkv + (size_t)seg * CC * CC) : Wproj;
    const float s = (seg == 0) ? SCALE : 1.0f;
    const int base = seg * 6720;
    for (int i = threadIdx.x; i < 6272; i += 256) {
        int d = i / 56, cp = i - d * 56;
        float2 wv = *(const float2*)(src + (size_t)d * CC + cp * 2);
        uint32_t hi, lo;
        split_pack(wv.x * s, wv.y * s, hi, lo);
        g_wh[base + d * 60 + cp] = hi;
        g_wl[base + d * 60 + cp] = lo;
    }
    for (int i = threadIdx.x; i < 448; i += 256) {   // zero tail cols 56..59
        int d = i >> 2;
        g_wh[base + d * 60 + 56 + (i & 3)] = 0;
        g_wl[base + d * 60 + 56 + (i & 3)] = 0;
    }
}

// =============================================================================
// Kernel A: QKV projection via mma.sync bf16-split; W tiles via cp.async.
// =============================================================================
__global__ __launch_bounds__(512, 2) void qkv_kernel(const float* __restrict__ x) {
    extern __shared__ char smb[];
    float* xs = (float*)(smb + WH_B);
    const uint32_t sbase = smem_u32(smb);

    const int tid = threadIdx.x;
    const int b   = blockIdx.y;
    const int hw0 = blockIdx.x * 128;

    // A conversion (x tile, transposed to [px][ch]) in two 56-channel chunks
    #pragma unroll
    for (int chunk = 0; chunk < 2; chunk++) {
        for (int i = tid; i < 1792; i += 512) {
            int c = i >> 5, p4 = i & 31;
            ((float4*)xs)[i] =
                ((const float4*)(x + (b * CC + chunk * 56 + c) * HWN + hw0))[p4];
        }
        __syncthreads();
        for (int i = tid; i < 3584; i += 512) {
            int px = i & 127, cp = i >> 7;
            uint32_t hi, lo;
            split_pack(xs[(cp * 2) * 128 + px], xs[(cp * 2 + 1) * 128 + px], hi, lo);
            int idx = px * 60 + chunk * 28 + cp;
            ((uint32_t*)(smb + AH_B))[idx] = hi;
            ((uint32_t*)(smb + AL_B))[idx] = lo;
        }
        __syncthreads();
    }

    const int lane = tid & 31;
    const int wid  = tid >> 5;
    const int wm   = wid & 7;
    const int wn   = wid >> 3;
    const int mrow = wm * 16;

    const int amat = lane >> 3, ar = lane & 7;
    const uint32_t a_off = (uint32_t)((mrow + ar + (amat & 1) * 8) * 240
                                      + (amat >> 1) * 16);
    const uint32_t b_lane_off = (uint32_t)((lane & 7) * 240 + ((lane >> 3) & 1) * 16);

    const int orow  = mrow + (lane >> 2);
    const int ocol0 = wn * 56 + 2 * (lane & 3);

    for (int seg = 0; seg < 3; seg++) {
        // ---- load pre-split W tiles (linear cp.async) ----
        for (int i = tid; i < 1680; i += 512) {
            cp16(sbase + WH_B + i * 16, g_wh + seg * 6720 + i * 4);
            cp16(sbase + WL_B + i * 16, g_wl + seg * 6720 + i * 4);
        }
        asm volatile("cp.async.commit_group;");
        asm volatile("cp.async.wait_group 0;" ::: "memory");
        __syncthreads();

        float acc[7][4];
        #pragma unroll
        for (int nt = 0; nt < 7; nt++)
            #pragma unroll
            for (int j = 0; j < 4; j++) acc[nt][j] = 0.0f;

        #pragma unroll
        for (int ks = 0; ks < 7; ks++) {
            uint32_t ah[4], al[4];
            ldsm4(ah, sbase + AH_B + a_off + ks * 32);
            ldsm4(al, sbase + AL_B + a_off + ks * 32);
            #pragma unroll
            for (int nt = 0; nt < 7; nt++) {
                uint32_t bh[2], bl[2];
                uint32_t boff = (uint32_t)((wn * 56 + nt * 8) * 240) + b_lane_off + ks * 32;
                ldsm2(bh, sbase + WH_B + boff);
                ldsm2(bl, sbase + WL_B + boff);
                mma_bf16(acc[nt], ah, bh);
                mma_bf16(acc[nt], ah, bl);
                mma_bf16(acc[nt], al, bh);
            }
        }

        // ---- epilogue: two passes (hi, lo) through stride-68 smem stage ----
        uint32_t* stg = (uint32_t*)(smb + WH_B);   // W dead after MMA loop
        #pragma unroll
        for (int pass = 0; pass < 2; pass++) {
            __syncthreads();
            for (int i = tid; i < 1024; i += 512) {
                int px = i >> 3, hh = (i >> 1) & 3, pc = 14 + (i & 1);
                stg[px * 68 + hh * 16 + pc] = 0;
            }
            #pragma unroll
            for (int nt = 0; nt < 7; nt++) {
                int d = ocol0 + nt * 8;
                int hh = d / 28;
                int cidx = (d - hh * 28) >> 1;
                uint32_t hi, lo;
                split_pack(acc[nt][0], acc[nt][1], hi, lo);
                stg[orow * 68 + hh * 16 + cidx] = pass ? lo : hi;
                split_pack(acc[nt][2], acc[nt][3], hi, lo);
                stg[(orow + 8) * 68 + hh * 16 + cidx] = pass ? lo : hi;
            }
            __syncthreads();
            uint32_t* gp;
            if (seg == 0)      gp = pass ? g_ql : g_qh;
            else if (seg == 1) gp = pass ? g_kl : g_kh;
            else               gp = pass ? g_vl : g_vh;
            for (int i = tid; i < 2048; i += 512) {
                int px = i >> 4, j = i & 15;
                uint4 v = *(const uint4*)(stg + px * 68 + j * 4);
                *(uint4*)(gp + ((size_t)(b * 4 + (j >> 2)) * HWN + hw0 + px) * 16
                          + (j & 3) * 4) = v;
            }
        }
        __syncthreads();
    }
}

// =============================================================================
// Kernel B: FA2-style windowed top-k attention on mma.sync (occ 5).
// Gather remapped: lanes 0-3 read 64 contiguous bytes of one row (full L2
// sector utilization; round-14 layout wasted half of every 32B sector).
// =============================================================================
__global__ __launch_bounds__(256, 5) void attn_kernel(const int* __restrict__ topk) {
    extern __shared__ char smb[];
    const uint32_t sbase = smem_u32(smb);
    const int tid  = threadIdx.x;
    const int lane = tid & 31;
    const int wrp  = tid >> 5;
    const int bx   = blockIdx.x;
    const int h    = bx & 3;
    const int w    = (bx >> 2) & 255;
    const int b    = bx >> 10;
    const int wy   = w >> 4, wx = w & 15;

    // ---- gather K/V hi+lo slices + Q (cp.async, sector-coalesced) ----
    {
        const int* tkw = topk + w * TOPK;
        const size_t hb = (size_t)(b * 4 + h) * HWN;
        for (int i = tid; i < 512; i += 256) {
            int row = i >> 2, c = i & 3;          // lanes 0-3: same row, 64B run
            int pos = __ldg(tkw + row);
            size_t s = (hb + pos) * 16 + c * 4;
            uint32_t doff = (uint32_t)(row * 80 + c * 16);
            cp16(sbase + KH_B + doff, g_kh + s);
            cp16(sbase + KL_B + doff, g_kl + s);
            cp16(sbase + VH_B + doff, g_vh + s);
            cp16(sbase + VL_B + doff, g_vl + s);
        }
        if (tid < 64) {
            int qi = tid >> 2, c = tid & 3;       // same remap for Q
            int hw = (wy * 4 + (qi >> 2)) * HH + wx * 4 + (qi & 3);
            size_t s = (hb + hw) * 16 + c * 4;
            cp16(sbase + QH_B + qi * 80 + c * 16, g_qh + s);
            cp16(sbase + QL_B + qi * 80 + c * 16, g_ql + s);
        }
        asm volatile("cp.async.commit_group;");
        asm volatile("cp.async.wait_group 0;" ::: "memory");
    }
    __syncthreads();

    // ---- S = Q K^T (3-term bf16 split). Warp owns n-tiles 2w, 2w+1 ----
    float c0[4] = {0.f, 0.f, 0.f, 0.f};
    float c1[4] = {0.f, 0.f, 0.f, 0.f};
    {
        const uint32_t q_l = (uint32_t)((lane & 15) * 80 + (lane >> 4) * 16);
        const uint32_t k4 = (uint32_t)((wrp * 16 + (lane & 7) + (lane >> 4) * 8) * 80
                                       + ((lane >> 3) & 1) * 16);
        #pragma unroll
        for (int ks = 0; ks < 2; ks++) {
            uint32_t aqh[4], aql[4];
            ldsm4(aqh, sbase + QH_B + q_l + ks * 32);
            ldsm4(aql, sbase + QL_B + q_l + ks * 32);
            uint32_t kh4[4], kl4[4];
            ldsm4(kh4, sbase + KH_B + k4 + ks * 32);
            ldsm4(kl4, sbase + KL_B + k4 + ks * 32);
            mma_bf16(c0, aqh, kh4);     mma_bf16(c0, aqh, kl4);     mma_bf16(c0, aql, kh4);
            mma_bf16(c1, aqh, kh4 + 2); mma_bf16(c1, aqh, kl4 + 2); mma_bf16(c1, aql, kh4 + 2);
        }
    }

    float* rmaxs = (float*)(smb + RMAX_B);
    float* rsums = (float*)(smb + RSUM_B);
    const int r0 = lane >> 2;
    {
        float m0 = fmaxf(fmaxf(c0[0], c0[1]), fmaxf(c1[0], c1[1]));
        float m1 = fmaxf(fmaxf(c0[2], c0[3]), fmaxf(c1[2], c1[3]));
        m0 = fmaxf(m0, __shfl_xor_sync(0xffffffffu, m0, 1));
        m0 = fmaxf(m0, __shfl_xor_sync(0xffffffffu, m0, 2));
        m1 = fmaxf(m1, __shfl_xor_sync(0xffffffffu, m1, 1));
        m1 = fmaxf(m1, __shfl_xor_sync(0xffffffffu, m1, 2));
        if ((lane & 3) == 0) {
            rmaxs[wrp * 16 + r0]     = m0;
            rmaxs[wrp * 16 + r0 + 8] = m1;
        }
    }
    __syncthreads();

    uint32_t aph[4], apl[4];
    {
        float g0 = rmaxs[r0], g1 = rmaxs[r0 + 8];
        #pragma unroll
        for (int ww = 1; ww < 8; ww++) {
            g0 = fmaxf(g0, rmaxs[ww * 16 + r0]);
            g1 = fmaxf(g1, rmaxs[ww * 16 + r0 + 8]);
        }
        c0[0] = __expf(c0[0] - g0); c0[1] = __expf(c0[1] - g0);
        c1[0] = __expf(c1[0] - g0); c1[1] = __expf(c1[1] - g0);
        c0[2] = __expf(c0[2] - g1); c0[3] = __expf(c0[3] - g1);
        c1[2] = __expf(c1[2] - g1); c1[3] = __expf(c1[3] - g1);
        float s0 = c0[0] + c0[1] + c1[0] + c1[1];
        float s1 = c0[2] + c0[3] + c1[2] + c1[3];
        s0 += __shfl_xor_sync(0xffffffffu, s0, 1);
        s0 += __shfl_xor_sync(0xffffffffu, s0, 2);
        s1 += __shfl_xor_sync(0xffffffffu, s1, 1);
        s1 += __shfl_xor_sync(0xffffffffu, s1, 2);
        if ((lane & 3) == 0) {
            rsums[wrp * 16 + r0]     = s0;
            rsums[wrp * 16 + r0 + 8] = s1;
        }
        split_pack(c0[0], c0[1], aph[0], apl[0]);
        split_pack(c0[2], c0[3], aph[1], apl[1]);
        split_pack(c1[0], c1[1], aph[2], apl[2]);
        split_pack(c1[2], c1[3], aph[3], apl[3]);
    }
    __syncthreads();   // rsums visible; K region now dead -> O stage overlay

    // ---- PV: warp's kstep = kj 16w..16w+15; V via ldmatrix.x4.trans ----
    {
        const uint32_t v4 = (uint32_t)((wrp * 16 + (lane & 15)) * 80 + (lane >> 4) * 16);
        float* slab = (float*)smb + wrp * 640;   // 16 rows x 40 f32
        #pragma unroll
        for (int ntp = 0; ntp < 2; ntp++) {
            uint32_t vh4[4], vl4[4];
            ldsm4t(vh4, sbase + VH_B + v4 + ntp * 32);
            ldsm4t(vl4, sbase + VL_B + v4 + ntp * 32);
            float o0[4] = {0.f, 0.f, 0.f, 0.f};
            float o1[4] = {0.f, 0.f, 0.f, 0.f};
            mma_bf16(o0, aph, vh4);     mma_bf16(o0, aph, vl4);     mma_bf16(o0, apl, vh4);
            mma_bf16(o1, aph, vh4 + 2); mma_bf16(o1, aph, vl4 + 2); mma_bf16(o1, apl, vh4 + 2);
            float* sp0 = slab + r0 * 40 + (2 * ntp) * 8 + 2 * (lane & 3);
            *(float2*)sp0            = make_float2(o0[0], o0[1]);
            *(float2*)(sp0 + 8 * 40) = make_float2(o0[2], o0[3]);
            float* sp1 = sp0 + 8;
            *(float2*)sp1            = make_float2(o1[0], o1[1]);
            *(float2*)(sp1 + 8 * 40) = make_float2(o1[2], o1[3]);
        }
    }
    __syncthreads();

    // ---- reduce 8 slabs, normalize, split, store ----
    if (tid < 224) {
        int qi = tid / 14, p = tid - qi * 14;
        float o0 = 0.f, o1 = 0.f, gs = 0.f;
        #pragma unroll
        for (int ww = 0; ww < 8; ww++) {
            float2 v = *(const float2*)((const float*)smb + ww * 640 + qi * 40 + 2 * p);
            o0 += v.x; o1 += v.y;
            gs += rsums[ww * 16 + qi];
        }
        float inv = 1.0f / gs;
        uint32_t hi, lo;
        split_pack(o0 * inv, o1 * inv, hi, lo);
        int hw = (wy * 4 + (qi >> 2)) * HH + wx * 4 + (qi & 3);
        size_t a = ((size_t)b * HWN + hw) * 60 + h * 14 + p;
        g_oh[a] = hi;
        g_ol[a] = lo;
    }
}

// =============================================================================
// Kernel C: output projection via mma.sync; A and W pre-split via cp.async.
// =============================================================================
__global__ __launch_bounds__(512, 2) void proj_kernel(const float* __restrict__ bias,
                                                      float* __restrict__ out) {
    extern __shared__ char smb[];
    const uint32_t sbase = smem_u32(smb);
    const int tid = threadIdx.x;
    const int b   = blockIdx.y;
    const int hw0 = blockIdx.x * 128;

    for (int i = tid; i < 1920; i += 512) {
        int row = i / 15, j = i - row * 15;
        size_t s = ((size_t)b * HWN + hw0 + row) * 60 + j * 4;
        uint32_t doff = (uint32_t)(row * 240 + j * 16);
        cp16(sbase + AH_B + doff, g_oh + s);
        cp16(sbase + AL_B + doff, g_ol + s);
    }
    for (int i = tid; i < 1680; i += 512) {
        cp16(sbase + WH_B + i * 16, g_wh + 3 * 6720 + i * 4);
        cp16(sbase + WL_B + i * 16, g_wl + 3 * 6720 + i * 4);
    }
    asm volatile("cp.async.commit_group;");
    asm volatile("cp.async.wait_group 0;" ::: "memory");
    __syncthreads();

    const int lane = tid & 31;
    const int wid  = tid >> 5;
    const int wm   = wid & 7;
    const int wn   = wid >> 3;
    const int mrow = wm * 16;
    const int amat = lane >> 3, ar = lane & 7;
    const uint32_t a_off = (uint32_t)((mrow + ar + (amat & 1) * 8) * 240
                                      + (amat >> 1) * 16);
    const uint32_t b_lane_off = (uint32_t)((lane & 7) * 240 + ((lane >> 3) & 1) * 16);
    const int orow  = mrow + (lane >> 2);
    const int ocol0 = wn * 56 + 2 * (lane & 3);

    float acc[7][4];
    #pragma unroll
    for (int nt = 0; nt < 7; nt++)
        #pragma unroll
        for (int j = 0; j < 4; j++) acc[nt][j] = 0.0f;

    #pragma unroll
    for (int ks = 0; ks < 7; ks++) {
        uint32_t ah[4], al[4];
        ldsm4(ah, sbase + AH_B + a_off + ks * 32);
        ldsm4(al, sbase + AL_B + a_off + ks * 32);
        #pragma unroll
        for (int nt = 0; nt < 7; nt++) {
            uint32_t bh[2], bl[2];
            uint32_t boff = (uint32_t)((wn * 56 + nt * 8) * 240) + b_lane_off + ks * 32;
            ldsm2(bh, sbase + WH_B + boff);
            ldsm2(bl, sbase + WL_B + boff);
            mma_bf16(acc[nt], ah, bh);
            mma_bf16(acc[nt], ah, bl);
            mma_bf16(acc[nt], al, bh);
        }
    }
    __syncthreads();   // A region dead; reuse as transpose stage

    float* stage = (float*)smb;
    #pragma unroll
    for (int nt = 0; nt < 7; nt++) {
        int d = ocol0 + nt * 8;
        stage[d * 132 + orow]           = acc[nt][0];
        stage[(d + 1) * 132 + orow]     = acc[nt][1];
        stage[d * 132 + orow + 8]       = acc[nt][2];
        stage[(d + 1) * 132 + orow + 8] = acc[nt][3];
    }
    __syncthreads();

    for (int i = tid; i < 3584; i += 512) {
        int d = i >> 5, j = i & 31;
        float4 v = *(const float4*)(stage + d * 132 + j * 4);
        float bv = __ldg(bias + d);
        v.x += bv; v.y += bv; v.z += bv; v.w += bv;
        *(float4*)(out + ((size_t)b * CC + d) * HWN + hw0 + j * 4) = v;
    }
}

// =============================================================================
extern "C" void kernel_launch(void* const* d_in, const int* in_sizes, int n_in,
                              void* d_out, int out_size) {
    const float* x     = (const float*)d_in[0];
    const float* Wqkv  = (const float*)d_in[1];
    const float* Wproj = (const float*)d_in[2];
    const float* bproj = (const float*)d_in[3];
    const int*   topk  = (const int*)d_in[4];
    float* out = (float*)d_out;

    cudaFuncSetAttribute(qkv_kernel,  cudaFuncAttributeMaxDynamicSharedMemorySize, MMA_SMEM_B);
    cudaFuncSetAttribute(attn_kernel, cudaFuncAttributeMaxDynamicSharedMemorySize, ATTN_SMEM_B);
    cudaFuncSetAttribute(proj_kernel, cudaFuncAttributeMaxDynamicSharedMemorySize, MMA_SMEM_B);

    prep_kernel<<<4, 256>>>(Wqkv, Wproj);
    qkv_kernel<<<dim3(32, 16), 512, MMA_SMEM_B>>>(x);
    attn_kernel<<<BB * NWIN * NHEAD, 256, ATTN_SMEM_B>>>(topk);
    proj_kernel<<<dim3(32, 16), 512, MMA_SMEM_B>>>(bproj, out);
}

// round 16
// speedup vs baseline: 3.7017x; 1.1131x over previous
#include <cuda_runtime.h>
#include <cuda_bf16.h>
#include <cstdint>

#define BB    16
#define CC    112
#define HH    64
#define HWN   4096
#define NHEAD 4
#define HD    28
#define NWIN  256
#define TOPK  128
#define SCALE 0.18898223650461363f   // 28^-0.5

// ---- mma (qkv/proj) smem byte offsets: 240B rows (15x16B odd, conflict-free)
#define AH_B   0
#define AL_B   30720
#define WH_B   61440
#define WL_B   88320
#define MMA_SMEM_B 115200
// qkv epilogue stage overlays WH/WL: 128 rows x 68 u32 = 34816B

// ---- attn smem byte offsets: 80B rows (5x16B odd, ldsm conflict-free) ----
// KL region is no longer loaded (Q/K are hi-only now) but stays allocated:
// the O-slab overlay uses KH+KL = 20480B exactly, as before.
#define KH_B    0        // 128 x 80B = 10240
#define KL_B    10240    // slab-only region
#define VH_B    20480
#define VL_B    30720
#define QH_B    40960    // 16 x 80B = 1280
#define QL_B    42240    // unused (kept for layout stability)
#define RMAX_B  43520    // 8 warps x 16 f32
#define RSUM_B  44032
#define ATTN_SMEM_B 44544

// ---------------- scratch (device globals; no allocation allowed) ------------
__device__ __align__(16) uint32_t g_qh[BB * NHEAD * HWN * 16];
__device__ __align__(16) uint32_t g_kh[BB * NHEAD * HWN * 16];
__device__ __align__(16) uint32_t g_vh[BB * NHEAD * HWN * 16];
__device__ __align__(16) uint32_t g_vl[BB * NHEAD * HWN * 16];
__device__ __align__(16) uint32_t g_oh[BB * HWN * 60];
__device__ __align__(16) uint32_t g_ol[BB * HWN * 60];
// pre-split weights: segs 0..2 = Wqkv (SCALE folded into seg 0), seg 3 = Wproj
__device__ __align__(16) uint32_t g_wh[4 * CC * 60];
__device__ __align__(16) uint32_t g_wl[4 * CC * 60];

__device__ __forceinline__ uint32_t smem_u32(const void* p) {
    uint32_t a;
    asm("{ .reg .u64 t; cvta.to.shared.u64 t, %1; cvt.u32.u64 %0, t; }" : "=r"(a) : "l"(p));
    return a;
}
__device__ __forceinline__ void cp16(uint32_t dst, const void* src) {
    asm volatile("cp.async.cg.shared.global [%0], [%1], 16;" :: "r"(dst), "l"(src) : "memory");
}
__device__ __forceinline__ void ldsm4(uint32_t* r, uint32_t a) {
    asm volatile("ldmatrix.sync.aligned.m8n8.x4.shared.b16 {%0,%1,%2,%3}, [%4];"
                 : "=r"(r[0]), "=r"(r[1]), "=r"(r[2]), "=r"(r[3]) : "r"(a));
}
__device__ __forceinline__ void ldsm2(uint32_t* r, uint32_t a) {
    asm volatile("ldmatrix.sync.aligned.m8n8.x2.shared.b16 {%0,%1}, [%2];"
                 : "=r"(r[0]), "=r"(r[1]) : "r"(a));
}
__device__ __forceinline__ void ldsm4t(uint32_t* r, uint32_t a) {
    asm volatile("ldmatrix.sync.aligned.m8n8.x4.trans.shared.b16 {%0,%1,%2,%3}, [%4];"
                 : "=r"(r[0]), "=r"(r[1]), "=r"(r[2]), "=r"(r[3]) : "r"(a));
}
__device__ __forceinline__ void mma_bf16(float* d, const uint32_t* a, const uint32_t* b) {
    asm volatile("mma.sync.aligned.m16n8k16.row.col.f32.bf16.bf16.f32 "
                 "{%0,%1,%2,%3}, {%4,%5,%6,%7}, {%8,%9}, {%0,%1,%2,%3};"
                 : "+f"(d[0]), "+f"(d[1]), "+f"(d[2]), "+f"(d[3])
                 : "r"(a[0]), "r"(a[1]), "r"(a[2]), "r"(a[3]), "r"(b[0]), "r"(b[1]));
}
__device__ __forceinline__ void split_pack(float a0, float a1, uint32_t& hi, uint32_t& lo) {
    __nv_bfloat16 h0 = __float2bfloat16(a0);
    __nv_bfloat16 h1 = __float2bfloat16(a1);
    __nv_bfloat16 l0 = __float2bfloat16(a0 - __bfloat162float(h0));
    __nv_bfloat16 l1 = __float2bfloat16(a1 - __bfloat162float(h1));
    hi = ((uint32_t)__bfloat16_as_ushort(h1) << 16) | __bfloat16_as_ushort(h0);
    lo = ((uint32_t)__bfloat16_as_ushort(l1) << 16) | __bfloat16_as_ushort(l0);
}

// =============================================================================
// Kernel 0: one-shot weight pre-split. Block = seg (0..2 Wqkv, 3 Wproj).
// =============================================================================
__global__ __launch_bounds__(256) void prep_kernel(const float* __restrict__ Wqkv,
                                                   const float* __restrict__ Wproj) {
    const int seg = blockIdx.x;
    const float* src = (seg < 3) ? (Wqkv + (size_t)seg * CC * CC) : Wproj;
    const float s = (seg == 0) ? SCALE : 1.0f;
    const int base = seg * 6720;
    for (int i = threadIdx.x; i < 6272; i += 256) {
        int d = i / 56, cp = i - d * 56;
        float2 wv = *(const float2*)(src + (size_t)d * CC + cp * 2);
        uint32_t hi, lo;
        split_pack(wv.x * s, wv.y * s, hi, lo);
        g_wh[base + d * 60 + cp] = hi;
        g_wl[base + d * 60 + cp] = lo;
    }
    for (int i = threadIdx.x; i < 448; i += 256) {   // zero tail cols 56..59
        int d = i >> 2;
        g_wh[base + d * 60 + 56 + (i & 3)] = 0;
        g_wl[base + d * 60 + 56 + (i & 3)] = 0;
    }
}

// =============================================================================
// Kernel A: QKV projection via mma.sync bf16-split; W tiles via cp.async.
// q/k segs write ONLY the hi plane (single epilogue pass); v writes hi+lo.
// =============================================================================
__global__ __launch_bounds__(512, 2) void qkv_kernel(const float* __restrict__ x) {
    extern __shared__ char smb[];
    float* xs = (float*)(smb + WH_B);
    const uint32_t sbase = smem_u32(smb);

    const int tid = threadIdx.x;
    const int b   = blockIdx.y;
    const int hw0 = blockIdx.x * 128;

    // A conversion (x tile, transposed to [px][ch]) in two 56-channel chunks
    #pragma unroll
    for (int chunk = 0; chunk < 2; chunk++) {
        for (int i = tid; i < 1792; i += 512) {
            int c = i >> 5, p4 = i & 31;
            ((float4*)xs)[i] =
                ((const float4*)(x + (b * CC + chunk * 56 + c) * HWN + hw0))[p4];
        }
        __syncthreads();
        for (int i = tid; i < 3584; i += 512) {
            int px = i & 127, cp = i >> 7;
            uint32_t hi, lo;
            split_pack(xs[(cp * 2) * 128 + px], xs[(cp * 2 + 1) * 128 + px], hi, lo);
            int idx = px * 60 + chunk * 28 + cp;
            ((uint32_t*)(smb + AH_B))[idx] = hi;
            ((uint32_t*)(smb + AL_B))[idx] = lo;
        }
        __syncthreads();
    }

    const int lane = tid & 31;
    const int wid  = tid >> 5;
    const int wm   = wid & 7;
    const int wn   = wid >> 3;
    const int mrow = wm * 16;

    const int amat = lane >> 3, ar = lane & 7;
    const uint32_t a_off = (uint32_t)((mrow + ar + (amat & 1) * 8) * 240
                                      + (amat >> 1) * 16);
    const uint32_t b_lane_off = (uint32_t)((lane & 7) * 240 + ((lane >> 3) & 1) * 16);

    const int orow  = mrow + (lane >> 2);
    const int ocol0 = wn * 56 + 2 * (lane & 3);

    for (int seg = 0; seg < 3; seg++) {
        // ---- load pre-split W tiles (linear cp.async) ----
        for (int i = tid; i < 1680; i += 512) {
            cp16(sbase + WH_B + i * 16, g_wh + seg * 6720 + i * 4);
            cp16(sbase + WL_B + i * 16, g_wl + seg * 6720 + i * 4);
        }
        asm volatile("cp.async.commit_group;");
        asm volatile("cp.async.wait_group 0;" ::: "memory");
        __syncthreads();

        float acc[7][4];
        #pragma unroll
        for (int nt = 0; nt < 7; nt++)
            #pragma unroll
            for (int j = 0; j < 4; j++) acc[nt][j] = 0.0f;

        #pragma unroll
        for (int ks = 0; ks < 7; ks++) {
            uint32_t ah[4], al[4];
            ldsm4(ah, sbase + AH_B + a_off + ks * 32);
            ldsm4(al, sbase + AL_B + a_off + ks * 32);
            #pragma unroll
            for (int nt = 0; nt < 7; nt++) {
                uint32_t bh[2], bl[2];
                uint32_t boff = (uint32_t)((wn * 56 + nt * 8) * 240) + b_lane_off + ks * 32;
                ldsm2(bh, sbase + WH_B + boff);
                ldsm2(bl, sbase + WL_B + boff);
                mma_bf16(acc[nt], ah, bh);
                mma_bf16(acc[nt], ah, bl);
                mma_bf16(acc[nt], al, bh);
            }
        }

        // ---- epilogue: q/k = hi only (1 pass); v = hi+lo (2 passes) ----
        uint32_t* stg = (uint32_t*)(smb + WH_B);   // W dead after MMA loop
        const int npass = (seg == 2) ? 2 : 1;
        for (int pass = 0; pass < npass; pass++) {
            __syncthreads();
            for (int i = tid; i < 1024; i += 512) {
                int px = i >> 3, hh = (i >> 1) & 3, pc = 14 + (i & 1);
                stg[px * 68 + hh * 16 + pc] = 0;
            }
            #pragma unroll
            for (int nt = 0; nt < 7; nt++) {
                int d = ocol0 + nt * 8;
                int hh = d / 28;
                int cidx = (d - hh * 28) >> 1;
                uint32_t hi, lo;
                split_pack(acc[nt][0], acc[nt][1], hi, lo);
                stg[orow * 68 + hh * 16 + cidx] = pass ? lo : hi;
                split_pack(acc[nt][2], acc[nt][3], hi, lo);
                stg[(orow + 8) * 68 + hh * 16 + cidx] = pass ? lo : hi;
            }
            __syncthreads();
            uint32_t* gp;
            if (seg == 0)      gp = g_qh;
            else if (seg == 1) gp = g_kh;
            else               gp = pass ? g_vl : g_vh;
            for (int i = tid; i < 2048; i += 512) {
                int px = i >> 4, j = i & 15;
                uint4 v = *(const uint4*)(stg + px * 68 + j * 4);
                *(uint4*)(gp + ((size_t)(b * 4 + (j >> 2)) * HWN + hw0 + px) * 16
                          + (j & 3) * 4) = v;
            }
        }
        __syncthreads();
    }
}

// =============================================================================
// Kernel B: FA2-style windowed top-k attention on mma.sync (occ 5).
// Q/K hi-only (S = Qh*Kh, 1 term); P and V remain bf16-split.
// =============================================================================
__global__ __launch_bounds__(256, 5) void attn_kernel(const int* __restrict__ topk) {
    extern __shared__ char smb[];
    const uint32_t sbase = smem_u32(smb);
    const int tid  = threadIdx.x;
    const int lane = tid & 31;
    const int wrp  = tid >> 5;
    const int bx   = blockIdx.x;
    const int h    = bx & 3;
    const int w    = (bx >> 2) & 255;
    const int b    = bx >> 10;
    const int wy   = w >> 4, wx = w & 15;

    // ---- gather K hi + V hi/lo + Q hi (cp.async, sector-coalesced) ----
    {
        const int* tkw = topk + w * TOPK;
        const size_t hb = (size_t)(b * 4 + h) * HWN;
        for (int i = tid; i < 512; i += 256) {
            int row = i >> 2, c = i & 3;          // lanes 0-3: same row, 64B run
            int pos = __ldg(tkw + row);
            size_t s = (hb + pos) * 16 + c * 4;
            uint32_t doff = (uint32_t)(row * 80 + c * 16);
            cp16(sbase + KH_B + doff, g_kh + s);
            cp16(sbase + VH_B + doff, g_vh + s);
            cp16(sbase + VL_B + doff, g_vl + s);
        }
        if (tid < 64) {
            int qi = tid >> 2, c = tid & 3;
            int hw = (wy * 4 + (qi >> 2)) * HH + wx * 4 + (qi & 3);
            size_t s = (hb + hw) * 16 + c * 4;
            cp16(sbase + QH_B + qi * 80 + c * 16, g_qh + s);
        }
        asm volatile("cp.async.commit_group;");
        asm volatile("cp.async.wait_group 0;" ::: "memory");
    }
    __syncthreads();

    // ---- S = Qh Kh^T (single term). Warp owns n-tiles 2w, 2w+1 ----
    float c0[4] = {0.f, 0.f, 0.f, 0.f};
    float c1[4] = {0.f, 0.f, 0.f, 0.f};
    {
        const uint32_t q_l = (uint32_t)((lane & 15) * 80 + (lane >> 4) * 16);
        const uint32_t k4 = (uint32_t)((wrp * 16 + (lane & 7) + (lane >> 4) * 8) * 80
                                       + ((lane >> 3) & 1) * 16);
        #pragma unroll
        for (int ks = 0; ks < 2; ks++) {
            uint32_t aqh[4];
            ldsm4(aqh, sbase + QH_B + q_l + ks * 32);
            uint32_t kh4[4];
            ldsm4(kh4, sbase + KH_B + k4 + ks * 32);
            mma_bf16(c0, aqh, kh4);
            mma_bf16(c1, aqh, kh4 + 2);
        }
    }

    float* rmaxs = (float*)(smb + RMAX_B);
    float* rsums = (float*)(smb + RSUM_B);
    const int r0 = lane >> 2;
    {
        float m0 = fmaxf(fmaxf(c0[0], c0[1]), fmaxf(c1[0], c1[1]));
        float m1 = fmaxf(fmaxf(c0[2], c0[3]), fmaxf(c1[2], c1[3]));
        m0 = fmaxf(m0, __shfl_xor_sync(0xffffffffu, m0, 1));
        m0 = fmaxf(m0, __shfl_xor_sync(0xffffffffu, m0, 2));
        m1 = fmaxf(m1, __shfl_xor_sync(0xffffffffu, m1, 1));
        m1 = fmaxf(m1, __shfl_xor_sync(0xffffffffu, m1, 2));
        if ((lane & 3) == 0) {
            rmaxs[wrp * 16 + r0]     = m0;
            rmaxs[wrp * 16 + r0 + 8] = m1;
        }
    }
    __syncthreads();

    uint32_t aph[4], apl[4];
    {
        float g0 = rmaxs[r0], g1 = rmaxs[r0 + 8];
        #pragma unroll
        for (int ww = 1; ww < 8; ww++) {
            g0 = fmaxf(g0, rmaxs[ww * 16 + r0]);
            g1 = fmaxf(g1, rmaxs[ww * 16 + r0 + 8]);
        }
        c0[0] = __expf(c0[0] - g0); c0[1] = __expf(c0[1] - g0);
        c1[0] = __expf(c1[0] - g0); c1[1] = __expf(c1[1] - g0);
        c0[2] = __expf(c0[2] - g1); c0[3] = __expf(c0[3] - g1);
        c1[2] = __expf(c1[2] - g1); c1[3] = __expf(c1[3] - g1);
        float s0 = c0[0] + c0[1] + c1[0] + c1[1];
        float s1 = c0[2] + c0[3] + c1[2] + c1[3];
        s0 += __shfl_xor_sync(0xffffffffu, s0, 1);
        s0 += __shfl_xor_sync(0xffffffffu, s0, 2);
        s1 += __shfl_xor_sync(0xffffffffu, s1, 1);
        s1 += __shfl_xor_sync(0xffffffffu, s1, 2);
        if ((lane & 3) == 0) {
            rsums[wrp * 16 + r0]     = s0;
            rsums[wrp * 16 + r0 + 8] = s1;
        }
        split_pack(c0[0], c0[1], aph[0], apl[0]);
        split_pack(c0[2], c0[3], aph[1], apl[1]);
        split_pack(c1[0], c1[1], aph[2], apl[2]);
        split_pack(c1[2], c1[3], aph[3], apl[3]);
    }
    __syncthreads();   // rsums visible; KH/KL region now dead -> O stage overlay

    // ---- PV: warp's kstep = kj 16w..16w+15; V via ldmatrix.x4.trans ----
    {
        const uint32_t v4 = (uint32_t)((wrp * 16 + (lane & 15)) * 80 + (lane >> 4) * 16);
        float* slab = (float*)smb + wrp * 640;   // 16 rows x 40 f32 (KH+KL region)
        #pragma unroll
        for (int ntp = 0; ntp < 2; ntp++) {
            uint32_t vh4[4], vl4[4];
            ldsm4t(vh4, sbase + VH_B + v4 + ntp * 32);
            ldsm4t(vl4, sbase + VL_B + v4 + ntp * 32);
            float o0[4] = {0.f, 0.f, 0.f, 0.f};
            float o1[4] = {0.f, 0.f, 0.f, 0.f};
            mma_bf16(o0, aph, vh4);     mma_bf16(o0, aph, vl4);     mma_bf16(o0, apl, vh4);
            mma_bf16(o1, aph, vh4 + 2); mma_bf16(o1, aph, vl4 + 2); mma_bf16(o1, apl, vh4 + 2);
            float* sp0 = slab + r0 * 40 + (2 * ntp) * 8 + 2 * (lane & 3);
            *(float2*)sp0            = make_float2(o0[0], o0[1]);
            *(float2*)(sp0 + 8 * 40) = make_float2(o0[2], o0[3]);
            float* sp1 = sp0 + 8;
            *(float2*)sp1            = make_float2(o1[0], o1[1]);
            *(float2*)(sp1 + 8 * 40) = make_float2(o1[2], o1[3]);
        }
    }
    __syncthreads();

    // ---- reduce 8 slabs, normalize, split, store ----
    if (tid < 224) {
        int qi = tid / 14, p = tid - qi * 14;
        float o0 = 0.f, o1 = 0.f, gs = 0.f;
        #pragma unroll
        for (int ww = 0; ww < 8; ww++) {
            float2 v = *(const float2*)((const float*)smb + ww * 640 + qi * 40 + 2 * p);
            o0 += v.x; o1 += v.y;
            gs += rsums[ww * 16 + qi];
        }
        float inv = 1.0f / gs;
        uint32_t hi, lo;
        split_pack(o0 * inv, o1 * inv, hi, lo);
        int hw = (wy * 4 + (qi >> 2)) * HH + wx * 4 + (qi & 3);
        size_t a = ((size_t)b * HWN + hw) * 60 + h * 14 + p;
        g_oh[a] = hi;
        g_ol[a] = lo;
    }
}

// =============================================================================
// Kernel C: output projection via mma.sync; A and W pre-split via cp.async.
// =============================================================================
__global__ __launch_bounds__(512, 2) void proj_kernel(const float* __restrict__ bias,
                                                      float* __restrict__ out) {
    extern __shared__ char smb[];
    const uint32_t sbase = smem_u32(smb);
    const int tid = threadIdx.x;
    const int b   = blockIdx.y;
    const int hw0 = blockIdx.x * 128;

    for (int i = tid; i < 1920; i += 512) {
        int row = i / 15, j = i - row * 15;
        size_t s = ((size_t)b * HWN + hw0 + row) * 60 + j * 4;
        uint32_t doff = (uint32_t)(row * 240 + j * 16);
        cp16(sbase + AH_B + doff, g_oh + s);
        cp16(sbase + AL_B + doff, g_ol + s);
    }
    for (int i = tid; i < 1680; i += 512) {
        cp16(sbase + WH_B + i * 16, g_wh + 3 * 6720 + i * 4);
        cp16(sbase + WL_B + i * 16, g_wl + 3 * 6720 + i * 4);
    }
    asm volatile("cp.async.commit_group;");
    asm volatile("cp.async.wait_group 0;" ::: "memory");
    __syncthreads();

    const int lane = tid & 31;
    const int wid  = tid >> 5;
    const int wm   = wid & 7;
    const int wn   = wid >> 3;
    const int mrow = wm * 16;
    const int amat = lane >> 3, ar = lane & 7;
    const uint32_t a_off = (uint32_t)((mrow + ar + (amat & 1) * 8) * 240
                                      + (amat >> 1) * 16);
    const uint32_t b_lane_off = (uint32_t)((lane & 7) * 240 + ((lane >> 3) & 1) * 16);
    const int orow  = mrow + (lane >> 2);
    const int ocol0 = wn * 56 + 2 * (lane & 3);

    float acc[7][4];
    #pragma unroll
    for (int nt = 0; nt < 7; nt++)
        #pragma unroll
        for (int j = 0; j < 4; j++) acc[nt][j] = 0.0f;

    #pragma unroll
    for (int ks = 0; ks < 7; ks++) {
        uint32_t ah[4], al[4];
        ldsm4(ah, sbase + AH_B + a_off + ks * 32);
        ldsm4(al, sbase + AL_B + a_off + ks * 32);
        #pragma unroll
        for (int nt = 0; nt < 7; nt++) {
            uint32_t bh[2], bl[2];
            uint32_t boff = (uint32_t)((wn * 56 + nt * 8) * 240) + b_lane_off + ks * 32;
            ldsm2(bh, sbase + WH_B + boff);
            ldsm2(bl, sbase + WL_B + boff);
            mma_bf16(acc[nt], ah, bh);
            mma_bf16(acc[nt], ah, bl);
            mma_bf16(acc[nt], al, bh);
        }
    }
    __syncthreads();   // A region dead; reuse as transpose stage

    float* stage = (float*)smb;
    #pragma unroll
    for (int nt = 0; nt < 7; nt++) {
        int d = ocol0 + nt * 8;
        stage[d * 132 + orow]           = acc[nt][0];
        stage[(d + 1) * 132 + orow]     = acc[nt][1];
        stage[d * 132 + orow + 8]       = acc[nt][2];
        stage[(d + 1) * 132 + orow + 8] = acc[nt][3];
    }
    __syncthreads();

    for (int i = tid; i < 3584; i += 512) {
        int d = i >> 5, j = i & 31;
        float4 v = *(const float4*)(stage + d * 132 + j * 4);
        float bv = __ldg(bias + d);
        v.x += bv; v.y += bv; v.z += bv; v.w += bv;
        *(float4*)(out + ((size_t)b * CC + d) * HWN + hw0 + j * 4) = v;
    }
}

// =============================================================================
extern "C" void kernel_launch(void* const* d_in, const int* in_sizes, int n_in,
                              void* d_out, int out_size) {
    const float* x     = (const float*)d_in[0];
    const float* Wqkv  = (const float*)d_in[1];
    const float* Wproj = (const float*)d_in[2];
    const float* bproj = (const float*)d_in[3];
    const int*   topk  = (const int*)d_in[4];
    float* out = (float*)d_out;

    cudaFuncSetAttribute(qkv_kernel,  cudaFuncAttributeMaxDynamicSharedMemorySize, MMA_SMEM_B);
    cudaFuncSetAttribute(attn_kernel, cudaFuncAttributeMaxDynamicSharedMemorySize, ATTN_SMEM_B);
    cudaFuncSetAttribute(proj_kernel, cudaFuncAttributeMaxDynamicSharedMemorySize, MMA_SMEM_B);

    prep_kernel<<<4, 256>>>(Wqkv, Wproj);
    qkv_kernel<<<dim3(32, 16), 512, MMA_SMEM_B>>>(x);
    attn_kernel<<<BB * NWIN * NHEAD, 256, ATTN_SMEM_B>>>(topk);
    proj_kernel<<<dim3(32, 16), 512, MMA_SMEM_B>>>(bproj, out);
}

// round 17
// speedup vs baseline: 3.9163x; 1.0580x over previous
#include <cuda_runtime.h>
#include <cuda_bf16.h>
#include <cstdint>

#define BB    16
#define CC    112
#define HH    64
#define HWN   4096
#define NHEAD 4
#define HD    28
#define NWIN  256
#define TOPK  128
#define SCALE 0.18898223650461363f   // 28^-0.5

// ---- mma (qkv/proj) smem byte offsets: 240B rows (15x16B odd, conflict-free)
#define AH_B   0
#define AL_B   30720
#define WH_B   61440
#define WL_B   88320
#define MMA_SMEM_B 115200
// qkv epilogue stage overlays WH/WL: 128 rows x 68 u32 = 34816B

// ---- attn smem byte offsets: 80B rows (5x16B odd, ldsm conflict-free) ----
#define KH_B    0        // 128 x 80B = 10240
#define KL_B    10240    // slab-only region (O overlay)
#define VH_B    20480
#define VL_B    30720
#define QH_B    40960    // 16 x 80B = 1280
#define QL_B    42240    // unused (layout stability)
#define RMAX_B  43520    // 8 warps x 16 f32
#define RSUM_B  44032
#define ATTN_SMEM_B 44544

// ---------------- scratch (device globals; no allocation allowed) ------------
__device__ __align__(16) uint32_t g_qh[BB * NHEAD * HWN * 16];
__device__ __align__(16) uint32_t g_kh[BB * NHEAD * HWN * 16];
__device__ __align__(16) uint32_t g_vh[BB * NHEAD * HWN * 16];
__device__ __align__(16) uint32_t g_vl[BB * NHEAD * HWN * 16];
__device__ __align__(16) uint32_t g_oh[BB * HWN * 60];
__device__ __align__(16) uint32_t g_ol[BB * HWN * 60];
__device__ __align__(16) uint32_t g_wh[4 * CC * 60];
__device__ __align__(16) uint32_t g_wl[4 * CC * 60];

__device__ __forceinline__ uint32_t smem_u32(const void* p) {
    uint32_t a;
    asm("{ .reg .u64 t; cvta.to.shared.u64 t, %1; cvt.u32.u64 %0, t; }" : "=r"(a) : "l"(p));
    return a;
}
__device__ __forceinline__ void cp16(uint32_t dst, const void* src) {
    asm volatile("cp.async.cg.shared.global [%0], [%1], 16;" :: "r"(dst), "l"(src) : "memory");
}
__device__ __forceinline__ void ldsm4(uint32_t* r, uint32_t a) {
    asm volatile("ldmatrix.sync.aligned.m8n8.x4.shared.b16 {%0,%1,%2,%3}, [%4];"
                 : "=r"(r[0]), "=r"(r[1]), "=r"(r[2]), "=r"(r[3]) : "r"(a));
}
__device__ __forceinline__ void ldsm2(uint32_t* r, uint32_t a) {
    asm volatile("ldmatrix.sync.aligned.m8n8.x2.shared.b16 {%0,%1}, [%2];"
                 : "=r"(r[0]), "=r"(r[1]) : "r"(a));
}
__device__ __forceinline__ void ldsm4t(uint32_t* r, uint32_t a) {
    asm volatile("ldmatrix.sync.aligned.m8n8.x4.trans.shared.b16 {%0,%1,%2,%3}, [%4];"
                 : "=r"(r[0]), "=r"(r[1]), "=r"(r[2]), "=r"(r[3]) : "r"(a));
}
__device__ __forceinline__ void mma_bf16(float* d, const uint32_t* a, const uint32_t* b) {
    asm volatile("mma.sync.aligned.m16n8k16.row.col.f32.bf16.bf16.f32 "
                 "{%0,%1,%2,%3}, {%4,%5,%6,%7}, {%8,%9}, {%0,%1,%2,%3};"
                 : "+f"(d[0]), "+f"(d[1]), "+f"(d[2]), "+f"(d[3])
                 : "r"(a[0]), "r"(a[1]), "r"(a[2]), "r"(a[3]), "r"(b[0]), "r"(b[1]));
}
__device__ __forceinline__ void split_pack(float a0, float a1, uint32_t& hi, uint32_t& lo) {
    __nv_bfloat16 h0 = __float2bfloat16(a0);
    __nv_bfloat16 h1 = __float2bfloat16(a1);
    __nv_bfloat16 l0 = __float2bfloat16(a0 - __bfloat162float(h0));
    __nv_bfloat16 l1 = __float2bfloat16(a1 - __bfloat162float(h1));
    hi = ((uint32_t)__bfloat16_as_ushort(h1) << 16) | __bfloat16_as_ushort(h0);
    lo = ((uint32_t)__bfloat16_as_ushort(l1) << 16) | __bfloat16_as_ushort(l0);
}

// =============================================================================
// Kernel 0: one-shot weight pre-split. Block = seg (0..2 Wqkv, 3 Wproj).
// =============================================================================
__global__ __launch_bounds__(256) void prep_kernel(const float* __restrict__ Wqkv,
                                                   const float* __restrict__ Wproj) {
    const int seg = blockIdx.x;
    const float* src = (seg < 3) ? (Wqkv + (size_t)seg * CC * CC) : Wproj;
    const float s = (seg == 0) ? SCALE : 1.0f;
    const int base = seg * 6720;
    for (int i = threadIdx.x; i < 6272; i += 256) {
        int d = i / 56, cp = i - d * 56;
        float2 wv = *(const float2*)(src + (size_t)d * CC + cp * 2);
        uint32_t hi, lo;
        split_pack(wv.x * s, wv.y * s, hi, lo);
        g_wh[base + d * 60 + cp] = hi;
        g_wl[base + d * 60 + cp] = lo;
    }
    for (int i = threadIdx.x; i < 448; i += 256) {
        int d = i >> 2;
        g_wh[base + d * 60 + 56 + (i & 3)] = 0;
        g_wl[base + d * 60 + 56 + (i & 3)] = 0;
    }
}

// =============================================================================
// Kernel A: QKV projection. q/k segs: 1-term MMA (Ah*Wh) + hi-only store;
// v seg: full 3-term + hi/lo store.
// =============================================================================
__global__ __launch_bounds__(512, 2) void qkv_kernel(const float* __restrict__ x) {
    extern __shared__ char smb[];
    float* xs = (float*)(smb + WH_B);
    const uint32_t sbase = smem_u32(smb);

    const int tid = threadIdx.x;
    const int b   = blockIdx.y;
    const int hw0 = blockIdx.x * 128;

    // A conversion (x tile, transposed to [px][ch]) in two 56-channel chunks
    #pragma unroll
    for (int chunk = 0; chunk < 2; chunk++) {
        for (int i = tid; i < 1792; i += 512) {
            int c = i >> 5, p4 = i & 31;
            ((float4*)xs)[i] =
                ((const float4*)(x + (b * CC + chunk * 56 + c) * HWN + hw0))[p4];
        }
        __syncthreads();
        for (int i = tid; i < 3584; i += 512) {
            int px = i & 127, cp = i >> 7;
            uint32_t hi, lo;
            split_pack(xs[(cp * 2) * 128 + px], xs[(cp * 2 + 1) * 128 + px], hi, lo);
            int idx = px * 60 + chunk * 28 + cp;
            ((uint32_t*)(smb + AH_B))[idx] = hi;
            ((uint32_t*)(smb + AL_B))[idx] = lo;
        }
        __syncthreads();
    }

    const int lane = tid & 31;
    const int wid  = tid >> 5;
    const int wm   = wid & 7;
    const int wn   = wid >> 3;
    const int mrow = wm * 16;

    const int amat = lane >> 3, ar = lane & 7;
    const uint32_t a_off = (uint32_t)((mrow + ar + (amat & 1) * 8) * 240
                                      + (amat >> 1) * 16);
    const uint32_t b_lane_off = (uint32_t)((lane & 7) * 240 + ((lane >> 3) & 1) * 16);

    const int orow  = mrow + (lane >> 2);
    const int ocol0 = wn * 56 + 2 * (lane & 3);

    for (int seg = 0; seg < 3; seg++) {
        // ---- load pre-split W tiles (WL only needed for v seg) ----
        for (int i = tid; i < 1680; i += 512) {
            cp16(sbase + WH_B + i * 16, g_wh + seg * 6720 + i * 4);
            if (seg == 2)
                cp16(sbase + WL_B + i * 16, g_wl + seg * 6720 + i * 4);
        }
        asm volatile("cp.async.commit_group;");
        asm volatile("cp.async.wait_group 0;" ::: "memory");
        __syncthreads();

        float acc[7][4];
        #pragma unroll
        for (int nt = 0; nt < 7; nt++)
            #pragma unroll
            for (int j = 0; j < 4; j++) acc[nt][j] = 0.0f;

        if (seg < 2) {
            // ---- q/k: single-term Ah*Wh ----
            #pragma unroll
            for (int ks = 0; ks < 7; ks++) {
                uint32_t ah[4];
                ldsm4(ah, sbase + AH_B + a_off + ks * 32);
                #pragma unroll
                for (int nt = 0; nt < 7; nt++) {
                    uint32_t bh[2];
                    uint32_t boff = (uint32_t)((wn * 56 + nt * 8) * 240) + b_lane_off + ks * 32;
                    ldsm2(bh, sbase + WH_B + boff);
                    mma_bf16(acc[nt], ah, bh);
                }
            }
        } else {
            // ---- v: 3-term bf16 split ----
            #pragma unroll
            for (int ks = 0; ks < 7; ks++) {
                uint32_t ah[4], al[4];
                ldsm4(ah, sbase + AH_B + a_off + ks * 32);
                ldsm4(al, sbase + AL_B + a_off + ks * 32);
                #pragma unroll
                for (int nt = 0; nt < 7; nt++) {
                    uint32_t bh[2], bl[2];
                    uint32_t boff = (uint32_t)((wn * 56 + nt * 8) * 240) + b_lane_off + ks * 32;
                    ldsm2(bh, sbase + WH_B + boff);
                    ldsm2(bl, sbase + WL_B + boff);
                    mma_bf16(acc[nt], ah, bh);
                    mma_bf16(acc[nt], ah, bl);
                    mma_bf16(acc[nt], al, bh);
                }
            }
        }

        // ---- epilogue: q/k = hi only (1 pass); v = hi+lo (2 passes) ----
        uint32_t* stg = (uint32_t*)(smb + WH_B);
        const int npass = (seg == 2) ? 2 : 1;
        for (int pass = 0; pass < npass; pass++) {
            __syncthreads();
            for (int i = tid; i < 1024; i += 512) {
                int px = i >> 3, hh = (i >> 1) & 3, pc = 14 + (i & 1);
                stg[px * 68 + hh * 16 + pc] = 0;
            }
            #pragma unroll
            for (int nt = 0; nt < 7; nt++) {
                int d = ocol0 + nt * 8;
                int hh = d / 28;
                int cidx = (d - hh * 28) >> 1;
                uint32_t hi, lo;
                split_pack(acc[nt][0], acc[nt][1], hi, lo);
                stg[orow * 68 + hh * 16 + cidx] = pass ? lo : hi;
                split_pack(acc[nt][2], acc[nt][3], hi, lo);
                stg[(orow + 8) * 68 + hh * 16 + cidx] = pass ? lo : hi;
            }
            __syncthreads();
            uint32_t* gp;
            if (seg == 0)      gp = g_qh;
            else if (seg == 1) gp = g_kh;
            else               gp = pass ? g_vl : g_vh;
            for (int i = tid; i < 2048; i += 512) {
                int px = i >> 4, j = i & 15;
                uint4 v = *(const uint4*)(stg + px * 68 + j * 4);
                *(uint4*)(gp + ((size_t)(b * 4 + (j >> 2)) * HWN + hw0 + px) * 16
                          + (j & 3) * 4) = v;
            }
        }
        __syncthreads();
    }
}

// =============================================================================
// Kernel B: FA2-style windowed top-k attention (unchanged from round 16).
// =============================================================================
__global__ __launch_bounds__(256, 5) void attn_kernel(const int* __restrict__ topk) {
    extern __shared__ char smb[];
    const uint32_t sbase = smem_u32(smb);
    const int tid  = threadIdx.x;
    const int lane = tid & 31;
    const int wrp  = tid >> 5;
    const int bx   = blockIdx.x;
    const int h    = bx & 3;
    const int w    = (bx >> 2) & 255;
    const int b    = bx >> 10;
    const int wy   = w >> 4, wx = w & 15;

    {
        const int* tkw = topk + w * TOPK;
        const size_t hb = (size_t)(b * 4 + h) * HWN;
        for (int i = tid; i < 512; i += 256) {
            int row = i >> 2, c = i & 3;
            int pos = __ldg(tkw + row);
            size_t s = (hb + pos) * 16 + c * 4;
            uint32_t doff = (uint32_t)(row * 80 + c * 16);
            cp16(sbase + KH_B + doff, g_kh + s);
            cp16(sbase + VH_B + doff, g_vh + s);
            cp16(sbase + VL_B + doff, g_vl + s);
        }
        if (tid < 64) {
            int qi = tid >> 2, c = tid & 3;
            int hw = (wy * 4 + (qi >> 2)) * HH + wx * 4 + (qi & 3);
            size_t s = (hb + hw) * 16 + c * 4;
            cp16(sbase + QH_B + qi * 80 + c * 16, g_qh + s);
        }
        asm volatile("cp.async.commit_group;");
        asm volatile("cp.async.wait_group 0;" ::: "memory");
    }
    __syncthreads();

    float c0[4] = {0.f, 0.f, 0.f, 0.f};
    float c1[4] = {0.f, 0.f, 0.f, 0.f};
    {
        const uint32_t q_l = (uint32_t)((lane & 15) * 80 + (lane >> 4) * 16);
        const uint32_t k4 = (uint32_t)((wrp * 16 + (lane & 7) + (lane >> 4) * 8) * 80
                                       + ((lane >> 3) & 1) * 16);
        #pragma unroll
        for (int ks = 0; ks < 2; ks++) {
            uint32_t aqh[4];
            ldsm4(aqh, sbase + QH_B + q_l + ks * 32);
            uint32_t kh4[4];
            ldsm4(kh4, sbase + KH_B + k4 + ks * 32);
            mma_bf16(c0, aqh, kh4);
            mma_bf16(c1, aqh, kh4 + 2);
        }
    }

    float* rmaxs = (float*)(smb + RMAX_B);
    float* rsums = (float*)(smb + RSUM_B);
    const int r0 = lane >> 2;
    {
        float m0 = fmaxf(fmaxf(c0[0], c0[1]), fmaxf(c1[0], c1[1]));
        float m1 = fmaxf(fmaxf(c0[2], c0[3]), fmaxf(c1[2], c1[3]));
        m0 = fmaxf(m0, __shfl_xor_sync(0xffffffffu, m0, 1));
        m0 = fmaxf(m0, __shfl_xor_sync(0xffffffffu, m0, 2));
        m1 = fmaxf(m1, __shfl_xor_sync(0xffffffffu, m1, 1));
        m1 = fmaxf(m1, __shfl_xor_sync(0xffffffffu, m1, 2));
        if ((lane & 3) == 0) {
            rmaxs[wrp * 16 + r0]     = m0;
            rmaxs[wrp * 16 + r0 + 8] = m1;
        }
    }
    __syncthreads();

    uint32_t aph[4], apl[4];
    {
        float g0 = rmaxs[r0], g1 = rmaxs[r0 + 8];
        #pragma unroll
        for (int ww = 1; ww < 8; ww++) {
            g0 = fmaxf(g0, rmaxs[ww * 16 + r0]);
            g1 = fmaxf(g1, rmaxs[ww * 16 + r0 + 8]);
        }
        c0[0] = __expf(c0[0] - g0); c0[1] = __expf(c0[1] - g0);
        c1[0] = __expf(c1[0] - g0); c1[1] = __expf(c1[1] - g0);
        c0[2] = __expf(c0[2] - g1); c0[3] = __expf(c0[3] - g1);
        c1[2] = __expf(c1[2] - g1); c1[3] = __expf(c1[3] - g1);
        float s0 = c0[0] + c0[1] + c1[0] + c1[1];
        float s1 = c0[2] + c0[3] + c1[2] + c1[3];
        s0 += __shfl_xor_sync(0xffffffffu, s0, 1);
        s0 += __shfl_xor_sync(0xffffffffu, s0, 2);
        s1 += __shfl_xor_sync(0xffffffffu, s1, 1);
        s1 += __shfl_xor_sync(0xffffffffu, s1, 2);
        if ((lane & 3) == 0) {
            rsums[wrp * 16 + r0]     = s0;
            rsums[wrp * 16 + r0 + 8] = s1;
        }
        split_pack(c0[0], c0[1], aph[0], apl[0]);
        split_pack(c0[2], c0[3], aph[1], apl[1]);
        split_pack(c1[0], c1[1], aph[2], apl[2]);
        split_pack(c1[2], c1[3], aph[3], apl[3]);
    }
    __syncthreads();

    {
        const uint32_t v4 = (uint32_t)((wrp * 16 + (lane & 15)) * 80 + (lane >> 4) * 16);
        float* slab = (float*)smb + wrp * 640;
        #pragma unroll
        for (int ntp = 0; ntp < 2; ntp++) {
            uint32_t vh4[4], vl4[4];
            ldsm4t(vh4, sbase + VH_B + v4 + ntp * 32);
            ldsm4t(vl4, sbase + VL_B + v4 + ntp * 32);
            float o0[4] = {0.f, 0.f, 0.f, 0.f};
            float o1[4] = {0.f, 0.f, 0.f, 0.f};
            mma_bf16(o0, aph, vh4);     mma_bf16(o0, aph, vl4);     mma_bf16(o0, apl, vh4);
            mma_bf16(o1, aph, vh4 + 2); mma_bf16(o1, aph, vl4 + 2); mma_bf16(o1, apl, vh4 + 2);
            float* sp0 = slab + r0 * 40 + (2 * ntp) * 8 + 2 * (lane & 3);
            *(float2*)sp0            = make_float2(o0[0], o0[1]);
            *(float2*)(sp0 + 8 * 40) = make_float2(o0[2], o0[3]);
            float* sp1 = sp0 + 8;
            *(float2*)sp1            = make_float2(o1[0], o1[1]);
            *(float2*)(sp1 + 8 * 40) = make_float2(o1[2], o1[3]);
        }
    }
    __syncthreads();

    if (tid < 224) {
        int qi = tid / 14, p = tid - qi * 14;
        float o0 = 0.f, o1 = 0.f, gs = 0.f;
        #pragma unroll
        for (int ww = 0; ww < 8; ww++) {
            float2 v = *(const float2*)((const float*)smb + ww * 640 + qi * 40 + 2 * p);
            o0 += v.x; o1 += v.y;
            gs += rsums[ww * 16 + qi];
        }
        float inv = 1.0f / gs;
        uint32_t hi, lo;
        split_pack(o0 * inv, o1 * inv, hi, lo);
        int hw = (wy * 4 + (qi >> 2)) * HH + wx * 4 + (qi & 3);
        size_t a = ((size_t)b * HWN + hw) * 60 + h * 14 + p;
        g_oh[a] = hi;
        g_ol[a] = lo;
    }
}

// =============================================================================
// Kernel C: output projection (unchanged from round 16).
// =============================================================================
__global__ __launch_bounds__(512, 2) void proj_kernel(const float* __restrict__ bias,
                                                      float* __restrict__ out) {
    extern __shared__ char smb[];
    const uint32_t sbase = smem_u32(smb);
    const int tid = threadIdx.x;
    const int b   = blockIdx.y;
    const int hw0 = blockIdx.x * 128;

    for (int i = tid; i < 1920; i += 512) {
        int row = i / 15, j = i - row * 15;
        size_t s = ((size_t)b * HWN + hw0 + row) * 60 + j * 4;
        uint32_t doff = (uint32_t)(row * 240 + j * 16);
        cp16(sbase + AH_B + doff, g_oh + s);
        cp16(sbase + AL_B + doff, g_ol + s);
    }
    for (int i = tid; i < 1680; i += 512) {
        cp16(sbase + WH_B + i * 16, g_wh + 3 * 6720 + i * 4);
        cp16(sbase + WL_B + i * 16, g_wl + 3 * 6720 + i * 4);
    }
    asm volatile("cp.async.commit_group;");
    asm volatile("cp.async.wait_group 0;" ::: "memory");
    __syncthreads();

    const int lane = tid & 31;
    const int wid  = tid >> 5;
    const int wm   = wid & 7;
    const int wn   = wid >> 3;
    const int mrow = wm * 16;
    const int amat = lane >> 3, ar = lane & 7;
    const uint32_t a_off = (uint32_t)((mrow + ar + (amat & 1) * 8) * 240
                                      + (amat >> 1) * 16);
    const uint32_t b_lane_off = (uint32_t)((lane & 7) * 240 + ((lane >> 3) & 1) * 16);
    const int orow  = mrow + (lane >> 2);
    const int ocol0 = wn * 56 + 2 * (lane & 3);

    float acc[7][4];
    #pragma unroll
    for (int nt = 0; nt < 7; nt++)
        #pragma unroll
        for (int j = 0; j < 4; j++) acc[nt][j] = 0.0f;

    #pragma unroll
    for (int ks = 0; ks < 7; ks++) {
        uint32_t ah[4], al[4];
        ldsm4(ah, sbase + AH_B + a_off + ks * 32);
        ldsm4(al, sbase + AL_B + a_off + ks * 32);
        #pragma unroll
        for (int nt = 0; nt < 7; nt++) {
            uint32_t bh[2], bl[2];
            uint32_t boff = (uint32_t)((wn * 56 + nt * 8) * 240) + b_lane_off + ks * 32;
            ldsm2(bh, sbase + WH_B + boff);
            ldsm2(bl, sbase + WL_B + boff);
            mma_bf16(acc[nt], ah, bh);
            mma_bf16(acc[nt], ah, bl);
            mma_bf16(acc[nt], al, bh);
        }
    }
    __syncthreads();

    float* stage = (float*)smb;
    #pragma unroll
    for (int nt = 0; nt < 7; nt++) {
        int d = ocol0 + nt * 8;
        stage[d * 132 + orow]           = acc[nt][0];
        stage[(d + 1) * 132 + orow]     = acc[nt][1];
        stage[d * 132 + orow + 8]       = acc[nt][2];
        stage[(d + 1) * 132 + orow + 8] = acc[nt][3];
    }
    __syncthreads();

    for (int i = tid; i < 3584; i += 512) {
        int d = i >> 5, j = i & 31;
        float4 v = *(const float4*)(stage + d * 132 + j * 4);
        float bv = __ldg(bias + d);
        v.x += bv; v.y += bv; v.z += bv; v.w += bv;
        *(float4*)(out + ((size_t)b * CC + d) * HWN + hw0 + j * 4) = v;
    }
}

// =============================================================================
extern "C" void kernel_launch(void* const* d_in, const int* in_sizes, int n_in,
                              void* d_out, int out_size) {
    const float* x     = (const float*)d_in[0];
    const float* Wqkv  = (const float*)d_in[1];
    const float* Wproj = (const float*)d_in[2];
    const float* bproj = (const float*)d_in[3];
    const int*   topk  = (const int*)d_in[4];
    float* out = (float*)d_out;

    cudaFuncSetAttribute(qkv_kernel,  cudaFuncAttributeMaxDynamicSharedMemorySize, MMA_SMEM_B);
    cudaFuncSetAttribute(attn_kernel, cudaFuncAttributeMaxDynamicSharedMemorySize, ATTN_SMEM_B);
    cudaFuncSetAttribute(proj_kernel, cudaFuncAttributeMaxDynamicSharedMemorySize, MMA_SMEM_B);

    prep_kernel<<<4, 256>>>(Wqkv, Wproj);
    qkv_kernel<<<dim3(32, 16), 512, MMA_SMEM_B>>>(x);
    attn_kernel<<<BB * NWIN * NHEAD, 256, ATTN_SMEM_B>>>(topk);
    proj_kernel<<<dim3(32, 16), 512, MMA_SMEM_B>>>(bproj, out);
}